// round 10
// baseline (speedup 1.0000x reference)
#include <cuda_runtime.h>
#include <cuda_fp16.h>
#include <math.h>
#include <stdint.h>

// Problem constants
#define DHID 1024
#define DA   512
#define BB   16
#define LL   2048
#define RR   64
#define MTOT (BB*LL)   // 32768

// ---------------------------------------------------------------------------
// Scratch (static device globals; no allocations allowed)
// ---------------------------------------------------------------------------
__device__ __half g_sh [(size_t)MTOT * DHID];  // student fp16
__device__ __half g_th [(size_t)MTOT * DHID];  // teacher fp16
__device__ __half g_qh [(size_t)MTOT * DA];    // qk fp16
__device__ __half g_uh [(size_t)MTOT * DHID];  // u fp16
__device__ __half g_yh [(size_t)MTOT * DHID];  // y fp16
__device__ float  g_c  [DA];                   // fused bias (fp32)
__device__ __half g_Ah  [DA * DHID];           // fused qk_W1 @ q_W (fp16)
__device__ __half g_Bmh [DA * DHID];           // fused qk_W2 @ k_W (fp16)
__device__ __half g_bkTh[DHID * DA];           // bk_W transposed (fp16)
__device__ __half g_bvh [DA * DHID];           // bv_W (fp16)

// ---------------------------------------------------------------------------
// mma / ldmatrix helpers
// ---------------------------------------------------------------------------
__device__ __forceinline__ void mma_f16(float* c, const uint32_t* a,
                                        uint32_t b0, uint32_t b1)
{
    asm volatile(
        "mma.sync.aligned.m16n8k16.row.col.f32.f16.f16.f32 "
        "{%0,%1,%2,%3}, {%4,%5,%6,%7}, {%8,%9}, {%0,%1,%2,%3};\n"
        : "+f"(c[0]), "+f"(c[1]), "+f"(c[2]), "+f"(c[3])
        : "r"(a[0]), "r"(a[1]), "r"(a[2]), "r"(a[3]), "r"(b0), "r"(b1));
}

__device__ __forceinline__ void ldm_x4(uint32_t* r, uint32_t addr)
{
    asm volatile(
        "ldmatrix.sync.aligned.m8n8.x4.shared.b16 {%0,%1,%2,%3}, [%4];\n"
        : "=r"(r[0]), "=r"(r[1]), "=r"(r[2]), "=r"(r[3]) : "r"(addr));
}

__device__ __forceinline__ uint32_t smem_u32(const void* p) {
    uint32_t a;
    asm("{ .reg .u64 t; cvta.to.shared.u64 t, %1; cvt.u32.u64 %0, t; }"
        : "=r"(a) : "l"(p));
    return a;
}

#define CP_ASYNC16(dst, src) \
    asm volatile("cp.async.cg.shared.global [%0], [%1], 16;" \
                 :: "r"(dst), "l"(src) : "memory")
#define CP_COMMIT() asm volatile("cp.async.commit_group;" ::: "memory")
#define CP_WAIT1()  asm volatile("cp.async.wait_group 1;" ::: "memory")
#define CP_WAIT0()  asm volatile("cp.async.wait_group 0;" ::: "memory")

// ---------------------------------------------------------------------------
// fp16 GEMM (NT), K-chunk = 64, single pass:
//   C[m,n] = sum_k X1[m,k]*W1[n,k] (+ X2*W2 phase) + bias[n]
// Tile 128x128x64/chunk; 8 warps of 32x64; 3-stage cp.async pipeline,
// ONE __syncthreads per chunk; register double-buffered ldmatrix fragments;
// precomputed per-thread pointers (no 64-bit math in loop);
// smem rows 144 B (128 data + 16 pad).
// ---------------------------------------------------------------------------
#define ROWB   144
#define PLANE  (128 * ROWB)           // 18432 B
#define NSTAGE 3
#define SMEM_G (NSTAGE * 2 * PLANE)   // 110592 B -> occ 2

struct GArgs {
    const __half *X1, *W1;
    const __half *X2, *W2;
    int K1, K2;
};

__device__ __forceinline__ void ld_frags(
    uint32_t abase, uint32_t bbase, uint32_t kb, uint32_t* af, uint32_t* bf)
{
    ldm_x4(af + 0, abase + kb);
    ldm_x4(af + 4, abase + kb + 16 * ROWB);
    #pragma unroll
    for (int j = 0; j < 4; ++j) ldm_x4(bf + 4 * j, bbase + kb + j * 16 * ROWB);
}

__global__ void __launch_bounds__(256, 2) gemm_h_nt(
    GArgs ga,
    const float* __restrict__ bias,
    float* __restrict__ Cf,               // fp32 out (nullable)
    __half* __restrict__ Ch,              // fp16 out (if Cf null)
    int M, int N)
{
    extern __shared__ __align__(16) char smraw[];
    const uint32_t sm0 = smem_u32(smraw);

    const int t    = threadIdx.x;
    const int warp = t >> 5;
    const int lane = t & 31;
    const int bm   = blockIdx.y * 128;
    const int bn   = blockIdx.x * 128;
    const int mw   = (warp & 3) * 32;
    const int nw   = (warp >> 2) * 64;
    const uint32_t laneoff = (lane & 15) * ROWB + (lane >> 4) * 16;
    const uint32_t aBase   = mw * ROWB + laneoff;
    const uint32_t bBase   = PLANE + nw * ROWB + laneoff;

    // Precomputed per-thread load pointers (4 X-rows + 4 W-rows each)
    const int rbase = t >> 3;
    const int grp   = t & 7;
    const __half *pX1[4], *pW1[4], *pX2[4], *pW2[4];
    uint32_t dofA[4], dofB[4];
    #pragma unroll
    for (int o = 0; o < 4; ++o) {
        const int row = rbase + o * 32;
        pX1[o] = ga.X1 + (size_t)(bm + row) * ga.K1 + grp * 8;
        pW1[o] = ga.W1 + (size_t)(bn + row) * ga.K1 + grp * 8;
        dofA[o] = row * ROWB + grp * 16;
        dofB[o] = PLANE + row * ROWB + grp * 16;
    }
    if (ga.X2) {
        #pragma unroll
        for (int o = 0; o < 4; ++o) {
            const int row = rbase + o * 32;
            pX2[o] = ga.X2 + (size_t)(bm + row) * ga.K2 + grp * 8;
            pW2[o] = ga.W2 + (size_t)(bn + row) * ga.K2 + grp * 8;
        }
    }

    const int nc1 = ga.K1 / 64;
    const int nch = ga.X2 ? nc1 + ga.K2 / 64 : nc1;

    float acc[2][8][4];
    #pragma unroll
    for (int i = 0; i < 2; ++i)
        #pragma unroll
        for (int j = 0; j < 8; ++j)
            #pragma unroll
            for (int e = 0; e < 4; ++e) acc[i][j][e] = 0.f;

    // chunk-load issuance (pointer + small offset only)
    auto issue = [&](int c) {
        const uint32_t sb = sm0 + (c % NSTAGE) * 2 * PLANE;
        const bool p2 = (c >= nc1);
        const int  k  = (p2 ? (c - nc1) : c) * 64;
        const __half* const* pX = p2 ? pX2 : pX1;
        const __half* const* pW = p2 ? pW2 : pW1;
        #pragma unroll
        for (int o = 0; o < 4; ++o) CP_ASYNC16(sb + dofA[o], pX[o] + k);
        #pragma unroll
        for (int o = 0; o < 4; ++o) CP_ASYNC16(sb + dofB[o], pW[o] + k);
        CP_COMMIT();
    };

    // Prologue: stages 0, 1
    if (0 < nch) issue(0);
    if (1 < nch) issue(1);

    uint32_t af[2][8], bf[2][16];

    for (int c = 0; c < nch; ++c) {
        if (c + 2 <= nch) CP_WAIT1(); else CP_WAIT0();
        __syncthreads();          // single barrier per chunk

        const uint32_t sb = sm0 + (c % NSTAGE) * 2 * PLANE;
        const uint32_t ab = sb + aBase;
        const uint32_t bb = sb + bBase;

        ld_frags(ab, bb, 0, af[0], bf[0]);
        #pragma unroll
        for (int ks = 0; ks < 4; ++ks) {
            const int cur = ks & 1;
            if (ks < 3)
                ld_frags(ab, bb, (ks + 1) * 32, af[cur ^ 1], bf[cur ^ 1]);
            #pragma unroll
            for (int i = 0; i < 2; ++i) {
                const uint32_t* ah = af[cur] + 4 * i;
                #pragma unroll
                for (int j8 = 0; j8 < 8; ++j8) {
                    uint32_t b0 = bf[cur][4 * (j8 >> 1) + (j8 & 1)];
                    uint32_t b1 = bf[cur][4 * (j8 >> 1) + (j8 & 1) + 2];
                    mma_f16(acc[i][j8], ah, b0, b1);
                }
            }
        }

        if (c + 2 < nch) issue(c + 2);
    }

    // Epilogue
    const int g = lane >> 2;
    const int q = lane & 3;
    #pragma unroll
    for (int i = 0; i < 2; ++i) {
        #pragma unroll
        for (int j8 = 0; j8 < 8; ++j8) {
            const int r0  = bm + mw + 16 * i + g;
            const int col = bn + nw + 8 * j8 + 2 * q;
            const float b0v = bias ? bias[col]     : 0.f;
            const float b1v = bias ? bias[col + 1] : 0.f;
            float v00 = acc[i][j8][0] + b0v, v01 = acc[i][j8][1] + b1v;
            float v10 = acc[i][j8][2] + b0v, v11 = acc[i][j8][3] + b1v;
            if (Cf) {
                *(float2*)&Cf[(size_t)r0 * N + col]       = make_float2(v00, v01);
                *(float2*)&Cf[(size_t)(r0 + 8) * N + col] = make_float2(v10, v11);
            } else {
                *(__half2*)&Ch[(size_t)r0 * N + col]       = __floats2half2_rn(v00, v01);
                *(__half2*)&Ch[(size_t)(r0 + 8) * N + col] = __floats2half2_rn(v10, v11);
            }
        }
    }
}

// ---------------------------------------------------------------------------
// Converters
// ---------------------------------------------------------------------------
__global__ void cvt_pair32to16(__half* __restrict__ h0, const float* __restrict__ s0,
                               __half* __restrict__ h1, const float* __restrict__ s1,
                               int n)
{
    int i = (blockIdx.x * blockDim.x + threadIdx.x) * 4;
    if (i >= n) return;
    float4 a = *(const float4*)&s0[i];
    *(__half2*)&h0[i]     = __floats2half2_rn(a.x, a.y);
    *(__half2*)&h0[i + 2] = __floats2half2_rn(a.z, a.w);
    float4 b = *(const float4*)&s1[i];
    *(__half2*)&h1[i]     = __floats2half2_rn(b.x, b.y);
    *(__half2*)&h1[i + 2] = __floats2half2_rn(b.z, b.w);
}

__global__ void cvt32to16(__half* __restrict__ h, const float* __restrict__ s, int n)
{
    int i = (blockIdx.x * blockDim.x + threadIdx.x) * 4;
    if (i >= n) return;
    float4 v = *(const float4*)&s[i];
    *(__half2*)&h[i]     = __floats2half2_rn(v.x, v.y);
    *(__half2*)&h[i + 2] = __floats2half2_rn(v.z, v.w);
}

// ---------------------------------------------------------------------------
// Transpose (fp32 in -> fp16 out), once for bk_W
// ---------------------------------------------------------------------------
__global__ void transpose_h_kernel(__half* __restrict__ out,
                                   const float* __restrict__ in,
                                   int Rrows, int Ccols)
{
    __shared__ float tile[32][33];
    int x = blockIdx.x * 32 + threadIdx.x;
    int y = blockIdx.y * 32 + threadIdx.y;
    #pragma unroll
    for (int i = 0; i < 4; ++i)
        tile[threadIdx.y + 8 * i][threadIdx.x] = in[(size_t)(y + 8 * i) * Ccols + x];
    __syncthreads();
    x = blockIdx.y * 32 + threadIdx.x;
    y = blockIdx.x * 32 + threadIdx.y;
    #pragma unroll
    for (int i = 0; i < 4; ++i)
        out[(size_t)(y + 8 * i) * Rrows + x] =
            __float2half_rn(tile[threadIdx.x][threadIdx.y + 8 * i]);
}

// ---------------------------------------------------------------------------
// Combined prep: Ah = qk_W[:, :512] @ q_W ; Bmh = qk_W[:, 512:] @ k_W
// ---------------------------------------------------------------------------
#define BM 128
#define BN 128
#define BK 16

__global__ void __launch_bounds__(256, 2) prep_weights_kernel(
    __half* __restrict__ CA, __half* __restrict__ CB,
    const float* __restrict__ qk_W,
    const float* __restrict__ q_W, const float* __restrict__ k_W)
{
    const int half  = blockIdx.y >> 2;
    const int by    = blockIdx.y & 3;
    __half* C       = half ? CB : CA;
    const float* X  = half ? qk_W + DA : qk_W;
    const float* W  = half ? k_W : q_W;
    const int N = DHID, K = DA, ldx = 2 * DA;

    __shared__ float As[BK][BM];
    __shared__ float Bs[BK][BN];
    const int t  = threadIdx.x;
    const int bm = by * BM;
    const int bn = blockIdx.x * BN;

    float acc[8][8];
    #pragma unroll
    for (int i = 0; i < 8; ++i)
        #pragma unroll
        for (int j = 0; j < 8; ++j) acc[i][j] = 0.f;

    const int lrow = t >> 2;
    const int lc4  = (t & 3) * 4;
    const int wk   = t >> 5;
    const int wn4  = (t & 31) * 4;

    for (int k0 = 0; k0 < K; k0 += BK) {
        #pragma unroll
        for (int h = 0; h < 2; ++h) {
            int row = lrow + h * 64;
            float4 v = *(const float4*)&X[(size_t)(bm + row) * ldx + k0 + lc4];
            As[lc4 + 0][row] = v.x;
            As[lc4 + 1][row] = v.y;
            As[lc4 + 2][row] = v.z;
            As[lc4 + 3][row] = v.w;
            int k = wk + h * 8;
            float4 w = *(const float4*)&W[(size_t)(k0 + k) * N + bn + wn4];
            *(float4*)&Bs[k][wn4] = w;
        }
        __syncthreads();
        const int m8 = (t >> 4) * 8;
        const int n8 = (t & 15) * 8;
        #pragma unroll
        for (int kk = 0; kk < BK; ++kk) {
            float a[8], b[8];
            *(float4*)&a[0] = *(const float4*)&As[kk][m8];
            *(float4*)&a[4] = *(const float4*)&As[kk][m8 + 4];
            *(float4*)&b[0] = *(const float4*)&Bs[kk][n8];
            *(float4*)&b[4] = *(const float4*)&Bs[kk][n8 + 4];
            #pragma unroll
            for (int i = 0; i < 8; ++i)
                #pragma unroll
                for (int j = 0; j < 8; ++j)
                    acc[i][j] += a[i] * b[j];
        }
        __syncthreads();
    }

    const int m0 = bm + (t >> 4) * 8;
    const int n0 = bn + (t & 15) * 8;
    #pragma unroll
    for (int i = 0; i < 8; ++i) {
        __half2 h0 = __floats2half2_rn(acc[i][0], acc[i][1]);
        __half2 h1 = __floats2half2_rn(acc[i][2], acc[i][3]);
        __half2 h2 = __floats2half2_rn(acc[i][4], acc[i][5]);
        __half2 h3 = __floats2half2_rn(acc[i][6], acc[i][7]);
        __half* dst = &C[(size_t)(m0 + i) * N + n0];
        *(__half2*)(dst + 0) = h0;
        *(__half2*)(dst + 2) = h1;
        *(__half2*)(dst + 4) = h2;
        *(__half2*)(dst + 6) = h3;
    }
}

// ---------------------------------------------------------------------------
// Fused bias: c[i] = sum_j qk_W[i,j]*q_b[j] + qk_W[i,512+j]*k_b[j] + qk_b[i]
// ---------------------------------------------------------------------------
__global__ void fuse_bias_kernel(float* __restrict__ c,
                                 const float* __restrict__ qk_W,
                                 const float* __restrict__ q_b,
                                 const float* __restrict__ k_b,
                                 const float* __restrict__ qk_b)
{
    int i = blockIdx.x * blockDim.x + threadIdx.x;
    if (i >= DA) return;
    float s = qk_b[i];
    const float* row = qk_W + (size_t)i * (2 * DA);
    for (int j = 0; j < DA; ++j)
        s += row[j] * q_b[j] + row[DA + j] * k_b[j];
    c[i] = s;
}

// ---------------------------------------------------------------------------
// Attention: one block per l. Reads basis ONCE (fp32), stashes fp16 copy in
// smem for the y pass. u fp16 in; y fp16 out.
// smem: u (16x1024 fp32, 64KB) + basis (64x1024 fp16, 128KB) + scores (~4KB)
// ---------------------------------------------------------------------------
#define SS_LD 65
#define ATT_SMEM (BB*DHID*4 + RR*DHID*2 + BB*SS_LD*4)   // 200768 B

__global__ void __launch_bounds__(256) attention_kernel(
    const __half* __restrict__ u,     // (B*L, 1024) fp16
    const float* __restrict__ basis,  // (L, R, 1024)
    __half* __restrict__ yh)
{
    extern __shared__ char smraw2[];
    float*  u_s = (float*)smraw2;                                // 64 KB
    __half* b_s = (__half*)(smraw2 + BB * DHID * 4);             // 128 KB
    float*  s_s = (float*)(smraw2 + BB * DHID * 4 + RR * DHID * 2);

    const int l    = blockIdx.x;
    const int t    = threadIdx.x;
    const int warp = t >> 5;
    const int lane = t & 31;
    const float scale = 0.044194173824159216f;  // 1/sqrt(512)

    // Load u tile (fp16 -> fp32 smem)
    for (int it = 0; it < 8; ++it) {
        int idx = t + it * 256;
        int b   = idx >> 7;
        int d8  = (idx & 127) * 8;
        uint4 raw = *(const uint4*)&u[((size_t)b * LL + l) * DHID + d8];
        const __half2* hp = (const __half2*)&raw;
        float* dst = &u_s[b * DHID + d8];
        #pragma unroll
        for (int k = 0; k < 4; ++k) {
            float2 f = __half22float2(hp[k]);
            dst[2 * k]     = f.x;
            dst[2 * k + 1] = f.y;
        }
    }
    __syncthreads();

    const float* basl = basis + (size_t)l * RR * DHID;
    __half2* b2_s = (__half2*)b_s;

    // Phase 1: scores + stash fp16 basis in smem (each warp owns 8 rows)
    for (int rr = 0; rr < 8; ++rr) {
        int r = warp * 8 + rr;
        const float2* brow2 = (const float2*)(basl + (size_t)r * DHID);
        float2 bas[16];
        #pragma unroll
        for (int i = 0; i < 16; ++i) bas[i] = brow2[lane + 32 * i];
        #pragma unroll
        for (int i = 0; i < 16; ++i)
            b2_s[r * 512 + lane + 32 * i] = __floats2half2_rn(bas[i].x, bas[i].y);
        #pragma unroll
        for (int b = 0; b < BB; ++b) {
            const float2* ur2 = (const float2*)&u_s[b * DHID];
            float p = 0.f;
            #pragma unroll
            for (int i = 0; i < 16; ++i) {
                float2 uv = ur2[lane + 32 * i];
                p += bas[i].x * uv.x + bas[i].y * uv.y;
            }
            #pragma unroll
            for (int o = 16; o; o >>= 1) p += __shfl_xor_sync(0xffffffffu, p, o);
            if (lane == 0) s_s[b * SS_LD + r] = p * scale;
        }
    }
    __syncthreads();

    // Phase 2: softmax over r (64 per b); warp w handles b = 2w, 2w+1
    {
        int b0 = warp * 2;
        #pragma unroll
        for (int bi = 0; bi < 2; ++bi) {
            int b = b0 + bi;
            float v0 = s_s[b * SS_LD + lane];
            float v1 = s_s[b * SS_LD + lane + 32];
            float mx = fmaxf(v0, v1);
            #pragma unroll
            for (int o = 16; o; o >>= 1) mx = fmaxf(mx, __shfl_xor_sync(0xffffffffu, mx, o));
            float e0 = __expf(v0 - mx);
            float e1 = __expf(v1 - mx);
            float sum = e0 + e1;
            #pragma unroll
            for (int o = 16; o; o >>= 1) sum += __shfl_xor_sync(0xffffffffu, sum, o);
            float inv = 1.f / sum;
            s_s[b * SS_LD + lane]      = e0 * inv;
            s_s[b * SS_LD + lane + 32] = e1 * inv;
        }
    }
    __syncthreads();

    // Phase 3: y from smem fp16 basis (no second global basis read)
    #pragma unroll
    for (int i = 0; i < 2; ++i) {
        const int d2 = i * 256 + t;         // half2 column index (0..511)
        float2 acc[BB];
        #pragma unroll
        for (int b = 0; b < BB; ++b) acc[b] = make_float2(0.f, 0.f);
        #pragma unroll 4
        for (int r = 0; r < RR; ++r) {
            float2 f = __half22float2(b2_s[r * 512 + d2]);
            #pragma unroll
            for (int b = 0; b < BB; ++b) {
                float w = s_s[b * SS_LD + r];
                acc[b].x += w * f.x;
                acc[b].y += w * f.y;
            }
        }
        #pragma unroll
        for (int b = 0; b < BB; ++b)
            *(__half2*)&yh[((size_t)b * LL + l) * DHID + 2 * d2] =
                __floats2half2_rn(acc[b].x, acc[b].y);
    }
}

// ---------------------------------------------------------------------------
// Launch
// ---------------------------------------------------------------------------
extern "C" void kernel_launch(void* const* d_in, const int* in_sizes, int n_in,
                              void* d_out, int out_size)
{
    const float* s_emb  = (const float*)d_in[0];
    const float* t_emb  = (const float*)d_in[1];
    const float* basis  = (const float*)d_in[2];
    const float* q_W    = (const float*)d_in[3];
    const float* q_b    = (const float*)d_in[4];
    const float* k_W    = (const float*)d_in[5];
    const float* k_b    = (const float*)d_in[6];
    const float* qk_W   = (const float*)d_in[7];
    const float* qk_b   = (const float*)d_in[8];
    const float* bk_W   = (const float*)d_in[9];
    // d_in[10] = bk_b : provably unused (softmax shift invariance)
    const float* bv_W   = (const float*)d_in[11];
    const float* bv_b   = (const float*)d_in[12];
    float* out = (float*)d_out;

    float  *p_c;
    __half *p_sh, *p_th, *p_qh, *p_uh, *p_yh;
    __half *p_Ah, *p_Bmh, *p_bkTh, *p_bvh;
    cudaGetSymbolAddress((void**)&p_c,    g_c);
    cudaGetSymbolAddress((void**)&p_sh,   g_sh);
    cudaGetSymbolAddress((void**)&p_th,   g_th);
    cudaGetSymbolAddress((void**)&p_qh,   g_qh);
    cudaGetSymbolAddress((void**)&p_uh,   g_uh);
    cudaGetSymbolAddress((void**)&p_yh,   g_yh);
    cudaGetSymbolAddress((void**)&p_Ah,   g_Ah);
    cudaGetSymbolAddress((void**)&p_Bmh,  g_Bmh);
    cudaGetSymbolAddress((void**)&p_bkTh, g_bkTh);
    cudaGetSymbolAddress((void**)&p_bvh,  g_bvh);

    cudaFuncSetAttribute(attention_kernel,
                         cudaFuncAttributeMaxDynamicSharedMemorySize, ATT_SMEM);
    cudaFuncSetAttribute(gemm_h_nt,
                         cudaFuncAttributeMaxDynamicSharedMemorySize, SMEM_G);

    // launch 0: s,t -> fp16
    const int ne = MTOT * DHID;
    cvt_pair32to16<<<ne / 4 / 256, 256>>>(p_sh, s_emb, p_th, t_emb, ne);

    // launch 1: fused projection matrices Ah, Bmh (fp16 out)
    {
        dim3 grid(DHID / BN, 8);
        prep_weights_kernel<<<grid, 256>>>(p_Ah, p_Bmh, qk_W, q_W, k_W);
    }

    // launch 2: fused bias
    fuse_bias_kernel<<<1, DA>>>(p_c, qk_W, q_b, k_b, qk_b);

    // launch 3 (ncu capture slot): qk = s@A^T + t@Bm^T + c -> fp16
    {
        GArgs ga = { p_sh, p_Ah, p_th, p_Bmh, DHID, DHID };
        dim3 grid(DA / 128, MTOT / 128);
        gemm_h_nt<<<grid, 256, SMEM_G>>>(ga, p_c, nullptr, p_qh, MTOT, DA);
    }

    // launch 4: bk_W transpose -> fp16
    {
        dim3 tg(DHID / 32, DA / 32);
        transpose_h_kernel<<<tg, dim3(32, 8)>>>(p_bkTh, bk_W, DA, DHID);
    }

    // launch 5: bv_W -> fp16
    cvt32to16<<<(DA * DHID) / 4 / 256, 256>>>(p_bvh, bv_W, DA * DHID);

    // launch 6: u = qk @ bkT^T -> fp16
    {
        GArgs ga = { p_qh, p_bkTh, nullptr, nullptr, DA, 0 };
        dim3 grid(DHID / 128, MTOT / 128);
        gemm_h_nt<<<grid, 256, SMEM_G>>>(ga, nullptr, nullptr, p_uh, MTOT, DHID);
    }

    // launch 7: attention (basis read once, fp16 smem reuse)
    attention_kernel<<<LL, 256, ATT_SMEM>>>(p_uh, basis, p_yh);

    // launch 8: z = y @ bv_W^T + bv_b -> fp32 out
    {
        GArgs ga = { p_yh, p_bvh, nullptr, nullptr, DHID, 0 };
        dim3 grid(DA / 128, MTOT / 128);
        gemm_h_nt<<<grid, 256, SMEM_G>>>(ga, bv_b, out, nullptr, MTOT, DA);
    }
}

// round 11
// speedup vs baseline: 1.6316x; 1.6316x over previous
#include <cuda_runtime.h>
#include <cuda_fp16.h>
#include <math.h>
#include <stdint.h>

// Problem constants
#define DHID 1024
#define DA   512
#define BB   16
#define LL   2048
#define RR   64
#define MTOT (BB*LL)   // 32768

// ---------------------------------------------------------------------------
// Scratch (static device globals; no allocations allowed)
// ---------------------------------------------------------------------------
__device__ __half g_sh [(size_t)MTOT * DHID];  // student fp16
__device__ __half g_th [(size_t)MTOT * DHID];  // teacher fp16
__device__ __half g_qh [(size_t)MTOT * DA];    // qk fp16
__device__ __half g_uh [(size_t)MTOT * DHID];  // u fp16
__device__ __half g_yh [(size_t)MTOT * DHID];  // y fp16
__device__ float  g_c  [DA];                   // fused bias (fp32)
__device__ __half g_Ah  [DA * DHID];           // fused qk_W1 @ q_W (fp16)
__device__ __half g_Bmh [DA * DHID];           // fused qk_W2 @ k_W (fp16)
__device__ __half g_bkTh[DHID * DA];           // bk_W transposed (fp16)
__device__ __half g_bvh [DA * DHID];           // bv_W (fp16)

// ---------------------------------------------------------------------------
// mma / ldmatrix helpers
// ---------------------------------------------------------------------------
__device__ __forceinline__ void mma_f16(float* c, const uint32_t* a,
                                        uint32_t b0, uint32_t b1)
{
    asm volatile(
        "mma.sync.aligned.m16n8k16.row.col.f32.f16.f16.f32 "
        "{%0,%1,%2,%3}, {%4,%5,%6,%7}, {%8,%9}, {%0,%1,%2,%3};\n"
        : "+f"(c[0]), "+f"(c[1]), "+f"(c[2]), "+f"(c[3])
        : "r"(a[0]), "r"(a[1]), "r"(a[2]), "r"(a[3]), "r"(b0), "r"(b1));
}

__device__ __forceinline__ void ldm_x4(uint32_t* r, uint32_t addr)
{
    asm volatile(
        "ldmatrix.sync.aligned.m8n8.x4.shared.b16 {%0,%1,%2,%3}, [%4];\n"
        : "=r"(r[0]), "=r"(r[1]), "=r"(r[2]), "=r"(r[3]) : "r"(addr));
}

__device__ __forceinline__ void ldm_x4_trans(uint32_t* r, uint32_t addr)
{
    asm volatile(
        "ldmatrix.sync.aligned.m8n8.x4.trans.shared.b16 {%0,%1,%2,%3}, [%4];\n"
        : "=r"(r[0]), "=r"(r[1]), "=r"(r[2]), "=r"(r[3]) : "r"(addr));
}

__device__ __forceinline__ uint32_t smem_u32(const void* p) {
    uint32_t a;
    asm("{ .reg .u64 t; cvta.to.shared.u64 t, %1; cvt.u32.u64 %0, t; }"
        : "=r"(a) : "l"(p));
    return a;
}

#define CP_ASYNC16(dst, src) \
    asm volatile("cp.async.cg.shared.global [%0], [%1], 16;" \
                 :: "r"(dst), "l"(src) : "memory")
#define CP_COMMIT() asm volatile("cp.async.commit_group;" ::: "memory")
#define CP_WAIT1()  asm volatile("cp.async.wait_group 1;" ::: "memory")
#define CP_WAIT0()  asm volatile("cp.async.wait_group 0;" ::: "memory")

// ---------------------------------------------------------------------------
// fp16 GEMM (NT), K-chunk = 64 (unchanged from best config)
// ---------------------------------------------------------------------------
#define ROWB   144
#define PLANE  (128 * ROWB)           // 18432 B
#define NSTAGE 3
#define SMEM_G (NSTAGE * 2 * PLANE)   // 110592 B -> occ 2

struct GArgs {
    const __half *X1, *W1;
    const __half *X2, *W2;
    int K1, K2;
};

__device__ __forceinline__ void ld_frags(
    uint32_t abase, uint32_t bbase, uint32_t kb, uint32_t* af, uint32_t* bf)
{
    ldm_x4(af + 0, abase + kb);
    ldm_x4(af + 4, abase + kb + 16 * ROWB);
    #pragma unroll
    for (int j = 0; j < 4; ++j) ldm_x4(bf + 4 * j, bbase + kb + j * 16 * ROWB);
}

__global__ void __launch_bounds__(256, 2) gemm_h_nt(
    GArgs ga,
    const float* __restrict__ bias,
    float* __restrict__ Cf,               // fp32 out (nullable)
    __half* __restrict__ Ch,              // fp16 out (if Cf null)
    int M, int N)
{
    extern __shared__ __align__(16) char smraw[];
    const uint32_t sm0 = smem_u32(smraw);

    const int t    = threadIdx.x;
    const int warp = t >> 5;
    const int lane = t & 31;
    const int bm   = blockIdx.y * 128;
    const int bn   = blockIdx.x * 128;
    const int mw   = (warp & 3) * 32;
    const int nw   = (warp >> 2) * 64;
    const uint32_t laneoff = (lane & 15) * ROWB + (lane >> 4) * 16;
    const uint32_t aBase   = mw * ROWB + laneoff;
    const uint32_t bBase   = PLANE + nw * ROWB + laneoff;

    const int rbase = t >> 3;
    const int grp   = t & 7;
    const __half *pX1[4], *pW1[4], *pX2[4], *pW2[4];
    uint32_t dofA[4], dofB[4];
    #pragma unroll
    for (int o = 0; o < 4; ++o) {
        const int row = rbase + o * 32;
        pX1[o] = ga.X1 + (size_t)(bm + row) * ga.K1 + grp * 8;
        pW1[o] = ga.W1 + (size_t)(bn + row) * ga.K1 + grp * 8;
        dofA[o] = row * ROWB + grp * 16;
        dofB[o] = PLANE + row * ROWB + grp * 16;
    }
    if (ga.X2) {
        #pragma unroll
        for (int o = 0; o < 4; ++o) {
            const int row = rbase + o * 32;
            pX2[o] = ga.X2 + (size_t)(bm + row) * ga.K2 + grp * 8;
            pW2[o] = ga.W2 + (size_t)(bn + row) * ga.K2 + grp * 8;
        }
    }

    const int nc1 = ga.K1 / 64;
    const int nch = ga.X2 ? nc1 + ga.K2 / 64 : nc1;

    float acc[2][8][4];
    #pragma unroll
    for (int i = 0; i < 2; ++i)
        #pragma unroll
        for (int j = 0; j < 8; ++j)
            #pragma unroll
            for (int e = 0; e < 4; ++e) acc[i][j][e] = 0.f;

    auto issue = [&](int c) {
        const uint32_t sb = sm0 + (c % NSTAGE) * 2 * PLANE;
        const bool p2 = (c >= nc1);
        const int  k  = (p2 ? (c - nc1) : c) * 64;
        const __half* const* pX = p2 ? pX2 : pX1;
        const __half* const* pW = p2 ? pW2 : pW1;
        #pragma unroll
        for (int o = 0; o < 4; ++o) CP_ASYNC16(sb + dofA[o], pX[o] + k);
        #pragma unroll
        for (int o = 0; o < 4; ++o) CP_ASYNC16(sb + dofB[o], pW[o] + k);
        CP_COMMIT();
    };

    if (0 < nch) issue(0);
    if (1 < nch) issue(1);

    uint32_t af[2][8], bf[2][16];

    for (int c = 0; c < nch; ++c) {
        if (c + 2 <= nch) CP_WAIT1(); else CP_WAIT0();
        __syncthreads();

        const uint32_t sb = sm0 + (c % NSTAGE) * 2 * PLANE;
        const uint32_t ab = sb + aBase;
        const uint32_t bb = sb + bBase;

        ld_frags(ab, bb, 0, af[0], bf[0]);
        #pragma unroll
        for (int ks = 0; ks < 4; ++ks) {
            const int cur = ks & 1;
            if (ks < 3)
                ld_frags(ab, bb, (ks + 1) * 32, af[cur ^ 1], bf[cur ^ 1]);
            #pragma unroll
            for (int i = 0; i < 2; ++i) {
                const uint32_t* ah = af[cur] + 4 * i;
                #pragma unroll
                for (int j8 = 0; j8 < 8; ++j8) {
                    uint32_t b0 = bf[cur][4 * (j8 >> 1) + (j8 & 1)];
                    uint32_t b1 = bf[cur][4 * (j8 >> 1) + (j8 & 1) + 2];
                    mma_f16(acc[i][j8], ah, b0, b1);
                }
            }
        }

        if (c + 2 < nch) issue(c + 2);
    }

    const int g = lane >> 2;
    const int q = lane & 3;
    #pragma unroll
    for (int i = 0; i < 2; ++i) {
        #pragma unroll
        for (int j8 = 0; j8 < 8; ++j8) {
            const int r0  = bm + mw + 16 * i + g;
            const int col = bn + nw + 8 * j8 + 2 * q;
            const float b0v = bias ? bias[col]     : 0.f;
            const float b1v = bias ? bias[col + 1] : 0.f;
            float v00 = acc[i][j8][0] + b0v, v01 = acc[i][j8][1] + b1v;
            float v10 = acc[i][j8][2] + b0v, v11 = acc[i][j8][3] + b1v;
            if (Cf) {
                *(float2*)&Cf[(size_t)r0 * N + col]       = make_float2(v00, v01);
                *(float2*)&Cf[(size_t)(r0 + 8) * N + col] = make_float2(v10, v11);
            } else {
                *(__half2*)&Ch[(size_t)r0 * N + col]       = __floats2half2_rn(v00, v01);
                *(__half2*)&Ch[(size_t)(r0 + 8) * N + col] = __floats2half2_rn(v10, v11);
            }
        }
    }
}

// ---------------------------------------------------------------------------
// Converters
// ---------------------------------------------------------------------------
__global__ void cvt_pair32to16(__half* __restrict__ h0, const float* __restrict__ s0,
                               __half* __restrict__ h1, const float* __restrict__ s1,
                               int n)
{
    int i = (blockIdx.x * blockDim.x + threadIdx.x) * 4;
    if (i >= n) return;
    float4 a = *(const float4*)&s0[i];
    *(__half2*)&h0[i]     = __floats2half2_rn(a.x, a.y);
    *(__half2*)&h0[i + 2] = __floats2half2_rn(a.z, a.w);
    float4 b = *(const float4*)&s1[i];
    *(__half2*)&h1[i]     = __floats2half2_rn(b.x, b.y);
    *(__half2*)&h1[i + 2] = __floats2half2_rn(b.z, b.w);
}

__global__ void cvt32to16(__half* __restrict__ h, const float* __restrict__ s, int n)
{
    int i = (blockIdx.x * blockDim.x + threadIdx.x) * 4;
    if (i >= n) return;
    float4 v = *(const float4*)&s[i];
    *(__half2*)&h[i]     = __floats2half2_rn(v.x, v.y);
    *(__half2*)&h[i + 2] = __floats2half2_rn(v.z, v.w);
}

// ---------------------------------------------------------------------------
// Transpose (fp32 in -> fp16 out), once for bk_W
// ---------------------------------------------------------------------------
__global__ void transpose_h_kernel(__half* __restrict__ out,
                                   const float* __restrict__ in,
                                   int Rrows, int Ccols)
{
    __shared__ float tile[32][33];
    int x = blockIdx.x * 32 + threadIdx.x;
    int y = blockIdx.y * 32 + threadIdx.y;
    #pragma unroll
    for (int i = 0; i < 4; ++i)
        tile[threadIdx.y + 8 * i][threadIdx.x] = in[(size_t)(y + 8 * i) * Ccols + x];
    __syncthreads();
    x = blockIdx.y * 32 + threadIdx.x;
    y = blockIdx.x * 32 + threadIdx.y;
    #pragma unroll
    for (int i = 0; i < 4; ++i)
        out[(size_t)(y + 8 * i) * Rrows + x] =
            __float2half_rn(tile[threadIdx.x][threadIdx.y + 8 * i]);
}

// ---------------------------------------------------------------------------
// Combined prep: Ah = qk_W[:, :512] @ q_W ; Bmh = qk_W[:, 512:] @ k_W
// ---------------------------------------------------------------------------
#define BM 128
#define BN 128
#define BK 16

__global__ void __launch_bounds__(256, 2) prep_weights_kernel(
    __half* __restrict__ CA, __half* __restrict__ CB,
    const float* __restrict__ qk_W,
    const float* __restrict__ q_W, const float* __restrict__ k_W)
{
    const int half  = blockIdx.y >> 2;
    const int by    = blockIdx.y & 3;
    __half* C       = half ? CB : CA;
    const float* X  = half ? qk_W + DA : qk_W;
    const float* W  = half ? k_W : q_W;
    const int N = DHID, K = DA, ldx = 2 * DA;

    __shared__ float As[BK][BM];
    __shared__ float Bs[BK][BN];
    const int t  = threadIdx.x;
    const int bm = by * BM;
    const int bn = blockIdx.x * BN;

    float acc[8][8];
    #pragma unroll
    for (int i = 0; i < 8; ++i)
        #pragma unroll
        for (int j = 0; j < 8; ++j) acc[i][j] = 0.f;

    const int lrow = t >> 2;
    const int lc4  = (t & 3) * 4;
    const int wk   = t >> 5;
    const int wn4  = (t & 31) * 4;

    for (int k0 = 0; k0 < K; k0 += BK) {
        #pragma unroll
        for (int h = 0; h < 2; ++h) {
            int row = lrow + h * 64;
            float4 v = *(const float4*)&X[(size_t)(bm + row) * ldx + k0 + lc4];
            As[lc4 + 0][row] = v.x;
            As[lc4 + 1][row] = v.y;
            As[lc4 + 2][row] = v.z;
            As[lc4 + 3][row] = v.w;
            int k = wk + h * 8;
            float4 w = *(const float4*)&W[(size_t)(k0 + k) * N + bn + wn4];
            *(float4*)&Bs[k][wn4] = w;
        }
        __syncthreads();
        const int m8 = (t >> 4) * 8;
        const int n8 = (t & 15) * 8;
        #pragma unroll
        for (int kk = 0; kk < BK; ++kk) {
            float a[8], b[8];
            *(float4*)&a[0] = *(const float4*)&As[kk][m8];
            *(float4*)&a[4] = *(const float4*)&As[kk][m8 + 4];
            *(float4*)&b[0] = *(const float4*)&Bs[kk][n8];
            *(float4*)&b[4] = *(const float4*)&Bs[kk][n8 + 4];
            #pragma unroll
            for (int i = 0; i < 8; ++i)
                #pragma unroll
                for (int j = 0; j < 8; ++j)
                    acc[i][j] += a[i] * b[j];
        }
        __syncthreads();
    }

    const int m0 = bm + (t >> 4) * 8;
    const int n0 = bn + (t & 15) * 8;
    #pragma unroll
    for (int i = 0; i < 8; ++i) {
        __half2 h0 = __floats2half2_rn(acc[i][0], acc[i][1]);
        __half2 h1 = __floats2half2_rn(acc[i][2], acc[i][3]);
        __half2 h2 = __floats2half2_rn(acc[i][4], acc[i][5]);
        __half2 h3 = __floats2half2_rn(acc[i][6], acc[i][7]);
        __half* dst = &C[(size_t)(m0 + i) * N + n0];
        *(__half2*)(dst + 0) = h0;
        *(__half2*)(dst + 2) = h1;
        *(__half2*)(dst + 4) = h2;
        *(__half2*)(dst + 6) = h3;
    }
}

// ---------------------------------------------------------------------------
// Fused bias
// ---------------------------------------------------------------------------
__global__ void fuse_bias_kernel(float* __restrict__ c,
                                 const float* __restrict__ qk_W,
                                 const float* __restrict__ q_b,
                                 const float* __restrict__ k_b,
                                 const float* __restrict__ qk_b)
{
    int i = blockIdx.x * blockDim.x + threadIdx.x;
    if (i >= DA) return;
    float s = qk_b[i];
    const float* row = qk_W + (size_t)i * (2 * DA);
    for (int j = 0; j < DA; ++j)
        s += row[j] * q_b[j] + row[DA + j] * k_b[j];
    c[i] = s;
}

// ---------------------------------------------------------------------------
// Attention v2 (tensor-core): one block per l, 256 threads.
// scores = u(16x1024) @ basis^T via mma; softmax; y = W(16x64) @ basis via
// mma with ldmatrix.trans B-fragments. basis staged fp16 in smem ONCE.
// smem: u 16x(1024+8)h = 33024 B; basis 64x(1024+8)h = 132096 B;
//       w_h 16x72h = 2304 B; s_s 16x65 f32 = 4160 B. total 171584 B.
// ---------------------------------------------------------------------------
#define U_ST   2064                    // bytes per u/basis smem row
#define OFF_U  0
#define OFF_B  33024
#define OFF_W  (33024 + 132096)        // 165120
#define OFF_S  (OFF_W + 2304)          // 167424
#define ATT2_SMEM (OFF_S + BB * 65 * 4)  // 171584
#define SS_LD 65

__global__ void __launch_bounds__(256) attention_kernel(
    const __half* __restrict__ u,     // (B*L, 1024) fp16
    const float* __restrict__ basis,  // (L, R, 1024) fp32
    __half* __restrict__ yh)
{
    extern __shared__ __align__(16) char smraw2[];
    const uint32_t sm0 = smem_u32(smraw2);
    float*  s_s = (float*)(smraw2 + OFF_S);
    __half* w_h = (__half*)(smraw2 + OFF_W);

    const int l    = blockIdx.x;
    const int t    = threadIdx.x;
    const int warp = t >> 5;
    const int lane = t & 31;
    const int g    = lane >> 2;
    const int q    = lane & 3;
    const float scale = 0.044194173824159216f;  // 1/sqrt(512)

    // --- Stage u (fp16, cp.async) ---
    #pragma unroll
    for (int it = 0; it < 8; ++it) {
        int idx = t + it * 256;         // 0..2047
        int b   = idx >> 7;
        int d8  = (idx & 127) * 8;
        CP_ASYNC16(sm0 + OFF_U + b * U_ST + d8 * 2,
                   &u[((size_t)b * LL + l) * DHID + d8]);
    }
    CP_COMMIT();

    // --- Stage basis (fp32 LDG -> fp16 STS), unrolled for MLP ---
    const float* basl = basis + (size_t)l * RR * DHID;
    #pragma unroll 1
    for (int blk = 0; blk < 8; ++blk) {
        float4 v[8];
        #pragma unroll
        for (int j = 0; j < 8; ++j) {
            int idx = t + (blk * 8 + j) * 256;   // 0..16383
            v[j] = *(const float4*)&basl[idx * 4];
        }
        #pragma unroll
        for (int j = 0; j < 8; ++j) {
            int idx = t + (blk * 8 + j) * 256;
            int r   = idx >> 8;                  // 0..63
            int d4  = idx & 255;
            __half2 h01 = __floats2half2_rn(v[j].x, v[j].y);
            __half2 h23 = __floats2half2_rn(v[j].z, v[j].w);
            char* dst = smraw2 + OFF_B + r * U_ST + d4 * 8;
            *(__half2*)dst       = h01;
            *(__half2*)(dst + 4) = h23;
        }
    }
    CP_WAIT0();
    __syncthreads();

    // --- Phase 1: scores via mma. warp owns r-rows [warp*8, warp*8+8) ---
    {
        float acc4[4] = {0.f, 0.f, 0.f, 0.f};
        const uint32_t aAddr = sm0 + OFF_U + (lane & 15) * U_ST + (lane >> 4) * 16;
        const uint32_t bAddr = sm0 + OFF_B + (warp * 8 + (lane & 7)) * U_ST
                                          + (lane >> 3) * 16;
        #pragma unroll 4
        for (int kt2 = 0; kt2 < 32; ++kt2) {
            const uint32_t kb = kt2 * 64;        // 2 k-tiles = 64 B
            uint32_t a0[4], a1[4], b4[4];
            ldm_x4(a0, aAddr + kb);
            ldm_x4(a1, aAddr + kb + 32);
            ldm_x4(b4, bAddr + kb);
            mma_f16(acc4, a0, b4[0], b4[1]);
            mma_f16(acc4, a1, b4[2], b4[3]);
        }
        const int r0 = warp * 8 + 2 * q;
        s_s[g * SS_LD + r0]           = acc4[0] * scale;
        s_s[g * SS_LD + r0 + 1]       = acc4[1] * scale;
        s_s[(g + 8) * SS_LD + r0]     = acc4[2] * scale;
        s_s[(g + 8) * SS_LD + r0 + 1] = acc4[3] * scale;
    }
    __syncthreads();

    // --- Phase 2: softmax over r; warp w handles b = 2w, 2w+1 ---
    {
        int b0 = warp * 2;
        #pragma unroll
        for (int bi = 0; bi < 2; ++bi) {
            int b = b0 + bi;
            float v0 = s_s[b * SS_LD + lane];
            float v1 = s_s[b * SS_LD + lane + 32];
            float mx = fmaxf(v0, v1);
            #pragma unroll
            for (int o = 16; o; o >>= 1) mx = fmaxf(mx, __shfl_xor_sync(0xffffffffu, mx, o));
            float e0 = __expf(v0 - mx);
            float e1 = __expf(v1 - mx);
            float sum = e0 + e1;
            #pragma unroll
            for (int o = 16; o; o >>= 1) sum += __shfl_xor_sync(0xffffffffu, sum, o);
            float inv = 1.f / sum;
            w_h[b * 72 + lane]      = __float2half_rn(e0 * inv);
            w_h[b * 72 + lane + 32] = __float2half_rn(e1 * inv);
        }
    }
    __syncthreads();

    // --- Phase 3: y = W @ basis via mma (.trans B). warp owns d-span 128 ---
    {
        uint32_t afr[4][4];
        const uint32_t wAddr = sm0 + OFF_W + (lane & 15) * 144 + (lane >> 4) * 16;
        #pragma unroll
        for (int kt = 0; kt < 4; ++kt) ldm_x4(afr[kt], wAddr + kt * 32);

        const int d0w = warp * 128;
        const uint32_t bTA = sm0 + OFF_B + (lane & 15) * U_ST + (lane >> 4) * 16;
        #pragma unroll
        for (int jp = 0; jp < 8; ++jp) {
            const int d0 = d0w + jp * 16;
            float acc2[2][4];
            #pragma unroll
            for (int e = 0; e < 4; ++e) { acc2[0][e] = 0.f; acc2[1][e] = 0.f; }
            #pragma unroll
            for (int kt = 0; kt < 4; ++kt) {
                uint32_t bt[4];
                ldm_x4_trans(bt, bTA + kt * 16 * U_ST + d0 * 2);
                mma_f16(acc2[0], afr[kt], bt[0], bt[1]);
                mma_f16(acc2[1], afr[kt], bt[2], bt[3]);
            }
            #pragma unroll
            for (int jj = 0; jj < 2; ++jj) {
                const int col = d0 + 8 * jj + 2 * q;
                *(__half2*)&yh[((size_t)g * LL + l) * DHID + col] =
                    __floats2half2_rn(acc2[jj][0], acc2[jj][1]);
                *(__half2*)&yh[((size_t)(g + 8) * LL + l) * DHID + col] =
                    __floats2half2_rn(acc2[jj][2], acc2[jj][3]);
            }
        }
    }
}

// ---------------------------------------------------------------------------
// Launch
// ---------------------------------------------------------------------------
extern "C" void kernel_launch(void* const* d_in, const int* in_sizes, int n_in,
                              void* d_out, int out_size)
{
    const float* s_emb  = (const float*)d_in[0];
    const float* t_emb  = (const float*)d_in[1];
    const float* basis  = (const float*)d_in[2];
    const float* q_W    = (const float*)d_in[3];
    const float* q_b    = (const float*)d_in[4];
    const float* k_W    = (const float*)d_in[5];
    const float* k_b    = (const float*)d_in[6];
    const float* qk_W   = (const float*)d_in[7];
    const float* qk_b   = (const float*)d_in[8];
    const float* bk_W   = (const float*)d_in[9];
    // d_in[10] = bk_b : provably unused (softmax shift invariance)
    const float* bv_W   = (const float*)d_in[11];
    const float* bv_b   = (const float*)d_in[12];
    float* out = (float*)d_out;

    float  *p_c;
    __half *p_sh, *p_th, *p_qh, *p_uh, *p_yh;
    __half *p_Ah, *p_Bmh, *p_bkTh, *p_bvh;
    cudaGetSymbolAddress((void**)&p_c,    g_c);
    cudaGetSymbolAddress((void**)&p_sh,   g_sh);
    cudaGetSymbolAddress((void**)&p_th,   g_th);
    cudaGetSymbolAddress((void**)&p_qh,   g_qh);
    cudaGetSymbolAddress((void**)&p_uh,   g_uh);
    cudaGetSymbolAddress((void**)&p_yh,   g_yh);
    cudaGetSymbolAddress((void**)&p_Ah,   g_Ah);
    cudaGetSymbolAddress((void**)&p_Bmh,  g_Bmh);
    cudaGetSymbolAddress((void**)&p_bkTh, g_bkTh);
    cudaGetSymbolAddress((void**)&p_bvh,  g_bvh);

    cudaFuncSetAttribute(attention_kernel,
                         cudaFuncAttributeMaxDynamicSharedMemorySize, ATT2_SMEM);
    cudaFuncSetAttribute(gemm_h_nt,
                         cudaFuncAttributeMaxDynamicSharedMemorySize, SMEM_G);

    // launch 0: s,t -> fp16
    const int ne = MTOT * DHID;
    cvt_pair32to16<<<ne / 4 / 256, 256>>>(p_sh, s_emb, p_th, t_emb, ne);

    // launch 1: fused projection matrices Ah, Bmh
    {
        dim3 grid(DHID / BN, 8);
        prep_weights_kernel<<<grid, 256>>>(p_Ah, p_Bmh, qk_W, q_W, k_W);
    }

    // launch 2: fused bias
    fuse_bias_kernel<<<1, DA>>>(p_c, qk_W, q_b, k_b, qk_b);

    // launch 3 (ncu capture slot): qk = s@A^T + t@Bm^T + c -> fp16
    {
        GArgs ga = { p_sh, p_Ah, p_th, p_Bmh, DHID, DHID };
        dim3 grid(DA / 128, MTOT / 128);
        gemm_h_nt<<<grid, 256, SMEM_G>>>(ga, p_c, nullptr, p_qh, MTOT, DA);
    }

    // launch 4: bk_W transpose -> fp16
    {
        dim3 tg(DHID / 32, DA / 32);
        transpose_h_kernel<<<tg, dim3(32, 8)>>>(p_bkTh, bk_W, DA, DHID);
    }

    // launch 5: bv_W -> fp16
    cvt32to16<<<(DA * DHID) / 4 / 256, 256>>>(p_bvh, bv_W, DA * DHID);

    // launch 6: u = qk @ bkT^T -> fp16
    {
        GArgs ga = { p_qh, p_bkTh, nullptr, nullptr, DA, 0 };
        dim3 grid(DHID / 128, MTOT / 128);
        gemm_h_nt<<<grid, 256, SMEM_G>>>(ga, nullptr, nullptr, p_uh, MTOT, DHID);
    }

    // launch 7: attention v2 (tensor cores)
    attention_kernel<<<LL, 256, ATT2_SMEM>>>(p_uh, basis, p_yh);

    // launch 8: z = y @ bv_W^T + bv_b -> fp32 out
    {
        GArgs ga = { p_yh, p_bvh, nullptr, nullptr, DHID, 0 };
        dim3 grid(DA / 128, MTOT / 128);
        gemm_h_nt<<<grid, 256, SMEM_G>>>(ga, bv_b, out, nullptr, MTOT, DA);
    }
}

// round 12
// speedup vs baseline: 1.6319x; 1.0002x over previous
#include <cuda_runtime.h>
#include <cuda_fp16.h>
#include <math.h>
#include <stdint.h>

// Problem constants
#define DHID 1024
#define DA   512
#define BB   16
#define LL   2048
#define RR   64
#define MTOT (BB*LL)   // 32768

// ---------------------------------------------------------------------------
// Scratch (static device globals; no allocations allowed)
// ---------------------------------------------------------------------------
__device__ __half g_sh [(size_t)MTOT * DHID];  // student fp16
__device__ __half g_th [(size_t)MTOT * DHID];  // teacher fp16
__device__ __half g_qh [(size_t)MTOT * DA];    // qk fp16
__device__ __half g_uh [(size_t)MTOT * DHID];  // u fp16
__device__ __half g_yh [(size_t)MTOT * DHID];  // y fp16
__device__ float  g_c  [DA];                   // fused bias (fp32)
__device__ __half g_Ah  [DA * DHID];           // fused qk_W1 @ q_W (fp16)
__device__ __half g_Bmh [DA * DHID];           // fused qk_W2 @ k_W (fp16)
__device__ __half g_bkTh[DHID * DA];           // bk_W transposed (fp16)
__device__ __half g_bvh [DA * DHID];           // bv_W (fp16)

// ---------------------------------------------------------------------------
// mma / ldmatrix helpers
// ---------------------------------------------------------------------------
__device__ __forceinline__ void mma_f16(float* c, const uint32_t* a,
                                        uint32_t b0, uint32_t b1)
{
    asm volatile(
        "mma.sync.aligned.m16n8k16.row.col.f32.f16.f16.f32 "
        "{%0,%1,%2,%3}, {%4,%5,%6,%7}, {%8,%9}, {%0,%1,%2,%3};\n"
        : "+f"(c[0]), "+f"(c[1]), "+f"(c[2]), "+f"(c[3])
        : "r"(a[0]), "r"(a[1]), "r"(a[2]), "r"(a[3]), "r"(b0), "r"(b1));
}

__device__ __forceinline__ void ldm_x4(uint32_t* r, uint32_t addr)
{
    asm volatile(
        "ldmatrix.sync.aligned.m8n8.x4.shared.b16 {%0,%1,%2,%3}, [%4];\n"
        : "=r"(r[0]), "=r"(r[1]), "=r"(r[2]), "=r"(r[3]) : "r"(addr));
}

__device__ __forceinline__ void ldm_x4_trans(uint32_t* r, uint32_t addr)
{
    asm volatile(
        "ldmatrix.sync.aligned.m8n8.x4.trans.shared.b16 {%0,%1,%2,%3}, [%4];\n"
        : "=r"(r[0]), "=r"(r[1]), "=r"(r[2]), "=r"(r[3]) : "r"(addr));
}

__device__ __forceinline__ uint32_t smem_u32(const void* p) {
    uint32_t a;
    asm("{ .reg .u64 t; cvta.to.shared.u64 t, %1; cvt.u32.u64 %0, t; }"
        : "=r"(a) : "l"(p));
    return a;
}

#define CP_ASYNC16(dst, src) \
    asm volatile("cp.async.cg.shared.global [%0], [%1], 16;" \
                 :: "r"(dst), "l"(src) : "memory")
#define CP_COMMIT() asm volatile("cp.async.commit_group;" ::: "memory")
#define CP_WAIT1()  asm volatile("cp.async.wait_group 1;" ::: "memory")
#define CP_WAIT0()  asm volatile("cp.async.wait_group 0;" ::: "memory")

// ---------------------------------------------------------------------------
// fp16 GEMM (NT), K-chunk = 64 (unchanged from best config)
// ---------------------------------------------------------------------------
#define ROWB   144
#define PLANE  (128 * ROWB)           // 18432 B
#define NSTAGE 3
#define SMEM_G (NSTAGE * 2 * PLANE)   // 110592 B -> occ 2

struct GArgs {
    const __half *X1, *W1;
    const __half *X2, *W2;
    int K1, K2;
};

__device__ __forceinline__ void ld_frags(
    uint32_t abase, uint32_t bbase, uint32_t kb, uint32_t* af, uint32_t* bf)
{
    ldm_x4(af + 0, abase + kb);
    ldm_x4(af + 4, abase + kb + 16 * ROWB);
    #pragma unroll
    for (int j = 0; j < 4; ++j) ldm_x4(bf + 4 * j, bbase + kb + j * 16 * ROWB);
}

__global__ void __launch_bounds__(256, 2) gemm_h_nt(
    GArgs ga,
    const float* __restrict__ bias,
    float* __restrict__ Cf,               // fp32 out (nullable)
    __half* __restrict__ Ch,              // fp16 out (if Cf null)
    int M, int N)
{
    extern __shared__ __align__(16) char smraw[];
    const uint32_t sm0 = smem_u32(smraw);

    const int t    = threadIdx.x;
    const int warp = t >> 5;
    const int lane = t & 31;
    const int bm   = blockIdx.y * 128;
    const int bn   = blockIdx.x * 128;
    const int mw   = (warp & 3) * 32;
    const int nw   = (warp >> 2) * 64;
    const uint32_t laneoff = (lane & 15) * ROWB + (lane >> 4) * 16;
    const uint32_t aBase   = mw * ROWB + laneoff;
    const uint32_t bBase   = PLANE + nw * ROWB + laneoff;

    const int rbase = t >> 3;
    const int grp   = t & 7;
    const __half *pX1[4], *pW1[4], *pX2[4], *pW2[4];
    uint32_t dofA[4], dofB[4];
    #pragma unroll
    for (int o = 0; o < 4; ++o) {
        const int row = rbase + o * 32;
        pX1[o] = ga.X1 + (size_t)(bm + row) * ga.K1 + grp * 8;
        pW1[o] = ga.W1 + (size_t)(bn + row) * ga.K1 + grp * 8;
        dofA[o] = row * ROWB + grp * 16;
        dofB[o] = PLANE + row * ROWB + grp * 16;
    }
    if (ga.X2) {
        #pragma unroll
        for (int o = 0; o < 4; ++o) {
            const int row = rbase + o * 32;
            pX2[o] = ga.X2 + (size_t)(bm + row) * ga.K2 + grp * 8;
            pW2[o] = ga.W2 + (size_t)(bn + row) * ga.K2 + grp * 8;
        }
    }

    const int nc1 = ga.K1 / 64;
    const int nch = ga.X2 ? nc1 + ga.K2 / 64 : nc1;

    float acc[2][8][4];
    #pragma unroll
    for (int i = 0; i < 2; ++i)
        #pragma unroll
        for (int j = 0; j < 8; ++j)
            #pragma unroll
            for (int e = 0; e < 4; ++e) acc[i][j][e] = 0.f;

    auto issue = [&](int c) {
        const uint32_t sb = sm0 + (c % NSTAGE) * 2 * PLANE;
        const bool p2 = (c >= nc1);
        const int  k  = (p2 ? (c - nc1) : c) * 64;
        const __half* const* pX = p2 ? pX2 : pX1;
        const __half* const* pW = p2 ? pW2 : pW1;
        #pragma unroll
        for (int o = 0; o < 4; ++o) CP_ASYNC16(sb + dofA[o], pX[o] + k);
        #pragma unroll
        for (int o = 0; o < 4; ++o) CP_ASYNC16(sb + dofB[o], pW[o] + k);
        CP_COMMIT();
    };

    if (0 < nch) issue(0);
    if (1 < nch) issue(1);

    uint32_t af[2][8], bf[2][16];

    for (int c = 0; c < nch; ++c) {
        if (c + 2 <= nch) CP_WAIT1(); else CP_WAIT0();
        __syncthreads();

        const uint32_t sb = sm0 + (c % NSTAGE) * 2 * PLANE;
        const uint32_t ab = sb + aBase;
        const uint32_t bb = sb + bBase;

        ld_frags(ab, bb, 0, af[0], bf[0]);
        #pragma unroll
        for (int ks = 0; ks < 4; ++ks) {
            const int cur = ks & 1;
            if (ks < 3)
                ld_frags(ab, bb, (ks + 1) * 32, af[cur ^ 1], bf[cur ^ 1]);
            #pragma unroll
            for (int i = 0; i < 2; ++i) {
                const uint32_t* ah = af[cur] + 4 * i;
                #pragma unroll
                for (int j8 = 0; j8 < 8; ++j8) {
                    uint32_t b0 = bf[cur][4 * (j8 >> 1) + (j8 & 1)];
                    uint32_t b1 = bf[cur][4 * (j8 >> 1) + (j8 & 1) + 2];
                    mma_f16(acc[i][j8], ah, b0, b1);
                }
            }
        }

        if (c + 2 < nch) issue(c + 2);
    }

    const int g = lane >> 2;
    const int q = lane & 3;
    #pragma unroll
    for (int i = 0; i < 2; ++i) {
        #pragma unroll
        for (int j8 = 0; j8 < 8; ++j8) {
            const int r0  = bm + mw + 16 * i + g;
            const int col = bn + nw + 8 * j8 + 2 * q;
            const float b0v = bias ? bias[col]     : 0.f;
            const float b1v = bias ? bias[col + 1] : 0.f;
            float v00 = acc[i][j8][0] + b0v, v01 = acc[i][j8][1] + b1v;
            float v10 = acc[i][j8][2] + b0v, v11 = acc[i][j8][3] + b1v;
            if (Cf) {
                *(float2*)&Cf[(size_t)r0 * N + col]       = make_float2(v00, v01);
                *(float2*)&Cf[(size_t)(r0 + 8) * N + col] = make_float2(v10, v11);
            } else {
                *(__half2*)&Ch[(size_t)r0 * N + col]       = __floats2half2_rn(v00, v01);
                *(__half2*)&Ch[(size_t)(r0 + 8) * N + col] = __floats2half2_rn(v10, v11);
            }
        }
    }
}

// ---------------------------------------------------------------------------
// Converters
// ---------------------------------------------------------------------------
__global__ void cvt_pair32to16(__half* __restrict__ h0, const float* __restrict__ s0,
                               __half* __restrict__ h1, const float* __restrict__ s1,
                               int n)
{
    int i = (blockIdx.x * blockDim.x + threadIdx.x) * 4;
    if (i >= n) return;
    float4 a = *(const float4*)&s0[i];
    *(__half2*)&h0[i]     = __floats2half2_rn(a.x, a.y);
    *(__half2*)&h0[i + 2] = __floats2half2_rn(a.z, a.w);
    float4 b = *(const float4*)&s1[i];
    *(__half2*)&h1[i]     = __floats2half2_rn(b.x, b.y);
    *(__half2*)&h1[i + 2] = __floats2half2_rn(b.z, b.w);
}

__global__ void cvt32to16(__half* __restrict__ h, const float* __restrict__ s, int n)
{
    int i = (blockIdx.x * blockDim.x + threadIdx.x) * 4;
    if (i >= n) return;
    float4 v = *(const float4*)&s[i];
    *(__half2*)&h[i]     = __floats2half2_rn(v.x, v.y);
    *(__half2*)&h[i + 2] = __floats2half2_rn(v.z, v.w);
}

// ---------------------------------------------------------------------------
// Transpose (fp32 in -> fp16 out), once for bk_W
// ---------------------------------------------------------------------------
__global__ void transpose_h_kernel(__half* __restrict__ out,
                                   const float* __restrict__ in,
                                   int Rrows, int Ccols)
{
    __shared__ float tile[32][33];
    int x = blockIdx.x * 32 + threadIdx.x;
    int y = blockIdx.y * 32 + threadIdx.y;
    #pragma unroll
    for (int i = 0; i < 4; ++i)
        tile[threadIdx.y + 8 * i][threadIdx.x] = in[(size_t)(y + 8 * i) * Ccols + x];
    __syncthreads();
    x = blockIdx.y * 32 + threadIdx.x;
    y = blockIdx.x * 32 + threadIdx.y;
    #pragma unroll
    for (int i = 0; i < 4; ++i)
        out[(size_t)(y + 8 * i) * Rrows + x] =
            __float2half_rn(tile[threadIdx.x][threadIdx.y + 8 * i]);
}

// ---------------------------------------------------------------------------
// Combined prep: Ah = qk_W[:, :512] @ q_W ; Bmh = qk_W[:, 512:] @ k_W
// ---------------------------------------------------------------------------
#define BM 128
#define BN 128
#define BK 16

__global__ void __launch_bounds__(256, 2) prep_weights_kernel(
    __half* __restrict__ CA, __half* __restrict__ CB,
    const float* __restrict__ qk_W,
    const float* __restrict__ q_W, const float* __restrict__ k_W)
{
    const int half  = blockIdx.y >> 2;
    const int by    = blockIdx.y & 3;
    __half* C       = half ? CB : CA;
    const float* X  = half ? qk_W + DA : qk_W;
    const float* W  = half ? k_W : q_W;
    const int N = DHID, K = DA, ldx = 2 * DA;

    __shared__ float As[BK][BM];
    __shared__ float Bs[BK][BN];
    const int t  = threadIdx.x;
    const int bm = by * BM;
    const int bn = blockIdx.x * BN;

    float acc[8][8];
    #pragma unroll
    for (int i = 0; i < 8; ++i)
        #pragma unroll
        for (int j = 0; j < 8; ++j) acc[i][j] = 0.f;

    const int lrow = t >> 2;
    const int lc4  = (t & 3) * 4;
    const int wk   = t >> 5;
    const int wn4  = (t & 31) * 4;

    for (int k0 = 0; k0 < K; k0 += BK) {
        #pragma unroll
        for (int h = 0; h < 2; ++h) {
            int row = lrow + h * 64;
            float4 v = *(const float4*)&X[(size_t)(bm + row) * ldx + k0 + lc4];
            As[lc4 + 0][row] = v.x;
            As[lc4 + 1][row] = v.y;
            As[lc4 + 2][row] = v.z;
            As[lc4 + 3][row] = v.w;
            int k = wk + h * 8;
            float4 w = *(const float4*)&W[(size_t)(k0 + k) * N + bn + wn4];
            *(float4*)&Bs[k][wn4] = w;
        }
        __syncthreads();
        const int m8 = (t >> 4) * 8;
        const int n8 = (t & 15) * 8;
        #pragma unroll
        for (int kk = 0; kk < BK; ++kk) {
            float a[8], b[8];
            *(float4*)&a[0] = *(const float4*)&As[kk][m8];
            *(float4*)&a[4] = *(const float4*)&As[kk][m8 + 4];
            *(float4*)&b[0] = *(const float4*)&Bs[kk][n8];
            *(float4*)&b[4] = *(const float4*)&Bs[kk][n8 + 4];
            #pragma unroll
            for (int i = 0; i < 8; ++i)
                #pragma unroll
                for (int j = 0; j < 8; ++j)
                    acc[i][j] += a[i] * b[j];
        }
        __syncthreads();
    }

    const int m0 = bm + (t >> 4) * 8;
    const int n0 = bn + (t & 15) * 8;
    #pragma unroll
    for (int i = 0; i < 8; ++i) {
        __half2 h0 = __floats2half2_rn(acc[i][0], acc[i][1]);
        __half2 h1 = __floats2half2_rn(acc[i][2], acc[i][3]);
        __half2 h2 = __floats2half2_rn(acc[i][4], acc[i][5]);
        __half2 h3 = __floats2half2_rn(acc[i][6], acc[i][7]);
        __half* dst = &C[(size_t)(m0 + i) * N + n0];
        *(__half2*)(dst + 0) = h0;
        *(__half2*)(dst + 2) = h1;
        *(__half2*)(dst + 4) = h2;
        *(__half2*)(dst + 6) = h3;
    }
}

// ---------------------------------------------------------------------------
// Fused bias
// ---------------------------------------------------------------------------
__global__ void fuse_bias_kernel(float* __restrict__ c,
                                 const float* __restrict__ qk_W,
                                 const float* __restrict__ q_b,
                                 const float* __restrict__ k_b,
                                 const float* __restrict__ qk_b)
{
    int i = blockIdx.x * blockDim.x + threadIdx.x;
    if (i >= DA) return;
    float s = qk_b[i];
    const float* row = qk_W + (size_t)i * (2 * DA);
    for (int j = 0; j < DA; ++j)
        s += row[j] * q_b[j] + row[DA + j] * k_b[j];
    c[i] = s;
}

// ---------------------------------------------------------------------------
// Attention v2 (tensor-core): one block per l, 256 threads.
// scores = u(16x1024) @ basis^T via mma; softmax; y = W(16x64) @ basis via
// mma with ldmatrix.trans B-fragments. basis staged fp16 in smem ONCE.
// smem: u 16x(1024+8)h = 33024 B; basis 64x(1024+8)h = 132096 B;
//       w_h 16x72h = 2304 B; s_s 16x65 f32 = 4160 B. total 171584 B.
// ---------------------------------------------------------------------------
#define U_ST   2064                    // bytes per u/basis smem row
#define OFF_U  0
#define OFF_B  33024
#define OFF_W  (33024 + 132096)        // 165120
#define OFF_S  (OFF_W + 2304)          // 167424
#define ATT2_SMEM (OFF_S + BB * 65 * 4)  // 171584
#define SS_LD 65

__global__ void __launch_bounds__(256) attention_kernel(
    const __half* __restrict__ u,     // (B*L, 1024) fp16
    const float* __restrict__ basis,  // (L, R, 1024) fp32
    __half* __restrict__ yh)
{
    extern __shared__ __align__(16) char smraw2[];
    const uint32_t sm0 = smem_u32(smraw2);
    float*  s_s = (float*)(smraw2 + OFF_S);
    __half* w_h = (__half*)(smraw2 + OFF_W);

    const int l    = blockIdx.x;
    const int t    = threadIdx.x;
    const int warp = t >> 5;
    const int lane = t & 31;
    const int g    = lane >> 2;
    const int q    = lane & 3;
    const float scale = 0.044194173824159216f;  // 1/sqrt(512)

    // --- Stage u (fp16, cp.async) ---
    #pragma unroll
    for (int it = 0; it < 8; ++it) {
        int idx = t + it * 256;         // 0..2047
        int b   = idx >> 7;
        int d8  = (idx & 127) * 8;
        CP_ASYNC16(sm0 + OFF_U + b * U_ST + d8 * 2,
                   &u[((size_t)b * LL + l) * DHID + d8]);
    }
    CP_COMMIT();

    // --- Stage basis (fp32 LDG -> fp16 STS), unrolled for MLP ---
    const float* basl = basis + (size_t)l * RR * DHID;
    #pragma unroll 1
    for (int blk = 0; blk < 8; ++blk) {
        float4 v[8];
        #pragma unroll
        for (int j = 0; j < 8; ++j) {
            int idx = t + (blk * 8 + j) * 256;   // 0..16383
            v[j] = *(const float4*)&basl[idx * 4];
        }
        #pragma unroll
        for (int j = 0; j < 8; ++j) {
            int idx = t + (blk * 8 + j) * 256;
            int r   = idx >> 8;                  // 0..63
            int d4  = idx & 255;
            __half2 h01 = __floats2half2_rn(v[j].x, v[j].y);
            __half2 h23 = __floats2half2_rn(v[j].z, v[j].w);
            char* dst = smraw2 + OFF_B + r * U_ST + d4 * 8;
            *(__half2*)dst       = h01;
            *(__half2*)(dst + 4) = h23;
        }
    }
    CP_WAIT0();
    __syncthreads();

    // --- Phase 1: scores via mma. warp owns r-rows [warp*8, warp*8+8) ---
    {
        float acc4[4] = {0.f, 0.f, 0.f, 0.f};
        const uint32_t aAddr = sm0 + OFF_U + (lane & 15) * U_ST + (lane >> 4) * 16;
        const uint32_t bAddr = sm0 + OFF_B + (warp * 8 + (lane & 7)) * U_ST
                                          + (lane >> 3) * 16;
        #pragma unroll 4
        for (int kt2 = 0; kt2 < 32; ++kt2) {
            const uint32_t kb = kt2 * 64;        // 2 k-tiles = 64 B
            uint32_t a0[4], a1[4], b4[4];
            ldm_x4(a0, aAddr + kb);
            ldm_x4(a1, aAddr + kb + 32);
            ldm_x4(b4, bAddr + kb);
            mma_f16(acc4, a0, b4[0], b4[1]);
            mma_f16(acc4, a1, b4[2], b4[3]);
        }
        const int r0 = warp * 8 + 2 * q;
        s_s[g * SS_LD + r0]           = acc4[0] * scale;
        s_s[g * SS_LD + r0 + 1]       = acc4[1] * scale;
        s_s[(g + 8) * SS_LD + r0]     = acc4[2] * scale;
        s_s[(g + 8) * SS_LD + r0 + 1] = acc4[3] * scale;
    }
    __syncthreads();

    // --- Phase 2: softmax over r; warp w handles b = 2w, 2w+1 ---
    {
        int b0 = warp * 2;
        #pragma unroll
        for (int bi = 0; bi < 2; ++bi) {
            int b = b0 + bi;
            float v0 = s_s[b * SS_LD + lane];
            float v1 = s_s[b * SS_LD + lane + 32];
            float mx = fmaxf(v0, v1);
            #pragma unroll
            for (int o = 16; o; o >>= 1) mx = fmaxf(mx, __shfl_xor_sync(0xffffffffu, mx, o));
            float e0 = __expf(v0 - mx);
            float e1 = __expf(v1 - mx);
            float sum = e0 + e1;
            #pragma unroll
            for (int o = 16; o; o >>= 1) sum += __shfl_xor_sync(0xffffffffu, sum, o);
            float inv = 1.f / sum;
            w_h[b * 72 + lane]      = __float2half_rn(e0 * inv);
            w_h[b * 72 + lane + 32] = __float2half_rn(e1 * inv);
        }
    }
    __syncthreads();

    // --- Phase 3: y = W @ basis via mma (.trans B). warp owns d-span 128 ---
    {
        uint32_t afr[4][4];
        const uint32_t wAddr = sm0 + OFF_W + (lane & 15) * 144 + (lane >> 4) * 16;
        #pragma unroll
        for (int kt = 0; kt < 4; ++kt) ldm_x4(afr[kt], wAddr + kt * 32);

        const int d0w = warp * 128;
        const uint32_t bTA = sm0 + OFF_B + (lane & 15) * U_ST + (lane >> 4) * 16;
        #pragma unroll
        for (int jp = 0; jp < 8; ++jp) {
            const int d0 = d0w + jp * 16;
            float acc2[2][4];
            #pragma unroll
            for (int e = 0; e < 4; ++e) { acc2[0][e] = 0.f; acc2[1][e] = 0.f; }
            #pragma unroll
            for (int kt = 0; kt < 4; ++kt) {
                uint32_t bt[4];
                ldm_x4_trans(bt, bTA + kt * 16 * U_ST + d0 * 2);
                mma_f16(acc2[0], afr[kt], bt[0], bt[1]);
                mma_f16(acc2[1], afr[kt], bt[2], bt[3]);
            }
            #pragma unroll
            for (int jj = 0; jj < 2; ++jj) {
                const int col = d0 + 8 * jj + 2 * q;
                *(__half2*)&yh[((size_t)g * LL + l) * DHID + col] =
                    __floats2half2_rn(acc2[jj][0], acc2[jj][1]);
                *(__half2*)&yh[((size_t)(g + 8) * LL + l) * DHID + col] =
                    __floats2half2_rn(acc2[jj][2], acc2[jj][3]);
            }
        }
    }
}

// ---------------------------------------------------------------------------
// Launch
// ---------------------------------------------------------------------------
extern "C" void kernel_launch(void* const* d_in, const int* in_sizes, int n_in,
                              void* d_out, int out_size)
{
    const float* s_emb  = (const float*)d_in[0];
    const float* t_emb  = (const float*)d_in[1];
    const float* basis  = (const float*)d_in[2];
    const float* q_W    = (const float*)d_in[3];
    const float* q_b    = (const float*)d_in[4];
    const float* k_W    = (const float*)d_in[5];
    const float* k_b    = (const float*)d_in[6];
    const float* qk_W   = (const float*)d_in[7];
    const float* qk_b   = (const float*)d_in[8];
    const float* bk_W   = (const float*)d_in[9];
    // d_in[10] = bk_b : provably unused (softmax shift invariance)
    const float* bv_W   = (const float*)d_in[11];
    const float* bv_b   = (const float*)d_in[12];
    float* out = (float*)d_out;

    float  *p_c;
    __half *p_sh, *p_th, *p_qh, *p_uh, *p_yh;
    __half *p_Ah, *p_Bmh, *p_bkTh, *p_bvh;
    cudaGetSymbolAddress((void**)&p_c,    g_c);
    cudaGetSymbolAddress((void**)&p_sh,   g_sh);
    cudaGetSymbolAddress((void**)&p_th,   g_th);
    cudaGetSymbolAddress((void**)&p_qh,   g_qh);
    cudaGetSymbolAddress((void**)&p_uh,   g_uh);
    cudaGetSymbolAddress((void**)&p_yh,   g_yh);
    cudaGetSymbolAddress((void**)&p_Ah,   g_Ah);
    cudaGetSymbolAddress((void**)&p_Bmh,  g_Bmh);
    cudaGetSymbolAddress((void**)&p_bkTh, g_bkTh);
    cudaGetSymbolAddress((void**)&p_bvh,  g_bvh);

    cudaFuncSetAttribute(attention_kernel,
                         cudaFuncAttributeMaxDynamicSharedMemorySize, ATT2_SMEM);
    cudaFuncSetAttribute(gemm_h_nt,
                         cudaFuncAttributeMaxDynamicSharedMemorySize, SMEM_G);

    // launch 0: s,t -> fp16
    const int ne = MTOT * DHID;
    cvt_pair32to16<<<ne / 4 / 256, 256>>>(p_sh, s_emb, p_th, t_emb, ne);

    // launch 1: fused projection matrices Ah, Bmh
    {
        dim3 grid(DHID / BN, 8);
        prep_weights_kernel<<<grid, 256>>>(p_Ah, p_Bmh, qk_W, q_W, k_W);
    }

    // launch 2: fused bias
    fuse_bias_kernel<<<1, DA>>>(p_c, qk_W, q_b, k_b, qk_b);

    // launch 3 (ncu capture slot): qk = s@A^T + t@Bm^T + c -> fp16
    {
        GArgs ga = { p_sh, p_Ah, p_th, p_Bmh, DHID, DHID };
        dim3 grid(DA / 128, MTOT / 128);
        gemm_h_nt<<<grid, 256, SMEM_G>>>(ga, p_c, nullptr, p_qh, MTOT, DA);
    }

    // launch 4: bk_W transpose -> fp16
    {
        dim3 tg(DHID / 32, DA / 32);
        transpose_h_kernel<<<tg, dim3(32, 8)>>>(p_bkTh, bk_W, DA, DHID);
    }

    // launch 5: bv_W -> fp16
    cvt32to16<<<(DA * DHID) / 4 / 256, 256>>>(p_bvh, bv_W, DA * DHID);

    // launch 6: u = qk @ bkT^T -> fp16
    {
        GArgs ga = { p_qh, p_bkTh, nullptr, nullptr, DA, 0 };
        dim3 grid(DHID / 128, MTOT / 128);
        gemm_h_nt<<<grid, 256, SMEM_G>>>(ga, nullptr, nullptr, p_uh, MTOT, DHID);
    }

    // launch 7: attention v2 (tensor cores)
    attention_kernel<<<LL, 256, ATT2_SMEM>>>(p_uh, basis, p_yh);

    // launch 8: z = y @ bv_W^T + bv_b -> fp32 out
    {
        GArgs ga = { p_yh, p_bvh, nullptr, nullptr, DHID, 0 };
        dim3 grid(DA / 128, MTOT / 128);
        gemm_h_nt<<<grid, 256, SMEM_G>>>(ga, bv_b, out, nullptr, MTOT, DA);
    }
}

// round 13
// speedup vs baseline: 1.6351x; 1.0019x over previous
#include <cuda_runtime.h>
#include <cuda_fp16.h>
#include <math.h>
#include <stdint.h>

// Problem constants
#define DHID 1024
#define DA   512
#define BB   16
#define LL   2048
#define RR   64
#define MTOT (BB*LL)   // 32768

// ---------------------------------------------------------------------------
// Scratch (static device globals; no allocations allowed)
// ---------------------------------------------------------------------------
__device__ __half g_sh [(size_t)MTOT * DHID];  // student fp16
__device__ __half g_th [(size_t)MTOT * DHID];  // teacher fp16
__device__ __half g_qh [(size_t)MTOT * DA];    // qk fp16
__device__ __half g_uh [(size_t)MTOT * DHID];  // u fp16
__device__ __half g_yh [(size_t)MTOT * DHID];  // y fp16
__device__ float  g_c  [DA];                   // fused bias (fp32)
__device__ __half g_Ah  [DA * DHID];           // fused qk_W1 @ q_W (fp16)
__device__ __half g_Bmh [DA * DHID];           // fused qk_W2 @ k_W (fp16)
__device__ __half g_bkTh[DHID * DA];           // bk_W transposed (fp16)
__device__ __half g_bvh [DA * DHID];           // bv_W (fp16)

// ---------------------------------------------------------------------------
// mma / ldmatrix helpers
// ---------------------------------------------------------------------------
__device__ __forceinline__ void mma_f16(float* c, const uint32_t* a,
                                        uint32_t b0, uint32_t b1)
{
    asm volatile(
        "mma.sync.aligned.m16n8k16.row.col.f32.f16.f16.f32 "
        "{%0,%1,%2,%3}, {%4,%5,%6,%7}, {%8,%9}, {%0,%1,%2,%3};\n"
        : "+f"(c[0]), "+f"(c[1]), "+f"(c[2]), "+f"(c[3])
        : "r"(a[0]), "r"(a[1]), "r"(a[2]), "r"(a[3]), "r"(b0), "r"(b1));
}

__device__ __forceinline__ void ldm_x4(uint32_t* r, uint32_t addr)
{
    asm volatile(
        "ldmatrix.sync.aligned.m8n8.x4.shared.b16 {%0,%1,%2,%3}, [%4];\n"
        : "=r"(r[0]), "=r"(r[1]), "=r"(r[2]), "=r"(r[3]) : "r"(addr));
}

__device__ __forceinline__ void ldm_x4_trans(uint32_t* r, uint32_t addr)
{
    asm volatile(
        "ldmatrix.sync.aligned.m8n8.x4.trans.shared.b16 {%0,%1,%2,%3}, [%4];\n"
        : "=r"(r[0]), "=r"(r[1]), "=r"(r[2]), "=r"(r[3]) : "r"(addr));
}

__device__ __forceinline__ uint32_t smem_u32(const void* p) {
    uint32_t a;
    asm("{ .reg .u64 t; cvta.to.shared.u64 t, %1; cvt.u32.u64 %0, t; }"
        : "=r"(a) : "l"(p));
    return a;
}

#define CP_ASYNC16(dst, src) \
    asm volatile("cp.async.cg.shared.global [%0], [%1], 16;" \
                 :: "r"(dst), "l"(src) : "memory")
#define CP_COMMIT() asm volatile("cp.async.commit_group;" ::: "memory")
#define CP_WAIT2()  asm volatile("cp.async.wait_group 2;" ::: "memory")
#define CP_WAIT1()  asm volatile("cp.async.wait_group 1;" ::: "memory")
#define CP_WAIT0()  asm volatile("cp.async.wait_group 0;" ::: "memory")

// ---------------------------------------------------------------------------
// fp16 GEMM (NT), K-chunk = 64 (best config; pointer arrays kept in regs)
// ---------------------------------------------------------------------------
#define ROWB   144
#define PLANE  (128 * ROWB)           // 18432 B
#define NSTAGE 3
#define SMEM_G (NSTAGE * 2 * PLANE)   // 110592 B -> occ 2

struct GArgs {
    const __half *X1, *W1;
    const __half *X2, *W2;
    int K1, K2;
};

__device__ __forceinline__ void ld_frags(
    uint32_t abase, uint32_t bbase, uint32_t kb, uint32_t* af, uint32_t* bf)
{
    ldm_x4(af + 0, abase + kb);
    ldm_x4(af + 4, abase + kb + 16 * ROWB);
    #pragma unroll
    for (int j = 0; j < 4; ++j) ldm_x4(bf + 4 * j, bbase + kb + j * 16 * ROWB);
}

// Fully compile-time-indexed issue body: all pointers stay in registers.
#define ISSUE8(pX, pW, k) do {                       \
    CP_ASYNC16(sb + dofA[0], (pX)[0] + (k));         \
    CP_ASYNC16(sb + dofA[1], (pX)[1] + (k));         \
    CP_ASYNC16(sb + dofA[2], (pX)[2] + (k));         \
    CP_ASYNC16(sb + dofA[3], (pX)[3] + (k));         \
    CP_ASYNC16(sb + dofB[0], (pW)[0] + (k));         \
    CP_ASYNC16(sb + dofB[1], (pW)[1] + (k));         \
    CP_ASYNC16(sb + dofB[2], (pW)[2] + (k));         \
    CP_ASYNC16(sb + dofB[3], (pW)[3] + (k));         \
    CP_COMMIT();                                     \
} while (0)

__global__ void __launch_bounds__(256, 2) gemm_h_nt(
    GArgs ga,
    const float* __restrict__ bias,
    float* __restrict__ Cf,               // fp32 out (nullable)
    __half* __restrict__ Ch,              // fp16 out (if Cf null)
    int M, int N)
{
    extern __shared__ __align__(16) char smraw[];
    const uint32_t sm0 = smem_u32(smraw);

    const int t    = threadIdx.x;
    const int warp = t >> 5;
    const int lane = t & 31;
    const int bm   = blockIdx.y * 128;
    const int bn   = blockIdx.x * 128;
    const int mw   = (warp & 3) * 32;
    const int nw   = (warp >> 2) * 64;
    const uint32_t laneoff = (lane & 15) * ROWB + (lane >> 4) * 16;
    const uint32_t aBase   = mw * ROWB + laneoff;
    const uint32_t bBase   = PLANE + nw * ROWB + laneoff;

    const int rbase = t >> 3;
    const int grp   = t & 7;
    const __half *pX1[4], *pW1[4], *pX2[4], *pW2[4];
    uint32_t dofA[4], dofB[4];
    #pragma unroll
    for (int o = 0; o < 4; ++o) {
        const int row = rbase + o * 32;
        pX1[o] = ga.X1 + (size_t)(bm + row) * ga.K1 + grp * 8;
        pW1[o] = ga.W1 + (size_t)(bn + row) * ga.K1 + grp * 8;
        dofA[o] = row * ROWB + grp * 16;
        dofB[o] = PLANE + row * ROWB + grp * 16;
    }
    #pragma unroll
    for (int o = 0; o < 4; ++o) { pX2[o] = pX1[o]; pW2[o] = pW1[o]; }
    if (ga.X2) {
        #pragma unroll
        for (int o = 0; o < 4; ++o) {
            const int row = rbase + o * 32;
            pX2[o] = ga.X2 + (size_t)(bm + row) * ga.K2 + grp * 8;
            pW2[o] = ga.W2 + (size_t)(bn + row) * ga.K2 + grp * 8;
        }
    }

    const int nc1 = ga.K1 / 64;
    const int nch = ga.X2 ? nc1 + ga.K2 / 64 : nc1;

    float acc[2][8][4];
    #pragma unroll
    for (int i = 0; i < 2; ++i)
        #pragma unroll
        for (int j = 0; j < 8; ++j)
            #pragma unroll
            for (int e = 0; e < 4; ++e) acc[i][j][e] = 0.f;

    // Prologue: stages 0, 1
    #pragma unroll
    for (int c0 = 0; c0 < 2; ++c0) {
        if (c0 < nch) {
            const uint32_t sb = sm0 + (c0 % NSTAGE) * 2 * PLANE;
            if (c0 < nc1) { const int k = c0 * 64;         ISSUE8(pX1, pW1, k); }
            else          { const int k = (c0 - nc1) * 64; ISSUE8(pX2, pW2, k); }
        }
    }

    uint32_t af[2][8], bf[2][16];

    for (int c = 0; c < nch; ++c) {
        if (c + 2 <= nch) CP_WAIT1(); else CP_WAIT0();
        __syncthreads();

        const uint32_t sbuf = sm0 + (c % NSTAGE) * 2 * PLANE;
        const uint32_t ab = sbuf + aBase;
        const uint32_t bb = sbuf + bBase;

        ld_frags(ab, bb, 0, af[0], bf[0]);
        #pragma unroll
        for (int ks = 0; ks < 4; ++ks) {
            const int cur = ks & 1;
            if (ks < 3)
                ld_frags(ab, bb, (ks + 1) * 32, af[cur ^ 1], bf[cur ^ 1]);
            #pragma unroll
            for (int i = 0; i < 2; ++i) {
                const uint32_t* ah = af[cur] + 4 * i;
                #pragma unroll
                for (int j8 = 0; j8 < 8; ++j8) {
                    uint32_t b0 = bf[cur][4 * (j8 >> 1) + (j8 & 1)];
                    uint32_t b1 = bf[cur][4 * (j8 >> 1) + (j8 & 1) + 2];
                    mma_f16(acc[i][j8], ah, b0, b1);
                }
            }
        }

        if (c + 2 < nch) {
            const int cn = c + 2;
            const uint32_t sb = sm0 + (cn % NSTAGE) * 2 * PLANE;
            if (cn < nc1) { const int k = cn * 64;         ISSUE8(pX1, pW1, k); }
            else          { const int k = (cn - nc1) * 64; ISSUE8(pX2, pW2, k); }
        }
    }

    const int g = lane >> 2;
    const int q = lane & 3;
    #pragma unroll
    for (int i = 0; i < 2; ++i) {
        #pragma unroll
        for (int j8 = 0; j8 < 8; ++j8) {
            const int r0  = bm + mw + 16 * i + g;
            const int col = bn + nw + 8 * j8 + 2 * q;
            const float b0v = bias ? bias[col]     : 0.f;
            const float b1v = bias ? bias[col + 1] : 0.f;
            float v00 = acc[i][j8][0] + b0v, v01 = acc[i][j8][1] + b1v;
            float v10 = acc[i][j8][2] + b0v, v11 = acc[i][j8][3] + b1v;
            if (Cf) {
                *(float2*)&Cf[(size_t)r0 * N + col]       = make_float2(v00, v01);
                *(float2*)&Cf[(size_t)(r0 + 8) * N + col] = make_float2(v10, v11);
            } else {
                *(__half2*)&Ch[(size_t)r0 * N + col]       = __floats2half2_rn(v00, v01);
                *(__half2*)&Ch[(size_t)(r0 + 8) * N + col] = __floats2half2_rn(v10, v11);
            }
        }
    }
}

// ---------------------------------------------------------------------------
// Converters
// ---------------------------------------------------------------------------
__global__ void cvt_pair32to16(__half* __restrict__ h0, const float* __restrict__ s0,
                               __half* __restrict__ h1, const float* __restrict__ s1,
                               int n)
{
    int i = (blockIdx.x * blockDim.x + threadIdx.x) * 4;
    if (i >= n) return;
    float4 a = *(const float4*)&s0[i];
    *(__half2*)&h0[i]     = __floats2half2_rn(a.x, a.y);
    *(__half2*)&h0[i + 2] = __floats2half2_rn(a.z, a.w);
    float4 b = *(const float4*)&s1[i];
    *(__half2*)&h1[i]     = __floats2half2_rn(b.x, b.y);
    *(__half2*)&h1[i + 2] = __floats2half2_rn(b.z, b.w);
}

__global__ void cvt32to16(__half* __restrict__ h, const float* __restrict__ s, int n)
{
    int i = (blockIdx.x * blockDim.x + threadIdx.x) * 4;
    if (i >= n) return;
    float4 v = *(const float4*)&s[i];
    *(__half2*)&h[i]     = __floats2half2_rn(v.x, v.y);
    *(__half2*)&h[i + 2] = __floats2half2_rn(v.z, v.w);
}

// ---------------------------------------------------------------------------
// Transpose (fp32 in -> fp16 out), once for bk_W
// ---------------------------------------------------------------------------
__global__ void transpose_h_kernel(__half* __restrict__ out,
                                   const float* __restrict__ in,
                                   int Rrows, int Ccols)
{
    __shared__ float tile[32][33];
    int x = blockIdx.x * 32 + threadIdx.x;
    int y = blockIdx.y * 32 + threadIdx.y;
    #pragma unroll
    for (int i = 0; i < 4; ++i)
        tile[threadIdx.y + 8 * i][threadIdx.x] = in[(size_t)(y + 8 * i) * Ccols + x];
    __syncthreads();
    x = blockIdx.y * 32 + threadIdx.x;
    y = blockIdx.x * 32 + threadIdx.y;
    #pragma unroll
    for (int i = 0; i < 4; ++i)
        out[(size_t)(y + 8 * i) * Rrows + x] =
            __float2half_rn(tile[threadIdx.x][threadIdx.y + 8 * i]);
}

// ---------------------------------------------------------------------------
// Combined prep: Ah = qk_W[:, :512] @ q_W ; Bmh = qk_W[:, 512:] @ k_W
// ---------------------------------------------------------------------------
#define BM 128
#define BN 128
#define BK 16

__global__ void __launch_bounds__(256, 2) prep_weights_kernel(
    __half* __restrict__ CA, __half* __restrict__ CB,
    const float* __restrict__ qk_W,
    const float* __restrict__ q_W, const float* __restrict__ k_W)
{
    const int half  = blockIdx.y >> 2;
    const int by    = blockIdx.y & 3;
    __half* C       = half ? CB : CA;
    const float* X  = half ? qk_W + DA : qk_W;
    const float* W  = half ? k_W : q_W;
    const int N = DHID, K = DA, ldx = 2 * DA;

    __shared__ float As[BK][BM];
    __shared__ float Bs[BK][BN];
    const int t  = threadIdx.x;
    const int bm = by * BM;
    const int bn = blockIdx.x * BN;

    float acc[8][8];
    #pragma unroll
    for (int i = 0; i < 8; ++i)
        #pragma unroll
        for (int j = 0; j < 8; ++j) acc[i][j] = 0.f;

    const int lrow = t >> 2;
    const int lc4  = (t & 3) * 4;
    const int wk   = t >> 5;
    const int wn4  = (t & 31) * 4;

    for (int k0 = 0; k0 < K; k0 += BK) {
        #pragma unroll
        for (int h = 0; h < 2; ++h) {
            int row = lrow + h * 64;
            float4 v = *(const float4*)&X[(size_t)(bm + row) * ldx + k0 + lc4];
            As[lc4 + 0][row] = v.x;
            As[lc4 + 1][row] = v.y;
            As[lc4 + 2][row] = v.z;
            As[lc4 + 3][row] = v.w;
            int k = wk + h * 8;
            float4 w = *(const float4*)&W[(size_t)(k0 + k) * N + bn + wn4];
            *(float4*)&Bs[k][wn4] = w;
        }
        __syncthreads();
        const int m8 = (t >> 4) * 8;
        const int n8 = (t & 15) * 8;
        #pragma unroll
        for (int kk = 0; kk < BK; ++kk) {
            float a[8], b[8];
            *(float4*)&a[0] = *(const float4*)&As[kk][m8];
            *(float4*)&a[4] = *(const float4*)&As[kk][m8 + 4];
            *(float4*)&b[0] = *(const float4*)&Bs[kk][n8];
            *(float4*)&b[4] = *(const float4*)&Bs[kk][n8 + 4];
            #pragma unroll
            for (int i = 0; i < 8; ++i)
                #pragma unroll
                for (int j = 0; j < 8; ++j)
                    acc[i][j] += a[i] * b[j];
        }
        __syncthreads();
    }

    const int m0 = bm + (t >> 4) * 8;
    const int n0 = bn + (t & 15) * 8;
    #pragma unroll
    for (int i = 0; i < 8; ++i) {
        __half2 h0 = __floats2half2_rn(acc[i][0], acc[i][1]);
        __half2 h1 = __floats2half2_rn(acc[i][2], acc[i][3]);
        __half2 h2 = __floats2half2_rn(acc[i][4], acc[i][5]);
        __half2 h3 = __floats2half2_rn(acc[i][6], acc[i][7]);
        __half* dst = &C[(size_t)(m0 + i) * N + n0];
        *(__half2*)(dst + 0) = h0;
        *(__half2*)(dst + 2) = h1;
        *(__half2*)(dst + 4) = h2;
        *(__half2*)(dst + 6) = h3;
    }
}

// ---------------------------------------------------------------------------
// Fused bias
// ---------------------------------------------------------------------------
__global__ void fuse_bias_kernel(float* __restrict__ c,
                                 const float* __restrict__ qk_W,
                                 const float* __restrict__ q_b,
                                 const float* __restrict__ k_b,
                                 const float* __restrict__ qk_b)
{
    int i = blockIdx.x * blockDim.x + threadIdx.x;
    if (i >= DA) return;
    float s = qk_b[i];
    const float* row = qk_W + (size_t)i * (2 * DA);
    for (int j = 0; j < DA; ++j)
        s += row[j] * q_b[j] + row[DA + j] * k_b[j];
    c[i] = s;
}

// ---------------------------------------------------------------------------
// Attention v3 (tensor-core + cp.async basis pipeline): one block per l.
// basis staged via 16 chunks of 4 rows through a 3-buffer fp32 scratch
// (cp.async, fully pipelined), converted to a resident fp16 tile.
// scores/y via mma as in v2.
// smem layout (bytes):
//   OFF_B  = 0       : basis fp16, 64 x 2064            = 132096
//   OFF_U  = 132096  : u fp16, 16 x 2064                =  33024
//   OFF_SC = 165120  : fp32 scratch, 3 x (4 x 4128)     =  49536
//   OFF_W  = 214656  : softmax weights fp16, 16 x 72    =   2304
//   OFF_S  = 216960  : scores fp32, 16 x 65             =   4160
//   total 221120
// ---------------------------------------------------------------------------
#define U_ST   2064
#define OFF_B  0
#define OFF_U  132096
#define OFF_SC 165120
#define SC_ST  4128
#define SC_BUF (4 * SC_ST)             // 16512
#define OFF_W  (OFF_SC + 3 * SC_BUF)   // 214656
#define OFF_S  (OFF_W + 2304)          // 216960
#define ATT3_SMEM (OFF_S + BB * 65 * 4)  // 221120
#define SS_LD 65

__global__ void __launch_bounds__(256) attention_kernel(
    const __half* __restrict__ u,     // (B*L, 1024) fp16
    const float* __restrict__ basis,  // (L, R, 1024) fp32
    __half* __restrict__ yh)
{
    extern __shared__ __align__(16) char smraw2[];
    const uint32_t sm0 = smem_u32(smraw2);
    float*  s_s = (float*)(smraw2 + OFF_S);
    __half* w_h = (__half*)(smraw2 + OFF_W);

    const int l    = blockIdx.x;
    const int t    = threadIdx.x;
    const int warp = t >> 5;
    const int lane = t & 31;
    const int g    = lane >> 2;
    const int q    = lane & 3;
    const float scale = 0.044194173824159216f;  // 1/sqrt(512)

    // --- u staging (cp.async, one group) ---
    #pragma unroll
    for (int it = 0; it < 8; ++it) {
        int idx = t + it * 256;
        int b   = idx >> 7;
        int d8  = (idx & 127) * 8;
        CP_ASYNC16(sm0 + OFF_U + b * U_ST + d8 * 2,
                   &u[((size_t)b * LL + l) * DHID + d8]);
    }
    CP_COMMIT();

    // --- basis staging: cp.async fp32 -> scratch, convert -> fp16 tile ---
    const float* basl = basis + (size_t)l * RR * DHID;
    const int rl4 = t >> 8;                // always 0; kept for clarity
    (void)rl4;

    // issue chunk c (rows 4c..4c+3) into scratch buffer c%3
    auto issue_b = [&](int c) {
        const uint32_t dst0 = sm0 + OFF_SC + (c % 3) * SC_BUF;
        const float* src0 = basl + (size_t)(c * 4) * DHID;
        #pragma unroll
        for (int j = 0; j < 4; ++j) {
            int idx = t + j * 256;          // 0..1023
            int rl  = idx >> 8;             // 0..3
            int d4  = idx & 255;            // 0..255 (16B groups)
            CP_ASYNC16(dst0 + rl * SC_ST + d4 * 16, src0 + rl * DHID + d4 * 4);
        }
        CP_COMMIT();
    };

    issue_b(0);
    issue_b(1);

    for (int c = 0; c < 16; ++c) {
        // wait for chunk c's group (chunk c+1 may stay in flight)
        if (c < 15) CP_WAIT1(); else CP_WAIT0();
        __syncthreads();                    // data visibility + scratch reuse

        if (c + 2 < 16) issue_b(c + 2);     // buffer (c+2)%3: readers done

        const char* sc = smraw2 + OFF_SC + (c % 3) * SC_BUF;
        #pragma unroll
        for (int j = 0; j < 2; ++j) {
            int gi = t + j * 256;           // 0..511
            int rl = gi >> 7;               // 0..3
            int d8 = (gi & 127) * 8;        // float index
            const float4* s4 = (const float4*)(sc + rl * SC_ST + d8 * 4);
            float4 v0 = s4[0];
            float4 v1 = s4[1];
            __half2 h0 = __floats2half2_rn(v0.x, v0.y);
            __half2 h1 = __floats2half2_rn(v0.z, v0.w);
            __half2 h2 = __floats2half2_rn(v1.x, v1.y);
            __half2 h3 = __floats2half2_rn(v1.z, v1.w);
            __half2* d = (__half2*)(smraw2 + OFF_B + (c * 4 + rl) * U_ST + d8 * 2);
            d[0] = h0; d[1] = h1; d[2] = h2; d[3] = h3;
        }
    }
    __syncthreads();   // basis tile + u complete (WAIT0 at c=15 drained all)

    // --- Phase 1: scores via mma. warp owns r-rows [warp*8, warp*8+8) ---
    {
        float acc4[4] = {0.f, 0.f, 0.f, 0.f};
        const uint32_t aAddr = sm0 + OFF_U + (lane & 15) * U_ST + (lane >> 4) * 16;
        const uint32_t bAddr = sm0 + OFF_B + (warp * 8 + (lane & 7)) * U_ST
                                          + (lane >> 3) * 16;
        #pragma unroll 4
        for (int kt2 = 0; kt2 < 32; ++kt2) {
            const uint32_t kb = kt2 * 64;
            uint32_t a0[4], a1[4], b4[4];
            ldm_x4(a0, aAddr + kb);
            ldm_x4(a1, aAddr + kb + 32);
            ldm_x4(b4, bAddr + kb);
            mma_f16(acc4, a0, b4[0], b4[1]);
            mma_f16(acc4, a1, b4[2], b4[3]);
        }
        const int r0 = warp * 8 + 2 * q;
        s_s[g * SS_LD + r0]           = acc4[0] * scale;
        s_s[g * SS_LD + r0 + 1]       = acc4[1] * scale;
        s_s[(g + 8) * SS_LD + r0]     = acc4[2] * scale;
        s_s[(g + 8) * SS_LD + r0 + 1] = acc4[3] * scale;
    }
    __syncthreads();

    // --- Phase 2: softmax over r; warp w handles b = 2w, 2w+1 ---
    {
        int b0 = warp * 2;
        #pragma unroll
        for (int bi = 0; bi < 2; ++bi) {
            int b = b0 + bi;
            float v0 = s_s[b * SS_LD + lane];
            float v1 = s_s[b * SS_LD + lane + 32];
            float mx = fmaxf(v0, v1);
            #pragma unroll
            for (int o = 16; o; o >>= 1) mx = fmaxf(mx, __shfl_xor_sync(0xffffffffu, mx, o));
            float e0 = __expf(v0 - mx);
            float e1 = __expf(v1 - mx);
            float sum = e0 + e1;
            #pragma unroll
            for (int o = 16; o; o >>= 1) sum += __shfl_xor_sync(0xffffffffu, sum, o);
            float inv = 1.f / sum;
            w_h[b * 72 + lane]      = __float2half_rn(e0 * inv);
            w_h[b * 72 + lane + 32] = __float2half_rn(e1 * inv);
        }
    }
    __syncthreads();

    // --- Phase 3: y = W @ basis via mma (.trans B). warp owns d-span 128 ---
    {
        uint32_t afr[4][4];
        const uint32_t wAddr = sm0 + OFF_W + (lane & 15) * 144 + (lane >> 4) * 16;
        #pragma unroll
        for (int kt = 0; kt < 4; ++kt) ldm_x4(afr[kt], wAddr + kt * 32);

        const int d0w = warp * 128;
        const uint32_t bTA = sm0 + OFF_B + (lane & 15) * U_ST + (lane >> 4) * 16;
        #pragma unroll
        for (int jp = 0; jp < 8; ++jp) {
            const int d0 = d0w + jp * 16;
            float acc2[2][4];
            #pragma unroll
            for (int e = 0; e < 4; ++e) { acc2[0][e] = 0.f; acc2[1][e] = 0.f; }
            #pragma unroll
            for (int kt = 0; kt < 4; ++kt) {
                uint32_t bt[4];
                ldm_x4_trans(bt, bTA + kt * 16 * U_ST + d0 * 2);
                mma_f16(acc2[0], afr[kt], bt[0], bt[1]);
                mma_f16(acc2[1], afr[kt], bt[2], bt[3]);
            }
            #pragma unroll
            for (int jj = 0; jj < 2; ++jj) {
                const int col = d0 + 8 * jj + 2 * q;
                *(__half2*)&yh[((size_t)g * LL + l) * DHID + col] =
                    __floats2half2_rn(acc2[jj][0], acc2[jj][1]);
                *(__half2*)&yh[((size_t)(g + 8) * LL + l) * DHID + col] =
                    __floats2half2_rn(acc2[jj][2], acc2[jj][3]);
            }
        }
    }
}

// ---------------------------------------------------------------------------
// Launch
// ---------------------------------------------------------------------------
extern "C" void kernel_launch(void* const* d_in, const int* in_sizes, int n_in,
                              void* d_out, int out_size)
{
    const float* s_emb  = (const float*)d_in[0];
    const float* t_emb  = (const float*)d_in[1];
    const float* basis  = (const float*)d_in[2];
    const float* q_W    = (const float*)d_in[3];
    const float* q_b    = (const float*)d_in[4];
    const float* k_W    = (const float*)d_in[5];
    const float* k_b    = (const float*)d_in[6];
    const float* qk_W   = (const float*)d_in[7];
    const float* qk_b   = (const float*)d_in[8];
    const float* bk_W   = (const float*)d_in[9];
    // d_in[10] = bk_b : provably unused (softmax shift invariance)
    const float* bv_W   = (const float*)d_in[11];
    const float* bv_b   = (const float*)d_in[12];
    float* out = (float*)d_out;

    float  *p_c;
    __half *p_sh, *p_th, *p_qh, *p_uh, *p_yh;
    __half *p_Ah, *p_Bmh, *p_bkTh, *p_bvh;
    cudaGetSymbolAddress((void**)&p_c,    g_c);
    cudaGetSymbolAddress((void**)&p_sh,   g_sh);
    cudaGetSymbolAddress((void**)&p_th,   g_th);
    cudaGetSymbolAddress((void**)&p_qh,   g_qh);
    cudaGetSymbolAddress((void**)&p_uh,   g_uh);
    cudaGetSymbolAddress((void**)&p_yh,   g_yh);
    cudaGetSymbolAddress((void**)&p_Ah,   g_Ah);
    cudaGetSymbolAddress((void**)&p_Bmh,  g_Bmh);
    cudaGetSymbolAddress((void**)&p_bkTh, g_bkTh);
    cudaGetSymbolAddress((void**)&p_bvh,  g_bvh);

    cudaFuncSetAttribute(attention_kernel,
                         cudaFuncAttributeMaxDynamicSharedMemorySize, ATT3_SMEM);
    cudaFuncSetAttribute(gemm_h_nt,
                         cudaFuncAttributeMaxDynamicSharedMemorySize, SMEM_G);

    // launch 0: s,t -> fp16
    const int ne = MTOT * DHID;
    cvt_pair32to16<<<ne / 4 / 256, 256>>>(p_sh, s_emb, p_th, t_emb, ne);

    // launch 1: fused projection matrices Ah, Bmh
    {
        dim3 grid(DHID / BN, 8);
        prep_weights_kernel<<<grid, 256>>>(p_Ah, p_Bmh, qk_W, q_W, k_W);
    }

    // launch 2: fused bias
    fuse_bias_kernel<<<1, DA>>>(p_c, qk_W, q_b, k_b, qk_b);

    // launch 3 (ncu capture slot): qk = s@A^T + t@Bm^T + c -> fp16
    {
        GArgs ga = { p_sh, p_Ah, p_th, p_Bmh, DHID, DHID };
        dim3 grid(DA / 128, MTOT / 128);
        gemm_h_nt<<<grid, 256, SMEM_G>>>(ga, p_c, nullptr, p_qh, MTOT, DA);
    }

    // launch 4: bk_W transpose -> fp16
    {
        dim3 tg(DHID / 32, DA / 32);
        transpose_h_kernel<<<tg, dim3(32, 8)>>>(p_bkTh, bk_W, DA, DHID);
    }

    // launch 5: bv_W -> fp16
    cvt32to16<<<(DA * DHID) / 4 / 256, 256>>>(p_bvh, bv_W, DA * DHID);

    // launch 6: u = qk @ bkT^T -> fp16
    {
        GArgs ga = { p_qh, p_bkTh, nullptr, nullptr, DA, 0 };
        dim3 grid(DHID / 128, MTOT / 128);
        gemm_h_nt<<<grid, 256, SMEM_G>>>(ga, nullptr, nullptr, p_uh, MTOT, DHID);
    }

    // launch 7: attention v3 (cp.async basis pipeline + tensor cores)
    attention_kernel<<<LL, 256, ATT3_SMEM>>>(p_uh, basis, p_yh);

    // launch 8: z = y @ bv_W^T + bv_b -> fp32 out
    {
        GArgs ga = { p_yh, p_bvh, nullptr, nullptr, DHID, 0 };
        dim3 grid(DA / 128, MTOT / 128);
        gemm_h_nt<<<grid, 256, SMEM_G>>>(ga, bv_b, out, nullptr, MTOT, DA);
    }
}

// round 14
// speedup vs baseline: 2.2156x; 1.3550x over previous
#include <cuda_runtime.h>
#include <cuda_fp16.h>
#include <math.h>
#include <stdint.h>

// Problem constants
#define DHID 1024
#define DA   512
#define BB   16
#define LL   2048
#define RR   64
#define MTOT (BB*LL)   // 32768

// ---------------------------------------------------------------------------
// Scratch (static device globals; no allocations allowed)
// ---------------------------------------------------------------------------
__device__ __half g_sh [(size_t)MTOT * DHID];  // student fp16
__device__ __half g_th [(size_t)MTOT * DHID];  // teacher fp16
__device__ __half g_qh [(size_t)MTOT * DA];    // qk fp16
__device__ __half g_uh [(size_t)MTOT * DHID];  // u fp16
__device__ __half g_yh [(size_t)MTOT * DHID];  // y fp16
__device__ float  g_c  [DA];                   // fused bias (fp32)
__device__ __half g_Ah  [DA * DHID];           // fused qk_W1 @ q_W (fp16)
__device__ __half g_Bmh [DA * DHID];           // fused qk_W2 @ k_W (fp16)
__device__ __half g_bkTh[DHID * DA];           // bk_W transposed (fp16)
__device__ __half g_bvh [DA * DHID];           // bv_W (fp16)

// ---------------------------------------------------------------------------
// mma / ldmatrix helpers
// ---------------------------------------------------------------------------
__device__ __forceinline__ void mma_f16(float* c, const uint32_t* a,
                                        uint32_t b0, uint32_t b1)
{
    asm volatile(
        "mma.sync.aligned.m16n8k16.row.col.f32.f16.f16.f32 "
        "{%0,%1,%2,%3}, {%4,%5,%6,%7}, {%8,%9}, {%0,%1,%2,%3};\n"
        : "+f"(c[0]), "+f"(c[1]), "+f"(c[2]), "+f"(c[3])
        : "r"(a[0]), "r"(a[1]), "r"(a[2]), "r"(a[3]), "r"(b0), "r"(b1));
}

__device__ __forceinline__ void ldm_x4(uint32_t* r, uint32_t addr)
{
    asm volatile(
        "ldmatrix.sync.aligned.m8n8.x4.shared.b16 {%0,%1,%2,%3}, [%4];\n"
        : "=r"(r[0]), "=r"(r[1]), "=r"(r[2]), "=r"(r[3]) : "r"(addr));
}

__device__ __forceinline__ void ldm_x4_trans(uint32_t* r, uint32_t addr)
{
    asm volatile(
        "ldmatrix.sync.aligned.m8n8.x4.trans.shared.b16 {%0,%1,%2,%3}, [%4];\n"
        : "=r"(r[0]), "=r"(r[1]), "=r"(r[2]), "=r"(r[3]) : "r"(addr));
}

__device__ __forceinline__ uint32_t smem_u32(const void* p) {
    uint32_t a;
    asm("{ .reg .u64 t; cvta.to.shared.u64 t, %1; cvt.u32.u64 %0, t; }"
        : "=r"(a) : "l"(p));
    return a;
}

#define CP_ASYNC16(dst, src) \
    asm volatile("cp.async.cg.shared.global [%0], [%1], 16;" \
                 :: "r"(dst), "l"(src) : "memory")
#define CP_COMMIT() asm volatile("cp.async.commit_group;" ::: "memory")
#define CP_WAIT1()  asm volatile("cp.async.wait_group 1;" ::: "memory")
#define CP_WAIT0()  asm volatile("cp.async.wait_group 0;" ::: "memory")

// ---------------------------------------------------------------------------
// fp16 GEMM (NT), K-chunk = 64 (validated best config — unchanged)
// ---------------------------------------------------------------------------
#define ROWB   144
#define PLANE  (128 * ROWB)           // 18432 B
#define NSTAGE 3
#define SMEM_G (NSTAGE * 2 * PLANE)   // 110592 B -> occ 2

struct GArgs {
    const __half *X1, *W1;
    const __half *X2, *W2;
    int K1, K2;
};

__device__ __forceinline__ void ld_frags(
    uint32_t abase, uint32_t bbase, uint32_t kb, uint32_t* af, uint32_t* bf)
{
    ldm_x4(af + 0, abase + kb);
    ldm_x4(af + 4, abase + kb + 16 * ROWB);
    #pragma unroll
    for (int j = 0; j < 4; ++j) ldm_x4(bf + 4 * j, bbase + kb + j * 16 * ROWB);
}

#define ISSUE8(pX, pW, k) do {                       \
    CP_ASYNC16(sb + dofA[0], (pX)[0] + (k));         \
    CP_ASYNC16(sb + dofA[1], (pX)[1] + (k));         \
    CP_ASYNC16(sb + dofA[2], (pX)[2] + (k));         \
    CP_ASYNC16(sb + dofA[3], (pX)[3] + (k));         \
    CP_ASYNC16(sb + dofB[0], (pW)[0] + (k));         \
    CP_ASYNC16(sb + dofB[1], (pW)[1] + (k));         \
    CP_ASYNC16(sb + dofB[2], (pW)[2] + (k));         \
    CP_ASYNC16(sb + dofB[3], (pW)[3] + (k));         \
    CP_COMMIT();                                     \
} while (0)

__global__ void __launch_bounds__(256, 2) gemm_h_nt(
    GArgs ga,
    const float* __restrict__ bias,
    float* __restrict__ Cf,               // fp32 out (nullable)
    __half* __restrict__ Ch,              // fp16 out (if Cf null)
    int M, int N)
{
    extern __shared__ __align__(16) char smraw[];
    const uint32_t sm0 = smem_u32(smraw);

    const int t    = threadIdx.x;
    const int warp = t >> 5;
    const int lane = t & 31;
    const int bm   = blockIdx.y * 128;
    const int bn   = blockIdx.x * 128;
    const int mw   = (warp & 3) * 32;
    const int nw   = (warp >> 2) * 64;
    const uint32_t laneoff = (lane & 15) * ROWB + (lane >> 4) * 16;
    const uint32_t aBase   = mw * ROWB + laneoff;
    const uint32_t bBase   = PLANE + nw * ROWB + laneoff;

    const int rbase = t >> 3;
    const int grp   = t & 7;
    const __half *pX1[4], *pW1[4], *pX2[4], *pW2[4];
    uint32_t dofA[4], dofB[4];
    #pragma unroll
    for (int o = 0; o < 4; ++o) {
        const int row = rbase + o * 32;
        pX1[o] = ga.X1 + (size_t)(bm + row) * ga.K1 + grp * 8;
        pW1[o] = ga.W1 + (size_t)(bn + row) * ga.K1 + grp * 8;
        dofA[o] = row * ROWB + grp * 16;
        dofB[o] = PLANE + row * ROWB + grp * 16;
    }
    #pragma unroll
    for (int o = 0; o < 4; ++o) { pX2[o] = pX1[o]; pW2[o] = pW1[o]; }
    if (ga.X2) {
        #pragma unroll
        for (int o = 0; o < 4; ++o) {
            const int row = rbase + o * 32;
            pX2[o] = ga.X2 + (size_t)(bm + row) * ga.K2 + grp * 8;
            pW2[o] = ga.W2 + (size_t)(bn + row) * ga.K2 + grp * 8;
        }
    }

    const int nc1 = ga.K1 / 64;
    const int nch = ga.X2 ? nc1 + ga.K2 / 64 : nc1;

    float acc[2][8][4];
    #pragma unroll
    for (int i = 0; i < 2; ++i)
        #pragma unroll
        for (int j = 0; j < 8; ++j)
            #pragma unroll
            for (int e = 0; e < 4; ++e) acc[i][j][e] = 0.f;

    #pragma unroll
    for (int c0 = 0; c0 < 2; ++c0) {
        if (c0 < nch) {
            const uint32_t sb = sm0 + (c0 % NSTAGE) * 2 * PLANE;
            if (c0 < nc1) { const int k = c0 * 64;         ISSUE8(pX1, pW1, k); }
            else          { const int k = (c0 - nc1) * 64; ISSUE8(pX2, pW2, k); }
        }
    }

    uint32_t af[2][8], bf[2][16];

    for (int c = 0; c < nch; ++c) {
        if (c + 2 <= nch) CP_WAIT1(); else CP_WAIT0();
        __syncthreads();

        const uint32_t sbuf = sm0 + (c % NSTAGE) * 2 * PLANE;
        const uint32_t ab = sbuf + aBase;
        const uint32_t bb = sbuf + bBase;

        ld_frags(ab, bb, 0, af[0], bf[0]);
        #pragma unroll
        for (int ks = 0; ks < 4; ++ks) {
            const int cur = ks & 1;
            if (ks < 3)
                ld_frags(ab, bb, (ks + 1) * 32, af[cur ^ 1], bf[cur ^ 1]);
            #pragma unroll
            for (int i = 0; i < 2; ++i) {
                const uint32_t* ah = af[cur] + 4 * i;
                #pragma unroll
                for (int j8 = 0; j8 < 8; ++j8) {
                    uint32_t b0 = bf[cur][4 * (j8 >> 1) + (j8 & 1)];
                    uint32_t b1 = bf[cur][4 * (j8 >> 1) + (j8 & 1) + 2];
                    mma_f16(acc[i][j8], ah, b0, b1);
                }
            }
        }

        if (c + 2 < nch) {
            const int cn = c + 2;
            const uint32_t sb = sm0 + (cn % NSTAGE) * 2 * PLANE;
            if (cn < nc1) { const int k = cn * 64;         ISSUE8(pX1, pW1, k); }
            else          { const int k = (cn - nc1) * 64; ISSUE8(pX2, pW2, k); }
        }
    }

    const int g = lane >> 2;
    const int q = lane & 3;
    #pragma unroll
    for (int i = 0; i < 2; ++i) {
        #pragma unroll
        for (int j8 = 0; j8 < 8; ++j8) {
            const int r0  = bm + mw + 16 * i + g;
            const int col = bn + nw + 8 * j8 + 2 * q;
            const float b0v = bias ? bias[col]     : 0.f;
            const float b1v = bias ? bias[col + 1] : 0.f;
            float v00 = acc[i][j8][0] + b0v, v01 = acc[i][j8][1] + b1v;
            float v10 = acc[i][j8][2] + b0v, v11 = acc[i][j8][3] + b1v;
            if (Cf) {
                *(float2*)&Cf[(size_t)r0 * N + col]       = make_float2(v00, v01);
                *(float2*)&Cf[(size_t)(r0 + 8) * N + col] = make_float2(v10, v11);
            } else {
                *(__half2*)&Ch[(size_t)r0 * N + col]       = __floats2half2_rn(v00, v01);
                *(__half2*)&Ch[(size_t)(r0 + 8) * N + col] = __floats2half2_rn(v10, v11);
            }
        }
    }
}

// ---------------------------------------------------------------------------
// Converters (8 elems/thread, single 16B store per array)
// ---------------------------------------------------------------------------
__global__ void cvt_pair32to16(__half* __restrict__ h0, const float* __restrict__ s0,
                               __half* __restrict__ h1, const float* __restrict__ s1,
                               int n)
{
    int i = (blockIdx.x * blockDim.x + threadIdx.x) * 8;
    if (i >= n) return;
    {
        float4 a0 = *(const float4*)&s0[i];
        float4 a1 = *(const float4*)&s0[i + 4];
        uint4 o;
        ((__half2*)&o)[0] = __floats2half2_rn(a0.x, a0.y);
        ((__half2*)&o)[1] = __floats2half2_rn(a0.z, a0.w);
        ((__half2*)&o)[2] = __floats2half2_rn(a1.x, a1.y);
        ((__half2*)&o)[3] = __floats2half2_rn(a1.z, a1.w);
        *(uint4*)&h0[i] = o;
    }
    {
        float4 b0 = *(const float4*)&s1[i];
        float4 b1 = *(const float4*)&s1[i + 4];
        uint4 o;
        ((__half2*)&o)[0] = __floats2half2_rn(b0.x, b0.y);
        ((__half2*)&o)[1] = __floats2half2_rn(b0.z, b0.w);
        ((__half2*)&o)[2] = __floats2half2_rn(b1.x, b1.y);
        ((__half2*)&o)[3] = __floats2half2_rn(b1.z, b1.w);
        *(uint4*)&h1[i] = o;
    }
}

__global__ void cvt32to16(__half* __restrict__ h, const float* __restrict__ s, int n)
{
    int i = (blockIdx.x * blockDim.x + threadIdx.x) * 8;
    if (i >= n) return;
    float4 a0 = *(const float4*)&s[i];
    float4 a1 = *(const float4*)&s[i + 4];
    uint4 o;
    ((__half2*)&o)[0] = __floats2half2_rn(a0.x, a0.y);
    ((__half2*)&o)[1] = __floats2half2_rn(a0.z, a0.w);
    ((__half2*)&o)[2] = __floats2half2_rn(a1.x, a1.y);
    ((__half2*)&o)[3] = __floats2half2_rn(a1.z, a1.w);
    *(uint4*)&h[i] = o;
}

// ---------------------------------------------------------------------------
// Transpose (fp32 in -> fp16 out), once for bk_W
// ---------------------------------------------------------------------------
__global__ void transpose_h_kernel(__half* __restrict__ out,
                                   const float* __restrict__ in,
                                   int Rrows, int Ccols)
{
    __shared__ float tile[32][33];
    int x = blockIdx.x * 32 + threadIdx.x;
    int y = blockIdx.y * 32 + threadIdx.y;
    #pragma unroll
    for (int i = 0; i < 4; ++i)
        tile[threadIdx.y + 8 * i][threadIdx.x] = in[(size_t)(y + 8 * i) * Ccols + x];
    __syncthreads();
    x = blockIdx.y * 32 + threadIdx.x;
    y = blockIdx.x * 32 + threadIdx.y;
    #pragma unroll
    for (int i = 0; i < 4; ++i)
        out[(size_t)(y + 8 * i) * Rrows + x] =
            __float2half_rn(tile[threadIdx.x][threadIdx.y + 8 * i]);
}

// ---------------------------------------------------------------------------
// Combined prep: Ah = qk_W[:, :512] @ q_W ; Bmh = qk_W[:, 512:] @ k_W
// ---------------------------------------------------------------------------
#define BM 128
#define BN 128
#define BK 16

__global__ void __launch_bounds__(256, 2) prep_weights_kernel(
    __half* __restrict__ CA, __half* __restrict__ CB,
    const float* __restrict__ qk_W,
    const float* __restrict__ q_W, const float* __restrict__ k_W)
{
    const int half  = blockIdx.y >> 2;
    const int by    = blockIdx.y & 3;
    __half* C       = half ? CB : CA;
    const float* X  = half ? qk_W + DA : qk_W;
    const float* W  = half ? k_W : q_W;
    const int N = DHID, K = DA, ldx = 2 * DA;

    __shared__ float As[BK][BM];
    __shared__ float Bs[BK][BN];
    const int t  = threadIdx.x;
    const int bm = by * BM;
    const int bn = blockIdx.x * BN;

    float acc[8][8];
    #pragma unroll
    for (int i = 0; i < 8; ++i)
        #pragma unroll
        for (int j = 0; j < 8; ++j) acc[i][j] = 0.f;

    const int lrow = t >> 2;
    const int lc4  = (t & 3) * 4;
    const int wk   = t >> 5;
    const int wn4  = (t & 31) * 4;

    for (int k0 = 0; k0 < K; k0 += BK) {
        #pragma unroll
        for (int h = 0; h < 2; ++h) {
            int row = lrow + h * 64;
            float4 v = *(const float4*)&X[(size_t)(bm + row) * ldx + k0 + lc4];
            As[lc4 + 0][row] = v.x;
            As[lc4 + 1][row] = v.y;
            As[lc4 + 2][row] = v.z;
            As[lc4 + 3][row] = v.w;
            int k = wk + h * 8;
            float4 w = *(const float4*)&W[(size_t)(k0 + k) * N + bn + wn4];
            *(float4*)&Bs[k][wn4] = w;
        }
        __syncthreads();
        const int m8 = (t >> 4) * 8;
        const int n8 = (t & 15) * 8;
        #pragma unroll
        for (int kk = 0; kk < BK; ++kk) {
            float a[8], b[8];
            *(float4*)&a[0] = *(const float4*)&As[kk][m8];
            *(float4*)&a[4] = *(const float4*)&As[kk][m8 + 4];
            *(float4*)&b[0] = *(const float4*)&Bs[kk][n8];
            *(float4*)&b[4] = *(const float4*)&Bs[kk][n8 + 4];
            #pragma unroll
            for (int i = 0; i < 8; ++i)
                #pragma unroll
                for (int j = 0; j < 8; ++j)
                    acc[i][j] += a[i] * b[j];
        }
        __syncthreads();
    }

    const int m0 = bm + (t >> 4) * 8;
    const int n0 = bn + (t & 15) * 8;
    #pragma unroll
    for (int i = 0; i < 8; ++i) {
        __half2 h0 = __floats2half2_rn(acc[i][0], acc[i][1]);
        __half2 h1 = __floats2half2_rn(acc[i][2], acc[i][3]);
        __half2 h2 = __floats2half2_rn(acc[i][4], acc[i][5]);
        __half2 h3 = __floats2half2_rn(acc[i][6], acc[i][7]);
        __half* dst = &C[(size_t)(m0 + i) * N + n0];
        *(__half2*)(dst + 0) = h0;
        *(__half2*)(dst + 2) = h1;
        *(__half2*)(dst + 4) = h2;
        *(__half2*)(dst + 6) = h3;
    }
}

// ---------------------------------------------------------------------------
// Fused bias (parallel): one block per output i; 256-thread reduction.
// c[i] = sum_j qk_W[i,j]*q_b[j] + qk_W[i,512+j]*k_b[j] + qk_b[i]
// ---------------------------------------------------------------------------
__global__ void fuse_bias_kernel(float* __restrict__ c,
                                 const float* __restrict__ qk_W,
                                 const float* __restrict__ q_b,
                                 const float* __restrict__ k_b,
                                 const float* __restrict__ qk_b)
{
    __shared__ float red[8];
    const int i = blockIdx.x;
    const int t = threadIdx.x;
    const float* row = qk_W + (size_t)i * (2 * DA);
    float s = 0.f;
    for (int j = t; j < DA; j += 256)
        s += row[j] * q_b[j] + row[DA + j] * k_b[j];
    #pragma unroll
    for (int o = 16; o; o >>= 1) s += __shfl_xor_sync(0xffffffffu, s, o);
    if ((t & 31) == 0) red[t >> 5] = s;
    __syncthreads();
    if (t == 0) {
        float tot = qk_b[i];
        #pragma unroll
        for (int k = 0; k < 8; ++k) tot += red[k];
        c[i] = tot;
    }
}

// ---------------------------------------------------------------------------
// Attention v4: 512 threads (16 warps), tensor-core phases, cp.async staging.
// Phase 1 splits K across warp pairs (wk = warp>>3, wr = warp&7); partial
// scores reduced in smem. Phase 3: warp owns d-span 64.
// smem layout (bytes):
//   OFF_B  = 0       : basis fp16, 64 x 2064            = 132096
//   OFF_U  = 132096  : u fp16, 16 x 2064                =  33024
//   OFF_SC = 165120  : fp32 scratch, 3 x (4 x 4128)     =  49536
//   OFF_W  = 214656  : softmax weights fp16, 16 x 72    =   2304
//   OFF_S  = 216960  : scores fp32, 2 x 16 x 65         =   8320
//   total 225280
// ---------------------------------------------------------------------------
#define U_ST   2064
#define OFF_B  0
#define OFF_U  132096
#define OFF_SC 165120
#define SC_ST  4128
#define SC_BUF (4 * SC_ST)             // 16512
#define OFF_W  (OFF_SC + 3 * SC_BUF)   // 214656
#define OFF_S  (OFF_W + 2304)          // 216960
#define SS_LD  65
#define ATT4_SMEM (OFF_S + 2 * BB * SS_LD * 4)  // 225280

__global__ void __launch_bounds__(512) attention_kernel(
    const __half* __restrict__ u,     // (B*L, 1024) fp16
    const float* __restrict__ basis,  // (L, R, 1024) fp32
    __half* __restrict__ yh)
{
    extern __shared__ __align__(16) char smraw2[];
    const uint32_t sm0 = smem_u32(smraw2);
    float*  s_s = (float*)(smraw2 + OFF_S);
    __half* w_h = (__half*)(smraw2 + OFF_W);

    const int l    = blockIdx.x;
    const int t    = threadIdx.x;
    const int warp = t >> 5;          // 0..15
    const int lane = t & 31;
    const int g    = lane >> 2;
    const int q    = lane & 3;
    const float scale = 0.044194173824159216f;  // 1/sqrt(512)

    // --- u staging (cp.async) ---
    #pragma unroll
    for (int it = 0; it < 4; ++it) {
        int idx = t + it * 512;       // 0..2047
        int b   = idx >> 7;
        int d8  = (idx & 127) * 8;
        CP_ASYNC16(sm0 + OFF_U + b * U_ST + d8 * 2,
                   &u[((size_t)b * LL + l) * DHID + d8]);
    }
    CP_COMMIT();

    // --- basis staging pipeline (16 chunks of 4 rows, 3 scratch buffers) ---
    const float* basl = basis + (size_t)l * RR * DHID;

    auto issue_b = [&](int c) {
        const uint32_t dst0 = sm0 + OFF_SC + (c % 3) * SC_BUF;
        const float* src0 = basl + (size_t)(c * 4) * DHID;
        #pragma unroll
        for (int j = 0; j < 2; ++j) {
            int idx = t + j * 512;          // 0..1023
            int rl  = idx >> 8;             // 0..3
            int d4  = idx & 255;
            CP_ASYNC16(dst0 + rl * SC_ST + d4 * 16, src0 + rl * DHID + d4 * 4);
        }
        CP_COMMIT();
    };

    issue_b(0);
    issue_b(1);

    for (int c = 0; c < 16; ++c) {
        if (c < 15) CP_WAIT1(); else CP_WAIT0();
        __syncthreads();

        if (c + 2 < 16) issue_b(c + 2);

        const char* sc = smraw2 + OFF_SC + (c % 3) * SC_BUF;
        {
            int rl = t >> 7;                // 0..3
            int d8 = (t & 127) * 8;
            const float4* s4 = (const float4*)(sc + rl * SC_ST + d8 * 4);
            float4 v0 = s4[0];
            float4 v1 = s4[1];
            __half2 h0 = __floats2half2_rn(v0.x, v0.y);
            __half2 h1 = __floats2half2_rn(v0.z, v0.w);
            __half2 h2 = __floats2half2_rn(v1.x, v1.y);
            __half2 h3 = __floats2half2_rn(v1.z, v1.w);
            __half2* d = (__half2*)(smraw2 + OFF_B + (c * 4 + rl) * U_ST + d8 * 2);
            d[0] = h0; d[1] = h1; d[2] = h2; d[3] = h3;
        }
    }
    __syncthreads();

    // --- Phase 1: scores via mma, K split across warp pairs ---
    {
        const int wk = warp >> 3;           // 0/1: k-half
        const int wr = warp & 7;            // r-block
        float acc4[4] = {0.f, 0.f, 0.f, 0.f};
        const uint32_t koff  = wk * 1024;   // 512 halves
        const uint32_t aAddr = sm0 + OFF_U + (lane & 15) * U_ST
                             + (lane >> 4) * 16 + koff;
        const uint32_t bAddr = sm0 + OFF_B + (wr * 8 + (lane & 7)) * U_ST
                             + (lane >> 3) * 16 + koff;
        #pragma unroll 4
        for (int kt2 = 0; kt2 < 16; ++kt2) {
            const uint32_t kb = kt2 * 64;
            uint32_t a0[4], a1[4], b4[4];
            ldm_x4(a0, aAddr + kb);
            ldm_x4(a1, aAddr + kb + 32);
            ldm_x4(b4, bAddr + kb);
            mma_f16(acc4, a0, b4[0], b4[1]);
            mma_f16(acc4, a1, b4[2], b4[3]);
        }
        float* sp = s_s + wk * (BB * SS_LD);
        const int r0 = wr * 8 + 2 * q;
        sp[g * SS_LD + r0]           = acc4[0];
        sp[g * SS_LD + r0 + 1]       = acc4[1];
        sp[(g + 8) * SS_LD + r0]     = acc4[2];
        sp[(g + 8) * SS_LD + r0 + 1] = acc4[3];
    }
    __syncthreads();

    // --- Phase 2: softmax; warp w handles b = w ---
    {
        const int b = warp;
        const float* s0 = s_s + b * SS_LD;
        const float* s1 = s_s + BB * SS_LD + b * SS_LD;
        float v0 = (s0[lane]      + s1[lane])      * scale;
        float v1 = (s0[lane + 32] + s1[lane + 32]) * scale;
        float mx = fmaxf(v0, v1);
        #pragma unroll
        for (int o = 16; o; o >>= 1) mx = fmaxf(mx, __shfl_xor_sync(0xffffffffu, mx, o));
        float e0 = __expf(v0 - mx);
        float e1 = __expf(v1 - mx);
        float sum = e0 + e1;
        #pragma unroll
        for (int o = 16; o; o >>= 1) sum += __shfl_xor_sync(0xffffffffu, sum, o);
        float inv = 1.f / sum;
        w_h[b * 72 + lane]      = __float2half_rn(e0 * inv);
        w_h[b * 72 + lane + 32] = __float2half_rn(e1 * inv);
    }
    __syncthreads();

    // --- Phase 3: y = W @ basis via mma (.trans B); warp owns d-span 64 ---
    {
        uint32_t afr[4][4];
        const uint32_t wAddr = sm0 + OFF_W + (lane & 15) * 144 + (lane >> 4) * 16;
        #pragma unroll
        for (int kt = 0; kt < 4; ++kt) ldm_x4(afr[kt], wAddr + kt * 32);

        const int d0w = warp * 64;
        const uint32_t bTA = sm0 + OFF_B + (lane & 15) * U_ST + (lane >> 4) * 16;
        #pragma unroll
        for (int jp = 0; jp < 4; ++jp) {
            const int d0 = d0w + jp * 16;
            float acc2[2][4];
            #pragma unroll
            for (int e = 0; e < 4; ++e) { acc2[0][e] = 0.f; acc2[1][e] = 0.f; }
            #pragma unroll
            for (int kt = 0; kt < 4; ++kt) {
                uint32_t bt[4];
                ldm_x4_trans(bt, bTA + kt * 16 * U_ST + d0 * 2);
                mma_f16(acc2[0], afr[kt], bt[0], bt[1]);
                mma_f16(acc2[1], afr[kt], bt[2], bt[3]);
            }
            #pragma unroll
            for (int jj = 0; jj < 2; ++jj) {
                const int col = d0 + 8 * jj + 2 * q;
                *(__half2*)&yh[((size_t)g * LL + l) * DHID + col] =
                    __floats2half2_rn(acc2[jj][0], acc2[jj][1]);
                *(__half2*)&yh[((size_t)(g + 8) * LL + l) * DHID + col] =
                    __floats2half2_rn(acc2[jj][2], acc2[jj][3]);
            }
        }
    }
}

// ---------------------------------------------------------------------------
// Launch
// ---------------------------------------------------------------------------
extern "C" void kernel_launch(void* const* d_in, const int* in_sizes, int n_in,
                              void* d_out, int out_size)
{
    const float* s_emb  = (const float*)d_in[0];
    const float* t_emb  = (const float*)d_in[1];
    const float* basis  = (const float*)d_in[2];
    const float* q_W    = (const float*)d_in[3];
    const float* q_b    = (const float*)d_in[4];
    const float* k_W    = (const float*)d_in[5];
    const float* k_b    = (const float*)d_in[6];
    const float* qk_W   = (const float*)d_in[7];
    const float* qk_b   = (const float*)d_in[8];
    const float* bk_W   = (const float*)d_in[9];
    // d_in[10] = bk_b : provably unused (softmax shift invariance)
    const float* bv_W   = (const float*)d_in[11];
    const float* bv_b   = (const float*)d_in[12];
    float* out = (float*)d_out;

    float  *p_c;
    __half *p_sh, *p_th, *p_qh, *p_uh, *p_yh;
    __half *p_Ah, *p_Bmh, *p_bkTh, *p_bvh;
    cudaGetSymbolAddress((void**)&p_c,    g_c);
    cudaGetSymbolAddress((void**)&p_sh,   g_sh);
    cudaGetSymbolAddress((void**)&p_th,   g_th);
    cudaGetSymbolAddress((void**)&p_qh,   g_qh);
    cudaGetSymbolAddress((void**)&p_uh,   g_uh);
    cudaGetSymbolAddress((void**)&p_yh,   g_yh);
    cudaGetSymbolAddress((void**)&p_Ah,   g_Ah);
    cudaGetSymbolAddress((void**)&p_Bmh,  g_Bmh);
    cudaGetSymbolAddress((void**)&p_bkTh, g_bkTh);
    cudaGetSymbolAddress((void**)&p_bvh,  g_bvh);

    cudaFuncSetAttribute(attention_kernel,
                         cudaFuncAttributeMaxDynamicSharedMemorySize, ATT4_SMEM);
    cudaFuncSetAttribute(gemm_h_nt,
                         cudaFuncAttributeMaxDynamicSharedMemorySize, SMEM_G);

    // launch 0: fused projection matrices Ah, Bmh
    {
        dim3 grid(DHID / BN, 8);
        prep_weights_kernel<<<grid, 256>>>(p_Ah, p_Bmh, qk_W, q_W, k_W);
    }

    // launch 1: fused bias (parallel)
    fuse_bias_kernel<<<DA, 256>>>(p_c, qk_W, q_b, k_b, qk_b);

    // launch 2: bk_W transpose -> fp16
    {
        dim3 tg(DHID / 32, DA / 32);
        transpose_h_kernel<<<tg, dim3(32, 8)>>>(p_bkTh, bk_W, DA, DHID);
    }

    // launch 3 (ncu capture slot): s,t -> fp16
    const int ne = MTOT * DHID;
    cvt_pair32to16<<<ne / 8 / 256, 256>>>(p_sh, s_emb, p_th, t_emb, ne);

    // launch 4: bv_W -> fp16
    cvt32to16<<<(DA * DHID) / 8 / 256, 256>>>(p_bvh, bv_W, DA * DHID);

    // launch 5: qk = s@A^T + t@Bm^T + c -> fp16
    {
        GArgs ga = { p_sh, p_Ah, p_th, p_Bmh, DHID, DHID };
        dim3 grid(DA / 128, MTOT / 128);
        gemm_h_nt<<<grid, 256, SMEM_G>>>(ga, p_c, nullptr, p_qh, MTOT, DA);
    }

    // launch 6: u = qk @ bkT^T -> fp16
    {
        GArgs ga = { p_qh, p_bkTh, nullptr, nullptr, DA, 0 };
        dim3 grid(DHID / 128, MTOT / 128);
        gemm_h_nt<<<grid, 256, SMEM_G>>>(ga, nullptr, nullptr, p_uh, MTOT, DHID);
    }

    // launch 7: attention v4 (512 threads)
    attention_kernel<<<LL, 512, ATT4_SMEM>>>(p_uh, basis, p_yh);

    // launch 8: z = y @ bv_W^T + bv_b -> fp32 out
    {
        GArgs ga = { p_yh, p_bvh, nullptr, nullptr, DHID, 0 };
        dim3 grid(DA / 128, MTOT / 128);
        gemm_h_nt<<<grid, 256, SMEM_G>>>(ga, bv_b, out, nullptr, MTOT, DA);
    }
}

// round 15
// speedup vs baseline: 2.3104x; 1.0428x over previous
#include <cuda_runtime.h>
#include <cuda_fp16.h>
#include <math.h>
#include <stdint.h>

// Problem constants
#define DHID 1024
#define DA   512
#define BB   16
#define LL   2048
#define RR   64
#define MTOT (BB*LL)   // 32768

// ---------------------------------------------------------------------------
// Scratch (static device globals; no allocations allowed)
// ---------------------------------------------------------------------------
__device__ __half g_sh [(size_t)MTOT * DHID];  // student fp16
__device__ __half g_th [(size_t)MTOT * DHID];  // teacher fp16
__device__ __half g_qh [(size_t)MTOT * DA];    // qk fp16
__device__ __half g_uh [(size_t)MTOT * DHID];  // u fp16
__device__ __half g_yh [(size_t)MTOT * DHID];  // y fp16
__device__ float  g_c  [DA];                   // fused bias (fp32)
__device__ __half g_Ah  [DA * DHID];           // fused qk_W1 @ q_W (fp16)
__device__ __half g_Bmh [DA * DHID];           // fused qk_W2 @ k_W (fp16)
__device__ __half g_bkTh[DHID * DA];           // bk_W transposed (fp16)
__device__ __half g_bvh [DA * DHID];           // bv_W (fp16)

// ---------------------------------------------------------------------------
// mma / ldmatrix helpers
// ---------------------------------------------------------------------------
__device__ __forceinline__ void mma_f16(float* c, const uint32_t* a,
                                        uint32_t b0, uint32_t b1)
{
    asm volatile(
        "mma.sync.aligned.m16n8k16.row.col.f32.f16.f16.f32 "
        "{%0,%1,%2,%3}, {%4,%5,%6,%7}, {%8,%9}, {%0,%1,%2,%3};\n"
        : "+f"(c[0]), "+f"(c[1]), "+f"(c[2]), "+f"(c[3])
        : "r"(a[0]), "r"(a[1]), "r"(a[2]), "r"(a[3]), "r"(b0), "r"(b1));
}

__device__ __forceinline__ void ldm_x4(uint32_t* r, uint32_t addr)
{
    asm volatile(
        "ldmatrix.sync.aligned.m8n8.x4.shared.b16 {%0,%1,%2,%3}, [%4];\n"
        : "=r"(r[0]), "=r"(r[1]), "=r"(r[2]), "=r"(r[3]) : "r"(addr));
}

__device__ __forceinline__ void ldm_x4_trans(uint32_t* r, uint32_t addr)
{
    asm volatile(
        "ldmatrix.sync.aligned.m8n8.x4.trans.shared.b16 {%0,%1,%2,%3}, [%4];\n"
        : "=r"(r[0]), "=r"(r[1]), "=r"(r[2]), "=r"(r[3]) : "r"(addr));
}

__device__ __forceinline__ uint32_t smem_u32(const void* p) {
    uint32_t a;
    asm("{ .reg .u64 t; cvta.to.shared.u64 t, %1; cvt.u32.u64 %0, t; }"
        : "=r"(a) : "l"(p));
    return a;
}

#define CP_ASYNC16(dst, src) \
    asm volatile("cp.async.cg.shared.global [%0], [%1], 16;" \
                 :: "r"(dst), "l"(src) : "memory")
#define CP_COMMIT() asm volatile("cp.async.commit_group;" ::: "memory")
#define CP_WAIT1()  asm volatile("cp.async.wait_group 1;" ::: "memory")
#define CP_WAIT0()  asm volatile("cp.async.wait_group 0;" ::: "memory")

// ---------------------------------------------------------------------------
// fp16 GEMM (NT), K-chunk = 64 (validated best config — unchanged)
// ---------------------------------------------------------------------------
#define ROWB   144
#define PLANE  (128 * ROWB)           // 18432 B
#define NSTAGE 3
#define SMEM_G (NSTAGE * 2 * PLANE)   // 110592 B -> occ 2

struct GArgs {
    const __half *X1, *W1;
    const __half *X2, *W2;
    int K1, K2;
};

__device__ __forceinline__ void ld_frags(
    uint32_t abase, uint32_t bbase, uint32_t kb, uint32_t* af, uint32_t* bf)
{
    ldm_x4(af + 0, abase + kb);
    ldm_x4(af + 4, abase + kb + 16 * ROWB);
    #pragma unroll
    for (int j = 0; j < 4; ++j) ldm_x4(bf + 4 * j, bbase + kb + j * 16 * ROWB);
}

#define ISSUE8(pX, pW, k) do {                       \
    CP_ASYNC16(sb + dofA[0], (pX)[0] + (k));         \
    CP_ASYNC16(sb + dofA[1], (pX)[1] + (k));         \
    CP_ASYNC16(sb + dofA[2], (pX)[2] + (k));         \
    CP_ASYNC16(sb + dofA[3], (pX)[3] + (k));         \
    CP_ASYNC16(sb + dofB[0], (pW)[0] + (k));         \
    CP_ASYNC16(sb + dofB[1], (pW)[1] + (k));         \
    CP_ASYNC16(sb + dofB[2], (pW)[2] + (k));         \
    CP_ASYNC16(sb + dofB[3], (pW)[3] + (k));         \
    CP_COMMIT();                                     \
} while (0)

__global__ void __launch_bounds__(256, 2) gemm_h_nt(
    GArgs ga,
    const float* __restrict__ bias,
    float* __restrict__ Cf,               // fp32 out (nullable)
    __half* __restrict__ Ch,              // fp16 out (if Cf null)
    int M, int N)
{
    extern __shared__ __align__(16) char smraw[];
    const uint32_t sm0 = smem_u32(smraw);

    const int t    = threadIdx.x;
    const int warp = t >> 5;
    const int lane = t & 31;
    const int bm   = blockIdx.y * 128;
    const int bn   = blockIdx.x * 128;
    const int mw   = (warp & 3) * 32;
    const int nw   = (warp >> 2) * 64;
    const uint32_t laneoff = (lane & 15) * ROWB + (lane >> 4) * 16;
    const uint32_t aBase   = mw * ROWB + laneoff;
    const uint32_t bBase   = PLANE + nw * ROWB + laneoff;

    const int rbase = t >> 3;
    const int grp   = t & 7;
    const __half *pX1[4], *pW1[4], *pX2[4], *pW2[4];
    uint32_t dofA[4], dofB[4];
    #pragma unroll
    for (int o = 0; o < 4; ++o) {
        const int row = rbase + o * 32;
        pX1[o] = ga.X1 + (size_t)(bm + row) * ga.K1 + grp * 8;
        pW1[o] = ga.W1 + (size_t)(bn + row) * ga.K1 + grp * 8;
        dofA[o] = row * ROWB + grp * 16;
        dofB[o] = PLANE + row * ROWB + grp * 16;
    }
    #pragma unroll
    for (int o = 0; o < 4; ++o) { pX2[o] = pX1[o]; pW2[o] = pW1[o]; }
    if (ga.X2) {
        #pragma unroll
        for (int o = 0; o < 4; ++o) {
            const int row = rbase + o * 32;
            pX2[o] = ga.X2 + (size_t)(bm + row) * ga.K2 + grp * 8;
            pW2[o] = ga.W2 + (size_t)(bn + row) * ga.K2 + grp * 8;
        }
    }

    const int nc1 = ga.K1 / 64;
    const int nch = ga.X2 ? nc1 + ga.K2 / 64 : nc1;

    float acc[2][8][4];
    #pragma unroll
    for (int i = 0; i < 2; ++i)
        #pragma unroll
        for (int j = 0; j < 8; ++j)
            #pragma unroll
            for (int e = 0; e < 4; ++e) acc[i][j][e] = 0.f;

    #pragma unroll
    for (int c0 = 0; c0 < 2; ++c0) {
        if (c0 < nch) {
            const uint32_t sb = sm0 + (c0 % NSTAGE) * 2 * PLANE;
            if (c0 < nc1) { const int k = c0 * 64;         ISSUE8(pX1, pW1, k); }
            else          { const int k = (c0 - nc1) * 64; ISSUE8(pX2, pW2, k); }
        }
    }

    uint32_t af[2][8], bf[2][16];

    for (int c = 0; c < nch; ++c) {
        if (c + 2 <= nch) CP_WAIT1(); else CP_WAIT0();
        __syncthreads();

        const uint32_t sbuf = sm0 + (c % NSTAGE) * 2 * PLANE;
        const uint32_t ab = sbuf + aBase;
        const uint32_t bb = sbuf + bBase;

        ld_frags(ab, bb, 0, af[0], bf[0]);
        #pragma unroll
        for (int ks = 0; ks < 4; ++ks) {
            const int cur = ks & 1;
            if (ks < 3)
                ld_frags(ab, bb, (ks + 1) * 32, af[cur ^ 1], bf[cur ^ 1]);
            #pragma unroll
            for (int i = 0; i < 2; ++i) {
                const uint32_t* ah = af[cur] + 4 * i;
                #pragma unroll
                for (int j8 = 0; j8 < 8; ++j8) {
                    uint32_t b0 = bf[cur][4 * (j8 >> 1) + (j8 & 1)];
                    uint32_t b1 = bf[cur][4 * (j8 >> 1) + (j8 & 1) + 2];
                    mma_f16(acc[i][j8], ah, b0, b1);
                }
            }
        }

        if (c + 2 < nch) {
            const int cn = c + 2;
            const uint32_t sb = sm0 + (cn % NSTAGE) * 2 * PLANE;
            if (cn < nc1) { const int k = cn * 64;         ISSUE8(pX1, pW1, k); }
            else          { const int k = (cn - nc1) * 64; ISSUE8(pX2, pW2, k); }
        }
    }

    const int g = lane >> 2;
    const int q = lane & 3;
    #pragma unroll
    for (int i = 0; i < 2; ++i) {
        #pragma unroll
        for (int j8 = 0; j8 < 8; ++j8) {
            const int r0  = bm + mw + 16 * i + g;
            const int col = bn + nw + 8 * j8 + 2 * q;
            const float b0v = bias ? bias[col]     : 0.f;
            const float b1v = bias ? bias[col + 1] : 0.f;
            float v00 = acc[i][j8][0] + b0v, v01 = acc[i][j8][1] + b1v;
            float v10 = acc[i][j8][2] + b0v, v11 = acc[i][j8][3] + b1v;
            if (Cf) {
                *(float2*)&Cf[(size_t)r0 * N + col]       = make_float2(v00, v01);
                *(float2*)&Cf[(size_t)(r0 + 8) * N + col] = make_float2(v10, v11);
            } else {
                *(__half2*)&Ch[(size_t)r0 * N + col]       = __floats2half2_rn(v00, v01);
                *(__half2*)&Ch[(size_t)(r0 + 8) * N + col] = __floats2half2_rn(v10, v11);
            }
        }
    }
}

// ---------------------------------------------------------------------------
// Converters (8 elems/thread, single 16B store per array) — at DRAM roofline
// ---------------------------------------------------------------------------
__global__ void cvt_pair32to16(__half* __restrict__ h0, const float* __restrict__ s0,
                               __half* __restrict__ h1, const float* __restrict__ s1,
                               int n)
{
    int i = (blockIdx.x * blockDim.x + threadIdx.x) * 8;
    if (i >= n) return;
    {
        float4 a0 = *(const float4*)&s0[i];
        float4 a1 = *(const float4*)&s0[i + 4];
        uint4 o;
        ((__half2*)&o)[0] = __floats2half2_rn(a0.x, a0.y);
        ((__half2*)&o)[1] = __floats2half2_rn(a0.z, a0.w);
        ((__half2*)&o)[2] = __floats2half2_rn(a1.x, a1.y);
        ((__half2*)&o)[3] = __floats2half2_rn(a1.z, a1.w);
        *(uint4*)&h0[i] = o;
    }
    {
        float4 b0 = *(const float4*)&s1[i];
        float4 b1 = *(const float4*)&s1[i + 4];
        uint4 o;
        ((__half2*)&o)[0] = __floats2half2_rn(b0.x, b0.y);
        ((__half2*)&o)[1] = __floats2half2_rn(b0.z, b0.w);
        ((__half2*)&o)[2] = __floats2half2_rn(b1.x, b1.y);
        ((__half2*)&o)[3] = __floats2half2_rn(b1.z, b1.w);
        *(uint4*)&h1[i] = o;
    }
}

__global__ void cvt32to16(__half* __restrict__ h, const float* __restrict__ s, int n)
{
    int i = (blockIdx.x * blockDim.x + threadIdx.x) * 8;
    if (i >= n) return;
    float4 a0 = *(const float4*)&s[i];
    float4 a1 = *(const float4*)&s[i + 4];
    uint4 o;
    ((__half2*)&o)[0] = __floats2half2_rn(a0.x, a0.y);
    ((__half2*)&o)[1] = __floats2half2_rn(a0.z, a0.w);
    ((__half2*)&o)[2] = __floats2half2_rn(a1.x, a1.y);
    ((__half2*)&o)[3] = __floats2half2_rn(a1.z, a1.w);
    *(uint4*)&h[i] = o;
}

// ---------------------------------------------------------------------------
// Transpose (fp32 in -> fp16 out), once for bk_W
// ---------------------------------------------------------------------------
__global__ void transpose_h_kernel(__half* __restrict__ out,
                                   const float* __restrict__ in,
                                   int Rrows, int Ccols)
{
    __shared__ float tile[32][33];
    int x = blockIdx.x * 32 + threadIdx.x;
    int y = blockIdx.y * 32 + threadIdx.y;
    #pragma unroll
    for (int i = 0; i < 4; ++i)
        tile[threadIdx.y + 8 * i][threadIdx.x] = in[(size_t)(y + 8 * i) * Ccols + x];
    __syncthreads();
    x = blockIdx.y * 32 + threadIdx.x;
    y = blockIdx.x * 32 + threadIdx.y;
    #pragma unroll
    for (int i = 0; i < 4; ++i)
        out[(size_t)(y + 8 * i) * Rrows + x] =
            __float2half_rn(tile[threadIdx.x][threadIdx.y + 8 * i]);
}

// ---------------------------------------------------------------------------
// Combined prep: Ah = qk_W[:, :512] @ q_W ; Bmh = qk_W[:, 512:] @ k_W
// ---------------------------------------------------------------------------
#define BM 128
#define BN 128
#define BK 16

__global__ void __launch_bounds__(256, 2) prep_weights_kernel(
    __half* __restrict__ CA, __half* __restrict__ CB,
    const float* __restrict__ qk_W,
    const float* __restrict__ q_W, const float* __restrict__ k_W)
{
    const int half  = blockIdx.y >> 2;
    const int by    = blockIdx.y & 3;
    __half* C       = half ? CB : CA;
    const float* X  = half ? qk_W + DA : qk_W;
    const float* W  = half ? k_W : q_W;
    const int N = DHID, K = DA, ldx = 2 * DA;

    __shared__ float As[BK][BM];
    __shared__ float Bs[BK][BN];
    const int t  = threadIdx.x;
    const int bm = by * BM;
    const int bn = blockIdx.x * BN;

    float acc[8][8];
    #pragma unroll
    for (int i = 0; i < 8; ++i)
        #pragma unroll
        for (int j = 0; j < 8; ++j) acc[i][j] = 0.f;

    const int lrow = t >> 2;
    const int lc4  = (t & 3) * 4;
    const int wk   = t >> 5;
    const int wn4  = (t & 31) * 4;

    for (int k0 = 0; k0 < K; k0 += BK) {
        #pragma unroll
        for (int h = 0; h < 2; ++h) {
            int row = lrow + h * 64;
            float4 v = *(const float4*)&X[(size_t)(bm + row) * ldx + k0 + lc4];
            As[lc4 + 0][row] = v.x;
            As[lc4 + 1][row] = v.y;
            As[lc4 + 2][row] = v.z;
            As[lc4 + 3][row] = v.w;
            int k = wk + h * 8;
            float4 w = *(const float4*)&W[(size_t)(k0 + k) * N + bn + wn4];
            *(float4*)&Bs[k][wn4] = w;
        }
        __syncthreads();
        const int m8 = (t >> 4) * 8;
        const int n8 = (t & 15) * 8;
        #pragma unroll
        for (int kk = 0; kk < BK; ++kk) {
            float a[8], b[8];
            *(float4*)&a[0] = *(const float4*)&As[kk][m8];
            *(float4*)&a[4] = *(const float4*)&As[kk][m8 + 4];
            *(float4*)&b[0] = *(const float4*)&Bs[kk][n8];
            *(float4*)&b[4] = *(const float4*)&Bs[kk][n8 + 4];
            #pragma unroll
            for (int i = 0; i < 8; ++i)
                #pragma unroll
                for (int j = 0; j < 8; ++j)
                    acc[i][j] += a[i] * b[j];
        }
        __syncthreads();
    }

    const int m0 = bm + (t >> 4) * 8;
    const int n0 = bn + (t & 15) * 8;
    #pragma unroll
    for (int i = 0; i < 8; ++i) {
        __half2 h0 = __floats2half2_rn(acc[i][0], acc[i][1]);
        __half2 h1 = __floats2half2_rn(acc[i][2], acc[i][3]);
        __half2 h2 = __floats2half2_rn(acc[i][4], acc[i][5]);
        __half2 h3 = __floats2half2_rn(acc[i][6], acc[i][7]);
        __half* dst = &C[(size_t)(m0 + i) * N + n0];
        *(__half2*)(dst + 0) = h0;
        *(__half2*)(dst + 2) = h1;
        *(__half2*)(dst + 4) = h2;
        *(__half2*)(dst + 6) = h3;
    }
}

// ---------------------------------------------------------------------------
// Fused bias (parallel)
// ---------------------------------------------------------------------------
__global__ void fuse_bias_kernel(float* __restrict__ c,
                                 const float* __restrict__ qk_W,
                                 const float* __restrict__ q_b,
                                 const float* __restrict__ k_b,
                                 const float* __restrict__ qk_b)
{
    __shared__ float red[8];
    const int i = blockIdx.x;
    const int t = threadIdx.x;
    const float* row = qk_W + (size_t)i * (2 * DA);
    float s = 0.f;
    for (int j = t; j < DA; j += 256)
        s += row[j] * q_b[j] + row[DA + j] * k_b[j];
    #pragma unroll
    for (int o = 16; o; o >>= 1) s += __shfl_xor_sync(0xffffffffu, s, o);
    if ((t & 31) == 0) red[t >> 5] = s;
    __syncthreads();
    if (t == 0) {
        float tot = qk_b[i];
        #pragma unroll
        for (int k = 0; k < 8; ++k) tot += red[k];
        c[i] = tot;
    }
}

// ---------------------------------------------------------------------------
// Attention v5: 512 threads, direct-LDG register-pipelined basis staging
// (no scratch, ONE sync), tensor-core phases as v4.
// smem layout (bytes):
//   OFF_B = 0      : basis fp16, 64 x 2064   = 132096
//   OFF_U = 132096 : u fp16, 16 x 2064       =  33024
//   OFF_W = 165120 : softmax weights, 16x72h =   2304
//   OFF_S = 167424 : scores fp32, 2 x 16x65  =   8320
//   total 175744
// ---------------------------------------------------------------------------
#define U_ST   2064
#define OFF_B  0
#define OFF_U  132096
#define OFF_W  165120
#define OFF_S  167424
#define SS_LD  65
#define ATT5_SMEM (OFF_S + 2 * BB * SS_LD * 4)  // 175744

__global__ void __launch_bounds__(512) attention_kernel(
    const __half* __restrict__ u,     // (B*L, 1024) fp16
    const float* __restrict__ basis,  // (L, R, 1024) fp32
    __half* __restrict__ yh)
{
    extern __shared__ __align__(16) char smraw2[];
    const uint32_t sm0 = smem_u32(smraw2);
    float*  s_s = (float*)(smraw2 + OFF_S);
    __half* w_h = (__half*)(smraw2 + OFF_W);

    const int l    = blockIdx.x;
    const int t    = threadIdx.x;
    const int warp = t >> 5;          // 0..15
    const int lane = t & 31;
    const int g    = lane >> 2;
    const int q    = lane & 3;
    const float scale = 0.044194173824159216f;  // 1/sqrt(512)

    // --- u staging (cp.async, one group) ---
    #pragma unroll
    for (int it = 0; it < 4; ++it) {
        int idx = t + it * 512;
        int b   = idx >> 7;
        int d8  = (idx & 127) * 8;
        CP_ASYNC16(sm0 + OFF_U + b * U_ST + d8 * 2,
                   &u[((size_t)b * LL + l) * DHID + d8]);
    }
    CP_COMMIT();

    // --- basis staging: direct LDG fp32, register double-buffer, STS fp16 ---
    // 8 chunks of 8 rows. Thread covers row (t>>6) in chunk, lane-in-row
    // lr = t&63; 4 float4 per thread at d4 = lr + 64*j.
    {
        const int rown = t >> 6;            // 0..7
        const int lr   = t & 63;
        const float* src0 = basis + (size_t)l * RR * DHID
                          + (size_t)rown * DHID + lr * 4;
        char* dst0 = smraw2 + OFF_B + rown * U_ST + lr * 8;

        float4 v[2][4];
        #pragma unroll
        for (int j = 0; j < 4; ++j) v[0][j] = *(const float4*)(src0 + 256 * j);

        #pragma unroll
        for (int c = 0; c < 8; ++c) {
            const int cur = c & 1;
            if (c < 7) {
                const float* s = src0 + (size_t)(c + 1) * 8 * DHID;
                #pragma unroll
                for (int j = 0; j < 4; ++j)
                    v[cur ^ 1][j] = *(const float4*)(s + 256 * j);
            }
            char* d = dst0 + (size_t)c * 8 * U_ST;
            #pragma unroll
            for (int j = 0; j < 4; ++j) {
                __half2 h01 = __floats2half2_rn(v[cur][j].x, v[cur][j].y);
                __half2 h23 = __floats2half2_rn(v[cur][j].z, v[cur][j].w);
                *(__half2*)(d + 512 * j)     = h01;
                *(__half2*)(d + 512 * j + 4) = h23;
            }
        }
    }
    CP_WAIT0();        // u group
    __syncthreads();   // basis tile + u visible to all

    // --- Phase 1: scores via mma, K split across warp pairs ---
    {
        const int wk = warp >> 3;           // 0/1: k-half
        const int wr = warp & 7;            // r-block
        float acc4[4] = {0.f, 0.f, 0.f, 0.f};
        const uint32_t koff  = wk * 1024;   // 512 halves
        const uint32_t aAddr = sm0 + OFF_U + (lane & 15) * U_ST
                             + (lane >> 4) * 16 + koff;
        const uint32_t bAddr = sm0 + OFF_B + (wr * 8 + (lane & 7)) * U_ST
                             + (lane >> 3) * 16 + koff;
        #pragma unroll 4
        for (int kt2 = 0; kt2 < 16; ++kt2) {
            const uint32_t kb = kt2 * 64;
            uint32_t a0[4], a1[4], b4[4];
            ldm_x4(a0, aAddr + kb);
            ldm_x4(a1, aAddr + kb + 32);
            ldm_x4(b4, bAddr + kb);
            mma_f16(acc4, a0, b4[0], b4[1]);
            mma_f16(acc4, a1, b4[2], b4[3]);
        }
        float* sp = s_s + wk * (BB * SS_LD);
        const int r0 = wr * 8 + 2 * q;
        sp[g * SS_LD + r0]           = acc4[0];
        sp[g * SS_LD + r0 + 1]       = acc4[1];
        sp[(g + 8) * SS_LD + r0]     = acc4[2];
        sp[(g + 8) * SS_LD + r0 + 1] = acc4[3];
    }
    __syncthreads();

    // --- Phase 2: softmax; warp w handles b = w ---
    {
        const int b = warp;
        const float* s0 = s_s + b * SS_LD;
        const float* s1 = s_s + BB * SS_LD + b * SS_LD;
        float v0 = (s0[lane]      + s1[lane])      * scale;
        float v1 = (s0[lane + 32] + s1[lane + 32]) * scale;
        float mx = fmaxf(v0, v1);
        #pragma unroll
        for (int o = 16; o; o >>= 1) mx = fmaxf(mx, __shfl_xor_sync(0xffffffffu, mx, o));
        float e0 = __expf(v0 - mx);
        float e1 = __expf(v1 - mx);
        float sum = e0 + e1;
        #pragma unroll
        for (int o = 16; o; o >>= 1) sum += __shfl_xor_sync(0xffffffffu, sum, o);
        float inv = 1.f / sum;
        w_h[b * 72 + lane]      = __float2half_rn(e0 * inv);
        w_h[b * 72 + lane + 32] = __float2half_rn(e1 * inv);
    }
    __syncthreads();

    // --- Phase 3: y = W @ basis via mma (.trans B); warp owns d-span 64 ---
    {
        uint32_t afr[4][4];
        const uint32_t wAddr = sm0 + OFF_W + (lane & 15) * 144 + (lane >> 4) * 16;
        #pragma unroll
        for (int kt = 0; kt < 4; ++kt) ldm_x4(afr[kt], wAddr + kt * 32);

        const int d0w = warp * 64;
        const uint32_t bTA = sm0 + OFF_B + (lane & 15) * U_ST + (lane >> 4) * 16;
        #pragma unroll
        for (int jp = 0; jp < 4; ++jp) {
            const int d0 = d0w + jp * 16;
            float acc2[2][4];
            #pragma unroll
            for (int e = 0; e < 4; ++e) { acc2[0][e] = 0.f; acc2[1][e] = 0.f; }
            #pragma unroll
            for (int kt = 0; kt < 4; ++kt) {
                uint32_t bt[4];
                ldm_x4_trans(bt, bTA + kt * 16 * U_ST + d0 * 2);
                mma_f16(acc2[0], afr[kt], bt[0], bt[1]);
                mma_f16(acc2[1], afr[kt], bt[2], bt[3]);
            }
            #pragma unroll
            for (int jj = 0; jj < 2; ++jj) {
                const int col = d0 + 8 * jj + 2 * q;
                *(__half2*)&yh[((size_t)g * LL + l) * DHID + col] =
                    __floats2half2_rn(acc2[jj][0], acc2[jj][1]);
                *(__half2*)&yh[((size_t)(g + 8) * LL + l) * DHID + col] =
                    __floats2half2_rn(acc2[jj][2], acc2[jj][3]);
            }
        }
    }
}

// ---------------------------------------------------------------------------
// Launch
// ---------------------------------------------------------------------------
extern "C" void kernel_launch(void* const* d_in, const int* in_sizes, int n_in,
                              void* d_out, int out_size)
{
    const float* s_emb  = (const float*)d_in[0];
    const float* t_emb  = (const float*)d_in[1];
    const float* basis  = (const float*)d_in[2];
    const float* q_W    = (const float*)d_in[3];
    const float* q_b    = (const float*)d_in[4];
    const float* k_W    = (const float*)d_in[5];
    const float* k_b    = (const float*)d_in[6];
    const float* qk_W   = (const float*)d_in[7];
    const float* qk_b   = (const float*)d_in[8];
    const float* bk_W   = (const float*)d_in[9];
    // d_in[10] = bk_b : provably unused (softmax shift invariance)
    const float* bv_W   = (const float*)d_in[11];
    const float* bv_b   = (const float*)d_in[12];
    float* out = (float*)d_out;

    float  *p_c;
    __half *p_sh, *p_th, *p_qh, *p_uh, *p_yh;
    __half *p_Ah, *p_Bmh, *p_bkTh, *p_bvh;
    cudaGetSymbolAddress((void**)&p_c,    g_c);
    cudaGetSymbolAddress((void**)&p_sh,   g_sh);
    cudaGetSymbolAddress((void**)&p_th,   g_th);
    cudaGetSymbolAddress((void**)&p_qh,   g_qh);
    cudaGetSymbolAddress((void**)&p_uh,   g_uh);
    cudaGetSymbolAddress((void**)&p_yh,   g_yh);
    cudaGetSymbolAddress((void**)&p_Ah,   g_Ah);
    cudaGetSymbolAddress((void**)&p_Bmh,  g_Bmh);
    cudaGetSymbolAddress((void**)&p_bkTh, g_bkTh);
    cudaGetSymbolAddress((void**)&p_bvh,  g_bvh);

    cudaFuncSetAttribute(attention_kernel,
                         cudaFuncAttributeMaxDynamicSharedMemorySize, ATT5_SMEM);
    cudaFuncSetAttribute(gemm_h_nt,
                         cudaFuncAttributeMaxDynamicSharedMemorySize, SMEM_G);

    // launch 0: fused projection matrices Ah, Bmh
    {
        dim3 grid(DHID / BN, 8);
        prep_weights_kernel<<<grid, 256>>>(p_Ah, p_Bmh, qk_W, q_W, k_W);
    }

    // launch 1: fused bias (parallel)
    fuse_bias_kernel<<<DA, 256>>>(p_c, qk_W, q_b, k_b, qk_b);

    // launch 2: bk_W transpose -> fp16
    {
        dim3 tg(DHID / 32, DA / 32);
        transpose_h_kernel<<<tg, dim3(32, 8)>>>(p_bkTh, bk_W, DA, DHID);
    }

    // launch 3 (ncu capture slot): s,t -> fp16
    const int ne = MTOT * DHID;
    cvt_pair32to16<<<ne / 8 / 256, 256>>>(p_sh, s_emb, p_th, t_emb, ne);

    // launch 4: bv_W -> fp16
    cvt32to16<<<(DA * DHID) / 8 / 256, 256>>>(p_bvh, bv_W, DA * DHID);

    // launch 5: qk = s@A^T + t@Bm^T + c -> fp16
    {
        GArgs ga = { p_sh, p_Ah, p_th, p_Bmh, DHID, DHID };
        dim3 grid(DA / 128, MTOT / 128);
        gemm_h_nt<<<grid, 256, SMEM_G>>>(ga, p_c, nullptr, p_qh, MTOT, DA);
    }

    // launch 6: u = qk @ bkT^T -> fp16
    {
        GArgs ga = { p_qh, p_bkTh, nullptr, nullptr, DA, 0 };
        dim3 grid(DHID / 128, MTOT / 128);
        gemm_h_nt<<<grid, 256, SMEM_G>>>(ga, nullptr, nullptr, p_uh, MTOT, DHID);
    }

    // launch 7: attention v5 (direct-LDG staging, 512 threads)
    attention_kernel<<<LL, 512, ATT5_SMEM>>>(p_uh, basis, p_yh);

    // launch 8: z = y @ bv_W^T + bv_b -> fp32 out
    {
        GArgs ga = { p_yh, p_bvh, nullptr, nullptr, DHID, 0 };
        dim3 grid(DA / 128, MTOT / 128);
        gemm_h_nt<<<grid, 256, SMEM_G>>>(ga, bv_b, out, nullptr, MTOT, DA);
    }
}

// round 16
// speedup vs baseline: 2.3155x; 1.0022x over previous
#include <cuda_runtime.h>
#include <cuda_fp16.h>
#include <math.h>
#include <stdint.h>

// Problem constants
#define DHID 1024
#define DA   512
#define BB   16
#define LL   2048
#define RR   64
#define MTOT (BB*LL)   // 32768

// ---------------------------------------------------------------------------
// Scratch (static device globals; no allocations allowed)
// ---------------------------------------------------------------------------
__device__ __half g_sh [(size_t)MTOT * DHID];  // student fp16
__device__ __half g_th [(size_t)MTOT * DHID];  // teacher fp16
__device__ __half g_qh [(size_t)MTOT * DA];    // qk fp16
__device__ __half g_uh [(size_t)MTOT * DHID];  // u fp16
__device__ __half g_yh [(size_t)MTOT * DHID];  // y fp16
__device__ float  g_c  [DA];                   // fused bias (fp32)
__device__ __half g_Ah  [DA * DHID];           // fused qk_W1 @ q_W (fp16)
__device__ __half g_Bmh [DA * DHID];           // fused qk_W2 @ k_W (fp16)
__device__ __half g_bkTh[DHID * DA];           // bk_W transposed (fp16)
__device__ __half g_bvh [DA * DHID];           // bv_W (fp16)

// ---------------------------------------------------------------------------
// mma / ldmatrix helpers
// ---------------------------------------------------------------------------
__device__ __forceinline__ void mma_f16(float* c, const uint32_t* a,
                                        uint32_t b0, uint32_t b1)
{
    asm volatile(
        "mma.sync.aligned.m16n8k16.row.col.f32.f16.f16.f32 "
        "{%0,%1,%2,%3}, {%4,%5,%6,%7}, {%8,%9}, {%0,%1,%2,%3};\n"
        : "+f"(c[0]), "+f"(c[1]), "+f"(c[2]), "+f"(c[3])
        : "r"(a[0]), "r"(a[1]), "r"(a[2]), "r"(a[3]), "r"(b0), "r"(b1));
}

__device__ __forceinline__ void ldm_x4(uint32_t* r, uint32_t addr)
{
    asm volatile(
        "ldmatrix.sync.aligned.m8n8.x4.shared.b16 {%0,%1,%2,%3}, [%4];\n"
        : "=r"(r[0]), "=r"(r[1]), "=r"(r[2]), "=r"(r[3]) : "r"(addr));
}

__device__ __forceinline__ void ldm_x4_trans(uint32_t* r, uint32_t addr)
{
    asm volatile(
        "ldmatrix.sync.aligned.m8n8.x4.trans.shared.b16 {%0,%1,%2,%3}, [%4];\n"
        : "=r"(r[0]), "=r"(r[1]), "=r"(r[2]), "=r"(r[3]) : "r"(addr));
}

__device__ __forceinline__ uint32_t smem_u32(const void* p) {
    uint32_t a;
    asm("{ .reg .u64 t; cvta.to.shared.u64 t, %1; cvt.u32.u64 %0, t; }"
        : "=r"(a) : "l"(p));
    return a;
}

#define CP_ASYNC16(dst, src) \
    asm volatile("cp.async.cg.shared.global [%0], [%1], 16;" \
                 :: "r"(dst), "l"(src) : "memory")
#define CP_COMMIT() asm volatile("cp.async.commit_group;" ::: "memory")
#define CP_WAIT1()  asm volatile("cp.async.wait_group 1;" ::: "memory")
#define CP_WAIT0()  asm volatile("cp.async.wait_group 0;" ::: "memory")

// ---------------------------------------------------------------------------
// fp16 GEMM (NT), K-chunk = 64 (validated best config — unchanged)
// ---------------------------------------------------------------------------
#define ROWB   144
#define PLANE  (128 * ROWB)           // 18432 B
#define NSTAGE 3
#define SMEM_G (NSTAGE * 2 * PLANE)   // 110592 B -> occ 2

struct GArgs {
    const __half *X1, *W1;
    const __half *X2, *W2;
    int K1, K2;
};

__device__ __forceinline__ void ld_frags(
    uint32_t abase, uint32_t bbase, uint32_t kb, uint32_t* af, uint32_t* bf)
{
    ldm_x4(af + 0, abase + kb);
    ldm_x4(af + 4, abase + kb + 16 * ROWB);
    #pragma unroll
    for (int j = 0; j < 4; ++j) ldm_x4(bf + 4 * j, bbase + kb + j * 16 * ROWB);
}

#define ISSUE8(pX, pW, k) do {                       \
    CP_ASYNC16(sb + dofA[0], (pX)[0] + (k));         \
    CP_ASYNC16(sb + dofA[1], (pX)[1] + (k));         \
    CP_ASYNC16(sb + dofA[2], (pX)[2] + (k));         \
    CP_ASYNC16(sb + dofA[3], (pX)[3] + (k));         \
    CP_ASYNC16(sb + dofB[0], (pW)[0] + (k));         \
    CP_ASYNC16(sb + dofB[1], (pW)[1] + (k));         \
    CP_ASYNC16(sb + dofB[2], (pW)[2] + (k));         \
    CP_ASYNC16(sb + dofB[3], (pW)[3] + (k));         \
    CP_COMMIT();                                     \
} while (0)

__global__ void __launch_bounds__(256, 2) gemm_h_nt(
    GArgs ga,
    const float* __restrict__ bias,
    float* __restrict__ Cf,               // fp32 out (nullable)
    __half* __restrict__ Ch,              // fp16 out (if Cf null)
    int M, int N)
{
    extern __shared__ __align__(16) char smraw[];
    const uint32_t sm0 = smem_u32(smraw);

    const int t    = threadIdx.x;
    const int warp = t >> 5;
    const int lane = t & 31;
    const int bm   = blockIdx.y * 128;
    const int bn   = blockIdx.x * 128;
    const int mw   = (warp & 3) * 32;
    const int nw   = (warp >> 2) * 64;
    const uint32_t laneoff = (lane & 15) * ROWB + (lane >> 4) * 16;
    const uint32_t aBase   = mw * ROWB + laneoff;
    const uint32_t bBase   = PLANE + nw * ROWB + laneoff;

    const int rbase = t >> 3;
    const int grp   = t & 7;
    const __half *pX1[4], *pW1[4], *pX2[4], *pW2[4];
    uint32_t dofA[4], dofB[4];
    #pragma unroll
    for (int o = 0; o < 4; ++o) {
        const int row = rbase + o * 32;
        pX1[o] = ga.X1 + (size_t)(bm + row) * ga.K1 + grp * 8;
        pW1[o] = ga.W1 + (size_t)(bn + row) * ga.K1 + grp * 8;
        dofA[o] = row * ROWB + grp * 16;
        dofB[o] = PLANE + row * ROWB + grp * 16;
    }
    #pragma unroll
    for (int o = 0; o < 4; ++o) { pX2[o] = pX1[o]; pW2[o] = pW1[o]; }
    if (ga.X2) {
        #pragma unroll
        for (int o = 0; o < 4; ++o) {
            const int row = rbase + o * 32;
            pX2[o] = ga.X2 + (size_t)(bm + row) * ga.K2 + grp * 8;
            pW2[o] = ga.W2 + (size_t)(bn + row) * ga.K2 + grp * 8;
        }
    }

    const int nc1 = ga.K1 / 64;
    const int nch = ga.X2 ? nc1 + ga.K2 / 64 : nc1;

    float acc[2][8][4];
    #pragma unroll
    for (int i = 0; i < 2; ++i)
        #pragma unroll
        for (int j = 0; j < 8; ++j)
            #pragma unroll
            for (int e = 0; e < 4; ++e) acc[i][j][e] = 0.f;

    #pragma unroll
    for (int c0 = 0; c0 < 2; ++c0) {
        if (c0 < nch) {
            const uint32_t sb = sm0 + (c0 % NSTAGE) * 2 * PLANE;
            if (c0 < nc1) { const int k = c0 * 64;         ISSUE8(pX1, pW1, k); }
            else          { const int k = (c0 - nc1) * 64; ISSUE8(pX2, pW2, k); }
        }
    }

    uint32_t af[2][8], bf[2][16];

    for (int c = 0; c < nch; ++c) {
        if (c + 2 <= nch) CP_WAIT1(); else CP_WAIT0();
        __syncthreads();

        const uint32_t sbuf = sm0 + (c % NSTAGE) * 2 * PLANE;
        const uint32_t ab = sbuf + aBase;
        const uint32_t bb = sbuf + bBase;

        ld_frags(ab, bb, 0, af[0], bf[0]);
        #pragma unroll
        for (int ks = 0; ks < 4; ++ks) {
            const int cur = ks & 1;
            if (ks < 3)
                ld_frags(ab, bb, (ks + 1) * 32, af[cur ^ 1], bf[cur ^ 1]);
            #pragma unroll
            for (int i = 0; i < 2; ++i) {
                const uint32_t* ah = af[cur] + 4 * i;
                #pragma unroll
                for (int j8 = 0; j8 < 8; ++j8) {
                    uint32_t b0 = bf[cur][4 * (j8 >> 1) + (j8 & 1)];
                    uint32_t b1 = bf[cur][4 * (j8 >> 1) + (j8 & 1) + 2];
                    mma_f16(acc[i][j8], ah, b0, b1);
                }
            }
        }

        if (c + 2 < nch) {
            const int cn = c + 2;
            const uint32_t sb = sm0 + (cn % NSTAGE) * 2 * PLANE;
            if (cn < nc1) { const int k = cn * 64;         ISSUE8(pX1, pW1, k); }
            else          { const int k = (cn - nc1) * 64; ISSUE8(pX2, pW2, k); }
        }
    }

    const int g = lane >> 2;
    const int q = lane & 3;
    #pragma unroll
    for (int i = 0; i < 2; ++i) {
        #pragma unroll
        for (int j8 = 0; j8 < 8; ++j8) {
            const int r0  = bm + mw + 16 * i + g;
            const int col = bn + nw + 8 * j8 + 2 * q;
            const float b0v = bias ? bias[col]     : 0.f;
            const float b1v = bias ? bias[col + 1] : 0.f;
            float v00 = acc[i][j8][0] + b0v, v01 = acc[i][j8][1] + b1v;
            float v10 = acc[i][j8][2] + b0v, v11 = acc[i][j8][3] + b1v;
            if (Cf) {
                *(float2*)&Cf[(size_t)r0 * N + col]       = make_float2(v00, v01);
                *(float2*)&Cf[(size_t)(r0 + 8) * N + col] = make_float2(v10, v11);
            } else {
                *(__half2*)&Ch[(size_t)r0 * N + col]       = __floats2half2_rn(v00, v01);
                *(__half2*)&Ch[(size_t)(r0 + 8) * N + col] = __floats2half2_rn(v10, v11);
            }
        }
    }
}

// ---------------------------------------------------------------------------
// Converters (8 elems/thread) — at DRAM roofline
// ---------------------------------------------------------------------------
__global__ void cvt_pair32to16(__half* __restrict__ h0, const float* __restrict__ s0,
                               __half* __restrict__ h1, const float* __restrict__ s1,
                               int n)
{
    int i = (blockIdx.x * blockDim.x + threadIdx.x) * 8;
    if (i >= n) return;
    {
        float4 a0 = *(const float4*)&s0[i];
        float4 a1 = *(const float4*)&s0[i + 4];
        uint4 o;
        ((__half2*)&o)[0] = __floats2half2_rn(a0.x, a0.y);
        ((__half2*)&o)[1] = __floats2half2_rn(a0.z, a0.w);
        ((__half2*)&o)[2] = __floats2half2_rn(a1.x, a1.y);
        ((__half2*)&o)[3] = __floats2half2_rn(a1.z, a1.w);
        *(uint4*)&h0[i] = o;
    }
    {
        float4 b0 = *(const float4*)&s1[i];
        float4 b1 = *(const float4*)&s1[i + 4];
        uint4 o;
        ((__half2*)&o)[0] = __floats2half2_rn(b0.x, b0.y);
        ((__half2*)&o)[1] = __floats2half2_rn(b0.z, b0.w);
        ((__half2*)&o)[2] = __floats2half2_rn(b1.x, b1.y);
        ((__half2*)&o)[3] = __floats2half2_rn(b1.z, b1.w);
        *(uint4*)&h1[i] = o;
    }
}

// ---------------------------------------------------------------------------
// Merged misc prep: z==0 -> bk_W transpose (fp32->fp16);
//                   z==1 -> bv_W convert (fp32->fp16, 8/thread)
// ---------------------------------------------------------------------------
__global__ void prep_misc_kernel(__half* __restrict__ bkT_out,
                                 const float* __restrict__ bk_W,
                                 __half* __restrict__ bv_out,
                                 const float* __restrict__ bv_W)
{
    if (blockIdx.z == 0) {
        __shared__ float tile[32][33];
        int x = blockIdx.x * 32 + threadIdx.x;
        int y = blockIdx.y * 32 + threadIdx.y;
        #pragma unroll
        for (int i = 0; i < 4; ++i)
            tile[threadIdx.y + 8 * i][threadIdx.x] =
                bk_W[(size_t)(y + 8 * i) * DHID + x];
        __syncthreads();
        x = blockIdx.y * 32 + threadIdx.x;
        y = blockIdx.x * 32 + threadIdx.y;
        #pragma unroll
        for (int i = 0; i < 4; ++i)
            bkT_out[(size_t)(y + 8 * i) * DA + x] =
                __float2half_rn(tile[threadIdx.x][threadIdx.y + 8 * i]);
    } else {
        int tid = (blockIdx.y * 32 + blockIdx.x) * 256
                + threadIdx.y * 32 + threadIdx.x;
        int i = tid * 8;
        if (i >= DA * DHID) return;
        float4 a0 = *(const float4*)&bv_W[i];
        float4 a1 = *(const float4*)&bv_W[i + 4];
        uint4 o;
        ((__half2*)&o)[0] = __floats2half2_rn(a0.x, a0.y);
        ((__half2*)&o)[1] = __floats2half2_rn(a0.z, a0.w);
        ((__half2*)&o)[2] = __floats2half2_rn(a1.x, a1.y);
        ((__half2*)&o)[3] = __floats2half2_rn(a1.z, a1.w);
        *(uint4*)&bv_out[i] = o;
    }
}

// ---------------------------------------------------------------------------
// Combined prep: Ah = qk_W[:, :512] @ q_W ; Bmh = qk_W[:, 512:] @ k_W
// ---------------------------------------------------------------------------
#define BM 128
#define BN 128
#define BK 16

__global__ void __launch_bounds__(256, 2) prep_weights_kernel(
    __half* __restrict__ CA, __half* __restrict__ CB,
    const float* __restrict__ qk_W,
    const float* __restrict__ q_W, const float* __restrict__ k_W)
{
    const int half  = blockIdx.y >> 2;
    const int by    = blockIdx.y & 3;
    __half* C       = half ? CB : CA;
    const float* X  = half ? qk_W + DA : qk_W;
    const float* W  = half ? k_W : q_W;
    const int N = DHID, K = DA, ldx = 2 * DA;

    __shared__ float As[BK][BM];
    __shared__ float Bs[BK][BN];
    const int t  = threadIdx.x;
    const int bm = by * BM;
    const int bn = blockIdx.x * BN;

    float acc[8][8];
    #pragma unroll
    for (int i = 0; i < 8; ++i)
        #pragma unroll
        for (int j = 0; j < 8; ++j) acc[i][j] = 0.f;

    const int lrow = t >> 2;
    const int lc4  = (t & 3) * 4;
    const int wk   = t >> 5;
    const int wn4  = (t & 31) * 4;

    for (int k0 = 0; k0 < K; k0 += BK) {
        #pragma unroll
        for (int h = 0; h < 2; ++h) {
            int row = lrow + h * 64;
            float4 v = *(const float4*)&X[(size_t)(bm + row) * ldx + k0 + lc4];
            As[lc4 + 0][row] = v.x;
            As[lc4 + 1][row] = v.y;
            As[lc4 + 2][row] = v.z;
            As[lc4 + 3][row] = v.w;
            int k = wk + h * 8;
            float4 w = *(const float4*)&W[(size_t)(k0 + k) * N + bn + wn4];
            *(float4*)&Bs[k][wn4] = w;
        }
        __syncthreads();
        const int m8 = (t >> 4) * 8;
        const int n8 = (t & 15) * 8;
        #pragma unroll
        for (int kk = 0; kk < BK; ++kk) {
            float a[8], b[8];
            *(float4*)&a[0] = *(const float4*)&As[kk][m8];
            *(float4*)&a[4] = *(const float4*)&As[kk][m8 + 4];
            *(float4*)&b[0] = *(const float4*)&Bs[kk][n8];
            *(float4*)&b[4] = *(const float4*)&Bs[kk][n8 + 4];
            #pragma unroll
            for (int i = 0; i < 8; ++i)
                #pragma unroll
                for (int j = 0; j < 8; ++j)
                    acc[i][j] += a[i] * b[j];
        }
        __syncthreads();
    }

    const int m0 = bm + (t >> 4) * 8;
    const int n0 = bn + (t & 15) * 8;
    #pragma unroll
    for (int i = 0; i < 8; ++i) {
        __half2 h0 = __floats2half2_rn(acc[i][0], acc[i][1]);
        __half2 h1 = __floats2half2_rn(acc[i][2], acc[i][3]);
        __half2 h2 = __floats2half2_rn(acc[i][4], acc[i][5]);
        __half2 h3 = __floats2half2_rn(acc[i][6], acc[i][7]);
        __half* dst = &C[(size_t)(m0 + i) * N + n0];
        *(__half2*)(dst + 0) = h0;
        *(__half2*)(dst + 2) = h1;
        *(__half2*)(dst + 4) = h2;
        *(__half2*)(dst + 6) = h3;
    }
}

// ---------------------------------------------------------------------------
// Fused bias (parallel)
// ---------------------------------------------------------------------------
__global__ void fuse_bias_kernel(float* __restrict__ c,
                                 const float* __restrict__ qk_W,
                                 const float* __restrict__ q_b,
                                 const float* __restrict__ k_b,
                                 const float* __restrict__ qk_b)
{
    __shared__ float red[8];
    const int i = blockIdx.x;
    const int t = threadIdx.x;
    const float* row = qk_W + (size_t)i * (2 * DA);
    float s = 0.f;
    for (int j = t; j < DA; j += 256)
        s += row[j] * q_b[j] + row[DA + j] * k_b[j];
    #pragma unroll
    for (int o = 16; o; o >>= 1) s += __shfl_xor_sync(0xffffffffu, s, o);
    if ((t & 31) == 0) red[t >> 5] = s;
    __syncthreads();
    if (t == 0) {
        float tot = qk_b[i];
        #pragma unroll
        for (int k = 0; k < 8; ++k) tot += red[k];
        c[i] = tot;
    }
}

// ---------------------------------------------------------------------------
// Attention v6: 512 threads, depth-4 register-pipelined LDG basis staging,
// tensor-core phases (as v5).
// smem layout (bytes):
//   OFF_B = 0      : basis fp16, 64 x 2064   = 132096
//   OFF_U = 132096 : u fp16, 16 x 2064       =  33024
//   OFF_W = 165120 : softmax weights, 16x72h =   2304
//   OFF_S = 167424 : scores fp32, 2 x 16x65  =   8320
//   total 175744
// ---------------------------------------------------------------------------
#define U_ST   2064
#define OFF_B  0
#define OFF_U  132096
#define OFF_W  165120
#define OFF_S  167424
#define SS_LD  65
#define ATT6_SMEM (OFF_S + 2 * BB * SS_LD * 4)  // 175744

__global__ void __launch_bounds__(512) attention_kernel(
    const __half* __restrict__ u,     // (B*L, 1024) fp16
    const float* __restrict__ basis,  // (L, R, 1024) fp32
    __half* __restrict__ yh)
{
    extern __shared__ __align__(16) char smraw2[];
    const uint32_t sm0 = smem_u32(smraw2);
    float*  s_s = (float*)(smraw2 + OFF_S);
    __half* w_h = (__half*)(smraw2 + OFF_W);

    const int l    = blockIdx.x;
    const int t    = threadIdx.x;
    const int warp = t >> 5;          // 0..15
    const int lane = t & 31;
    const int g    = lane >> 2;
    const int q    = lane & 3;
    const float scale = 0.044194173824159216f;  // 1/sqrt(512)

    // --- u staging (cp.async, one group) ---
    #pragma unroll
    for (int it = 0; it < 4; ++it) {
        int idx = t + it * 512;
        int b   = idx >> 7;
        int d8  = (idx & 127) * 8;
        CP_ASYNC16(sm0 + OFF_U + b * U_ST + d8 * 2,
                   &u[((size_t)b * LL + l) * DHID + d8]);
    }
    CP_COMMIT();

    // --- basis staging: direct LDG fp32, DEPTH-4 register pipeline ---
    // 8 chunks of 8 rows. Thread covers row (t>>6), lane-in-row lr = t&63;
    // 4 float4 per thread per chunk.
    {
        const int rown = t >> 6;            // 0..7
        const int lr   = t & 63;
        const float* src0 = basis + (size_t)l * RR * DHID
                          + (size_t)rown * DHID + lr * 4;
        char* dst0 = smraw2 + OFF_B + rown * U_ST + lr * 8;

        float4 v[4][4];
        #pragma unroll
        for (int c0 = 0; c0 < 3; ++c0) {
            const float* s = src0 + (size_t)c0 * 8 * DHID;
            #pragma unroll
            for (int j = 0; j < 4; ++j)
                v[c0][j] = *(const float4*)(s + 256 * j);
        }

        #pragma unroll
        for (int c = 0; c < 8; ++c) {
            if (c + 3 < 8) {
                const float* s = src0 + (size_t)(c + 3) * 8 * DHID;
                #pragma unroll
                for (int j = 0; j < 4; ++j)
                    v[(c + 3) & 3][j] = *(const float4*)(s + 256 * j);
            }
            const float4* vc = v[c & 3];
            char* d = dst0 + (size_t)c * 8 * U_ST;
            #pragma unroll
            for (int j = 0; j < 4; ++j) {
                __half2 h01 = __floats2half2_rn(vc[j].x, vc[j].y);
                __half2 h23 = __floats2half2_rn(vc[j].z, vc[j].w);
                *(__half2*)(d + 512 * j)     = h01;
                *(__half2*)(d + 512 * j + 4) = h23;
            }
        }
    }
    CP_WAIT0();        // u group
    __syncthreads();   // basis tile + u visible to all

    // --- Phase 1: scores via mma, K split across warp pairs ---
    {
        const int wk = warp >> 3;           // 0/1: k-half
        const int wr = warp & 7;            // r-block
        float acc4[4] = {0.f, 0.f, 0.f, 0.f};
        const uint32_t koff  = wk * 1024;   // 512 halves
        const uint32_t aAddr = sm0 + OFF_U + (lane & 15) * U_ST
                             + (lane >> 4) * 16 + koff;
        const uint32_t bAddr = sm0 + OFF_B + (wr * 8 + (lane & 7)) * U_ST
                             + (lane >> 3) * 16 + koff;
        #pragma unroll 4
        for (int kt2 = 0; kt2 < 16; ++kt2) {
            const uint32_t kb = kt2 * 64;
            uint32_t a0[4], a1[4], b4[4];
            ldm_x4(a0, aAddr + kb);
            ldm_x4(a1, aAddr + kb + 32);
            ldm_x4(b4, bAddr + kb);
            mma_f16(acc4, a0, b4[0], b4[1]);
            mma_f16(acc4, a1, b4[2], b4[3]);
        }
        float* sp = s_s + wk * (BB * SS_LD);
        const int r0 = wr * 8 + 2 * q;
        sp[g * SS_LD + r0]           = acc4[0];
        sp[g * SS_LD + r0 + 1]       = acc4[1];
        sp[(g + 8) * SS_LD + r0]     = acc4[2];
        sp[(g + 8) * SS_LD + r0 + 1] = acc4[3];
    }
    __syncthreads();

    // --- Phase 2: softmax; warp w handles b = w ---
    {
        const int b = warp;
        const float* s0 = s_s + b * SS_LD;
        const float* s1 = s_s + BB * SS_LD + b * SS_LD;
        float v0 = (s0[lane]      + s1[lane])      * scale;
        float v1 = (s0[lane + 32] + s1[lane + 32]) * scale;
        float mx = fmaxf(v0, v1);
        #pragma unroll
        for (int o = 16; o; o >>= 1) mx = fmaxf(mx, __shfl_xor_sync(0xffffffffu, mx, o));
        float e0 = __expf(v0 - mx);
        float e1 = __expf(v1 - mx);
        float sum = e0 + e1;
        #pragma unroll
        for (int o = 16; o; o >>= 1) sum += __shfl_xor_sync(0xffffffffu, sum, o);
        float inv = 1.f / sum;
        w_h[b * 72 + lane]      = __float2half_rn(e0 * inv);
        w_h[b * 72 + lane + 32] = __float2half_rn(e1 * inv);
    }
    __syncthreads();

    // --- Phase 3: y = W @ basis via mma (.trans B); warp owns d-span 64 ---
    {
        uint32_t afr[4][4];
        const uint32_t wAddr = sm0 + OFF_W + (lane & 15) * 144 + (lane >> 4) * 16;
        #pragma unroll
        for (int kt = 0; kt < 4; ++kt) ldm_x4(afr[kt], wAddr + kt * 32);

        const int d0w = warp * 64;
        const uint32_t bTA = sm0 + OFF_B + (lane & 15) * U_ST + (lane >> 4) * 16;
        #pragma unroll
        for (int jp = 0; jp < 4; ++jp) {
            const int d0 = d0w + jp * 16;
            float acc2[2][4];
            #pragma unroll
            for (int e = 0; e < 4; ++e) { acc2[0][e] = 0.f; acc2[1][e] = 0.f; }
            #pragma unroll
            for (int kt = 0; kt < 4; ++kt) {
                uint32_t bt[4];
                ldm_x4_trans(bt, bTA + kt * 16 * U_ST + d0 * 2);
                mma_f16(acc2[0], afr[kt], bt[0], bt[1]);
                mma_f16(acc2[1], afr[kt], bt[2], bt[3]);
            }
            #pragma unroll
            for (int jj = 0; jj < 2; ++jj) {
                const int col = d0 + 8 * jj + 2 * q;
                *(__half2*)&yh[((size_t)g * LL + l) * DHID + col] =
                    __floats2half2_rn(acc2[jj][0], acc2[jj][1]);
                *(__half2*)&yh[((size_t)(g + 8) * LL + l) * DHID + col] =
                    __floats2half2_rn(acc2[jj][2], acc2[jj][3]);
            }
        }
    }
}

// ---------------------------------------------------------------------------
// Launch
// ---------------------------------------------------------------------------
extern "C" void kernel_launch(void* const* d_in, const int* in_sizes, int n_in,
                              void* d_out, int out_size)
{
    const float* s_emb  = (const float*)d_in[0];
    const float* t_emb  = (const float*)d_in[1];
    const float* basis  = (const float*)d_in[2];
    const float* q_W    = (const float*)d_in[3];
    const float* q_b    = (const float*)d_in[4];
    const float* k_W    = (const float*)d_in[5];
    const float* k_b    = (const float*)d_in[6];
    const float* qk_W   = (const float*)d_in[7];
    const float* qk_b   = (const float*)d_in[8];
    const float* bk_W   = (const float*)d_in[9];
    // d_in[10] = bk_b : provably unused (softmax shift invariance)
    const float* bv_W   = (const float*)d_in[11];
    const float* bv_b   = (const float*)d_in[12];
    float* out = (float*)d_out;

    float  *p_c;
    __half *p_sh, *p_th, *p_qh, *p_uh, *p_yh;
    __half *p_Ah, *p_Bmh, *p_bkTh, *p_bvh;
    cudaGetSymbolAddress((void**)&p_c,    g_c);
    cudaGetSymbolAddress((void**)&p_sh,   g_sh);
    cudaGetSymbolAddress((void**)&p_th,   g_th);
    cudaGetSymbolAddress((void**)&p_qh,   g_qh);
    cudaGetSymbolAddress((void**)&p_uh,   g_uh);
    cudaGetSymbolAddress((void**)&p_yh,   g_yh);
    cudaGetSymbolAddress((void**)&p_Ah,   g_Ah);
    cudaGetSymbolAddress((void**)&p_Bmh,  g_Bmh);
    cudaGetSymbolAddress((void**)&p_bkTh, g_bkTh);
    cudaGetSymbolAddress((void**)&p_bvh,  g_bvh);

    cudaFuncSetAttribute(attention_kernel,
                         cudaFuncAttributeMaxDynamicSharedMemorySize, ATT6_SMEM);
    cudaFuncSetAttribute(gemm_h_nt,
                         cudaFuncAttributeMaxDynamicSharedMemorySize, SMEM_G);

    // launch 0: fused projection matrices Ah, Bmh
    {
        dim3 grid(DHID / BN, 8);
        prep_weights_kernel<<<grid, 256>>>(p_Ah, p_Bmh, qk_W, q_W, k_W);
    }

    // launch 1: fused bias (parallel)
    fuse_bias_kernel<<<DA, 256>>>(p_c, qk_W, q_b, k_b, qk_b);

    // launch 2: merged misc prep (bk_W transpose + bv_W convert)
    {
        dim3 tg(DHID / 32, DA / 32, 2);
        prep_misc_kernel<<<tg, dim3(32, 8)>>>(p_bkTh, bk_W, p_bvh, bv_W);
    }

    // launch 3 (ncu capture slot): s,t -> fp16
    const int ne = MTOT * DHID;
    cvt_pair32to16<<<ne / 8 / 256, 256>>>(p_sh, s_emb, p_th, t_emb, ne);

    // launch 4: qk = s@A^T + t@Bm^T + c -> fp16
    {
        GArgs ga = { p_sh, p_Ah, p_th, p_Bmh, DHID, DHID };
        dim3 grid(DA / 128, MTOT / 128);
        gemm_h_nt<<<grid, 256, SMEM_G>>>(ga, p_c, nullptr, p_qh, MTOT, DA);
    }

    // launch 5: u = qk @ bkT^T -> fp16
    {
        GArgs ga = { p_qh, p_bkTh, nullptr, nullptr, DA, 0 };
        dim3 grid(DHID / 128, MTOT / 128);
        gemm_h_nt<<<grid, 256, SMEM_G>>>(ga, nullptr, nullptr, p_uh, MTOT, DHID);
    }

    // launch 6: attention v6 (depth-4 staging, 512 threads)
    attention_kernel<<<LL, 512, ATT6_SMEM>>>(p_uh, basis, p_yh);

    // launch 7: z = y @ bv_W^T + bv_b -> fp32 out
    {
        GArgs ga = { p_yh, p_bvh, nullptr, nullptr, DHID, 0 };
        dim3 grid(DA / 128, MTOT / 128);
        gemm_h_nt<<<grid, 256, SMEM_G>>>(ga, bv_b, out, nullptr, MTOT, DA);
    }
}